// round 7
// baseline (speedup 1.0000x reference)
#include <cuda_runtime.h>
#include <math.h>
#include <stdint.h>

// Problem constants
#define C_DIM 64
#define D_DIM 32
#define H_DIM 96
#define W_DIM 96
#define B_DIM 2
#define WT 4          // w-tile per block
#define NTHREADS 512

// smem layout (floats), all offsets 16B-aligned
#define SV_OFF    0       // phase A/B: x tile [64][136]=8704 ; after mid-B sync: V [4 w(*2309)][c(*36)][e] (max 9227)
#define SQ_OFF    9240    // Q [4 w (*1185)][32 q (*36)][d] : 4740
#define SK_OFF    13980   // K : 4740
#define SAT_OFF   18720   // attn [4 w(*1152)][e(*36)][d] : 4608
#define SEX_OFF   23328   // softmax pair-exchange: 16 warps * 32 : 512
#define SBIAS_OFF 23840   // 128
#define SPOS_OFF  23968   // 1024
#define SMEM_FLOATS 24992
#define SMEM_BYTES (SMEM_FLOATS * 4)   // 99968 B -> 2 CTAs/SM
// sout staging overlays SQ..SK: sout[c*136 + w*32 + d], 64*136 = 8704 <= 9480

__device__ float g_tb[32];
__device__ float g_wpack[8192];   // prepacked tf32 W in A-fragment order

__device__ __forceinline__ float tf32r(float x) {
    uint32_t u;
    asm("cvt.rna.tf32.f32 %0, %1;" : "=r"(u) : "f"(x));
    return __uint_as_float(u);
}

__device__ __forceinline__ void mma_tf32(float* d, const float4& a, uint32_t b0, uint32_t b1) {
    const uint32_t* A = reinterpret_cast<const uint32_t*>(&a);
    asm volatile(
        "mma.sync.aligned.m16n8k8.row.col.f32.tf32.tf32.f32 "
        "{%0,%1,%2,%3}, {%4,%5,%6,%7}, {%8,%9}, {%0,%1,%2,%3};"
        : "+f"(d[0]), "+f"(d[1]), "+f"(d[2]), "+f"(d[3])
        : "r"(A[0]), "r"(A[1]), "r"(A[2]), "r"(A[3]), "r"(b0), "r"(b1));
}

__device__ __forceinline__ void cp16(float* smem_dst, const float* gmem_src) {
    unsigned s = (unsigned)__cvta_generic_to_shared(smem_dst);
    asm volatile("cp.async.ca.shared.global [%0], [%1], 16;" :: "r"(s), "l"(gmem_src));
}

// ---------------------------------------------------------------------------
// Setup kernel: text bias + weight prepack (fragment order, tf32-rounded)
// ---------------------------------------------------------------------------
__global__ void setup_kernel(const float* __restrict__ text_emb,
                             const float* __restrict__ wt,
                             const float* __restrict__ bt,
                             const float* __restrict__ wq,
                             const float* __restrict__ wk,
                             const float* __restrict__ wv) {
    __shared__ float mcol[256];
    int t = threadIdx.x;
    float s = 0.f;
    #pragma unroll
    for (int r = 0; r < 32; ++r) s += text_emb[r * 256 + t];
    mcol[t] = s * (1.0f / 32.0f);
    __syncthreads();
    int warp = t >> 5, lane = t & 31;
    for (int q = warp; q < 32; q += 8) {
        float acc = 0.f;
        #pragma unroll
        for (int k = 0; k < 8; ++k) acc += wt[q * 256 + lane + k * 32] * mcol[lane + k * 32];
        #pragma unroll
        for (int o = 16; o > 0; o >>= 1) acc += __shfl_xor_sync(0xffffffffu, acc, o);
        if (lane == 0) g_tb[q] = acc + bt[q];
    }
    // g_wpack[((mt*8+kt)*32 + lane)*4 + v] = W[mt*16+g+(v&1)*8][kt*8+tt+(v>>1)*4]
    #pragma unroll
    for (int it = 0; it < 32; ++it) {
        int idx  = t + it * 256;
        int v    = idx & 3;
        int ln   = (idx >> 2) & 31;
        int kt   = (idx >> 7) & 7;
        int mt   = idx >> 10;
        int g = ln >> 2, tt = ln & 3;
        int o = mt * 16 + g + (v & 1) * 8;
        int c = kt * 8 + tt + (v >> 1) * 4;
        float wval;
        if (o < 32)       wval = wq[o * 64 + c];
        else if (o < 64)  wval = wk[(o - 32) * 64 + c];
        else              wval = wv[(o - 64) * 64 + c];
        g_wpack[idx] = tf32r(wval);
    }
}

// ---------------------------------------------------------------------------
// Main fused kernel: one block per (b, h, w-tile of 4); 512 threads, 2 CTA/SM
// ---------------------------------------------------------------------------
__global__ __launch_bounds__(NTHREADS, 2)
void attn_kernel(const float* __restrict__ x,
                 const float* __restrict__ bq, const float* __restrict__ bk,
                 const float* __restrict__ bv,
                 const float* __restrict__ pos, const float* __restrict__ gamma,
                 float* __restrict__ out) {
    extern __shared__ float sm[];
    float* sxv   = sm + SV_OFF;    // x tile (A/B), V fragments afterwards
    float* sq    = sm + SQ_OFF;
    float* sk    = sm + SK_OFF;
    float* sat   = sm + SAT_OFF;
    float* sex   = sm + SEX_OFF;
    float* sbias = sm + SBIAS_OFF;
    float* spos  = sm + SPOS_OFF;
    float* sout  = sm + SQ_OFF;    // staging reuse (stride 136)

    const int tid = threadIdx.x;
    const int bid = blockIdx.x;
    const int nwT = W_DIM / WT;   // 24
    const int b   = bid / (H_DIM * nwT);
    const int rem = bid % (H_DIM * nwT);
    const int h   = rem / nwT;
    const int w0  = (rem % nwT) * WT;

    const int HW = H_DIM * W_DIM; // 9216
    const size_t base = (size_t)b * C_DIM * D_DIM * HW + (size_t)h * W_DIM + w0;

    // ---- Phase A: async x tile load (raw fp32; HMMA.TF32 truncates) ----
    #pragma unroll
    for (int it = 0; it < 4; ++it) {
        int i = tid + it * NTHREADS;          // 2048 float4s
        int c = i >> 5, d = i & 31;
        cp16(&sxv[c * 136 + d * 4], x + base + ((size_t)c * D_DIM + d) * HW);
    }
    if (tid < 128) {
        float bb;
        if (tid < 32)      bb = bq[tid] + g_tb[tid];
        else if (tid < 64) bb = bk[tid - 32] + g_tb[tid - 32];
        else               bb = bv[tid - 64];
        sbias[tid] = bb;
    }
    #pragma unroll
    for (int it = 0; it < 2; ++it) spos[tid + it * NTHREADS] = pos[tid + it * NTHREADS];
    asm volatile("cp.async.commit_group;");
    asm volatile("cp.async.wait_group 0;" ::: "memory");
    __syncthreads();

    // ---- Phase B: tf32 MMA GEMM  C[128 o][128 n] = W[128,64] * X[64,128] ----
    const int warp = tid >> 5, lane = tid & 31;
    const int g = lane >> 2, t = lane & 3;
    const int mw = warp & 7;        // o-group of 16: 0,1:Q 2,3:K 4..7:V
    const int nh = warp >> 3;       // n half (64 wide)

    {
        float acc[8][4];
        #pragma unroll
        for (int nt = 0; nt < 8; ++nt)
            #pragma unroll
            for (int v = 0; v < 4; ++v) acc[nt][v] = 0.f;

        const float4* wp4 = reinterpret_cast<const float4*>(g_wpack);
        #pragma unroll
        for (int kt = 0; kt < 8; ++kt) {
            float4 a = __ldg(&wp4[(mw * 8 + kt) * 32 + lane]);
            const float* xb0 = &sxv[(kt * 8 + t) * 136 + nh * 64 + g];
            const float* xb1 = &sxv[(kt * 8 + t + 4) * 136 + nh * 64 + g];
            #pragma unroll
            for (int nt = 0; nt < 8; ++nt) {
                uint32_t b0 = __float_as_uint(xb0[nt * 8]);
                uint32_t b1 = __float_as_uint(xb1[nt * 8]);
                mma_tf32(acc[nt], a, b0, b1);
            }
        }

        // Q/K epilogue (before mid-barrier): sq/sk[w*1185 + q*36 + d]
        if (mw < 4) {
            float* dst = (mw < 2) ? sq : sk;
            const int qb_ = (mw & 1) * 16;
            const int boff = (mw < 2) ? 0 : 32;
            const float qscale = (mw < 2) ? 0.17677669529663687f : 1.0f;
            #pragma unroll
            for (int nt = 0; nt < 8; ++nt) {
                #pragma unroll
                for (int v = 0; v < 4; ++v) {
                    int q = qb_ + g + (v >> 1) * 8;
                    int n = nh * 64 + nt * 8 + 2 * t + (v & 1);
                    int d = n >> 2, w = n & 3;
                    float val = acc[nt][v] + sbias[boff + q] + spos[q * 32 + d];
                    dst[w * 1185 + q * 36 + d] = tf32r(val * qscale);
                }
            }
        }
        __syncthreads();   // all X reads done; V may overwrite sxv

        // V epilogue: sv[w*2309 + c*36 + e]
        if (mw >= 4) {
            const int cbb = (mw - 4) * 16;
            #pragma unroll
            for (int nt = 0; nt < 8; ++nt) {
                #pragma unroll
                for (int v = 0; v < 4; ++v) {
                    int cch = cbb + g + (v >> 1) * 8;
                    int n = nh * 64 + nt * 8 + 2 * t + (v & 1);
                    int e = n >> 2, w = n & 3;
                    sxv[w * 2309 + cch * 36 + e] = tf32r(acc[nt][v] + sbias[64 + cch]);
                }
            }
        }
    }

    // ---- Phase C: scores via MMA + split softmax. warp = (w, dh, eh) ----
    const int aw = warp & 3;
    {
        const int dh = ((warp >> 2) & 1) * 16;
        const int eh = (warp >> 3) * 16;
        const float* qb = &sq[aw * 1185];   // [q*36 + d]
        const float* kb = &sk[aw * 1185];   // [q*36 + e]

        float fs[2][4];
        #pragma unroll
        for (int nt = 0; nt < 2; ++nt)
            #pragma unroll
            for (int v = 0; v < 4; ++v) fs[nt][v] = 0.f;

        #pragma unroll
        for (int kt = 0; kt < 4; ++kt) {
            float4 afr;   // A[m=d][k=q]
            afr.x = qb[(kt * 8 + t) * 36 + dh + g];
            afr.y = qb[(kt * 8 + t) * 36 + dh + g + 8];
            afr.z = qb[(kt * 8 + t + 4) * 36 + dh + g];
            afr.w = qb[(kt * 8 + t + 4) * 36 + dh + g + 8];
            #pragma unroll
            for (int nt = 0; nt < 2; ++nt) {   // B[k=q][n=e]
                uint32_t b0 = __float_as_uint(kb[(kt * 8 + t) * 36 + eh + nt * 8 + g]);
                uint32_t b1 = __float_as_uint(kb[(kt * 8 + t + 4) * 36 + eh + nt * 8 + g]);
                mma_tf32(fs[nt], afr, b0, b1);
            }
        }
        // fs[nt][v]: S[d = dh + g + (v>>1)*8][e = eh + nt*8 + 2t + (v&1)]

        // partial softmax over this warp's 16-e half
        float m0 = fmaxf(fmaxf(fs[0][0], fs[0][1]), fmaxf(fs[1][0], fs[1][1]));
        float m1 = fmaxf(fmaxf(fs[0][2], fs[0][3]), fmaxf(fs[1][2], fs[1][3]));
        m0 = fmaxf(m0, __shfl_xor_sync(0xffffffffu, m0, 1));
        m0 = fmaxf(m0, __shfl_xor_sync(0xffffffffu, m0, 2));
        m1 = fmaxf(m1, __shfl_xor_sync(0xffffffffu, m1, 1));
        m1 = fmaxf(m1, __shfl_xor_sync(0xffffffffu, m1, 2));

        float s0 = 0.f, s1 = 0.f;
        #pragma unroll
        for (int nt = 0; nt < 2; ++nt) {
            fs[nt][0] = __expf(fs[nt][0] - m0); s0 += fs[nt][0];
            fs[nt][1] = __expf(fs[nt][1] - m0); s0 += fs[nt][1];
            fs[nt][2] = __expf(fs[nt][2] - m1); s1 += fs[nt][2];
            fs[nt][3] = __expf(fs[nt][3] - m1); s1 += fs[nt][3];
        }
        s0 += __shfl_xor_sync(0xffffffffu, s0, 1);
        s0 += __shfl_xor_sync(0xffffffffu, s0, 2);
        s1 += __shfl_xor_sync(0xffffffffu, s1, 1);
        s1 += __shfl_xor_sync(0xffffffffu, s1, 2);

        // exchange with partner warp (other e-half): pair id = warp&7
        if (t == 0)
            *reinterpret_cast<float4*>(&sex[warp * 32 + g * 4]) = make_float4(m0, s0, m1, s1);
        const int barid = (warp & 7) + 1;
        asm volatile("bar.sync %0, %1;" :: "r"(barid), "r"(64) : "memory");
        float4 p = *reinterpret_cast<const float4*>(&sex[(warp ^ 8) * 32 + g * 4]);

        float mf0 = fmaxf(m0, p.x);
        float sf0 = s0 * __expf(m0 - mf0) + p.y * __expf(p.x - mf0);
        float r0  = __fdividef(__expf(m0 - mf0), sf0);
        float mf1 = fmaxf(m1, p.z);
        float sf1 = s1 * __expf(m1 - mf1) + p.w * __expf(p.z - mf1);
        float r1  = __fdividef(__expf(m1 - mf1), sf1);

        // transposed attn store: sat[w*1152 + e*36 + d]
        float* satw = &sat[aw * 1152];
        #pragma unroll
        for (int nt = 0; nt < 2; ++nt) {
            int e = eh + nt * 8 + 2 * t;
            satw[e * 36 + dh + g]           = tf32r(fs[nt][0] * r0);
            satw[(e + 1) * 36 + dh + g]     = tf32r(fs[nt][1] * r0);
            satw[e * 36 + dh + g + 8]       = tf32r(fs[nt][2] * r1);
            satw[(e + 1) * 36 + dh + g + 8] = tf32r(fs[nt][3] * r1);
        }
    }
    __syncthreads();   // V + attn complete; sq/sk dead -> sout

    // ---- Phase D: out[c][d] = V[c][e] @ attn[e][d]. warp = (w, ch, dq) ----
    {
        const int ch = ((warp >> 2) & 1) * 32;
        const int dq = (warp >> 3) * 16;
        const float* vb = &sxv[aw * 2309 + ch * 36];   // [c*36 + e]
        const float* ab = &sat[aw * 1152];             // [e*36 + d]

        float od[2][2][4];
        #pragma unroll
        for (int mt = 0; mt < 2; ++mt)
            #pragma unroll
            for (int nt = 0; nt < 2; ++nt)
                #pragma unroll
                for (int v = 0; v < 4; ++v) od[mt][nt][v] = 0.f;

        #pragma unroll
        for (int kt = 0; kt < 4; ++kt) {
            float4 av0, av1;   // A[m=c][k=e]
            av0.x = vb[g * 36 + kt * 8 + t];
            av0.y = vb[(g + 8) * 36 + kt * 8 + t];
            av0.z = vb[g * 36 + kt * 8 + t + 4];
            av0.w = vb[(g + 8) * 36 + kt * 8 + t + 4];
            av1.x = vb[(16 + g) * 36 + kt * 8 + t];
            av1.y = vb[(16 + g + 8) * 36 + kt * 8 + t];
            av1.z = vb[(16 + g) * 36 + kt * 8 + t + 4];
            av1.w = vb[(16 + g + 8) * 36 + kt * 8 + t + 4];
            #pragma unroll
            for (int nt = 0; nt < 2; ++nt) {   // B[k=e][n=d]
                uint32_t b0 = __float_as_uint(ab[(kt * 8 + t) * 36 + dq + nt * 8 + g]);
                uint32_t b1 = __float_as_uint(ab[(kt * 8 + t + 4) * 36 + dq + nt * 8 + g]);
                mma_tf32(od[0][nt], av0, b0, b1);
                mma_tf32(od[1][nt], av1, b0, b1);
            }
        }
        // od[mt][nt][v]: out[c = ch+mt*16+g+(v>>1)*8][d = dq + nt*8 + 2t + (v&1)]

        #pragma unroll
        for (int mt = 0; mt < 2; ++mt) {
            #pragma unroll
            for (int nt = 0; nt < 2; ++nt) {
                int c0 = ch + mt * 16 + g;
                int d0 = dq + nt * 8 + 2 * t;
                *reinterpret_cast<float2*>(&sout[c0 * 136 + aw * 32 + d0]) =
                    make_float2(od[mt][nt][0], od[mt][nt][1]);
                *reinterpret_cast<float2*>(&sout[(c0 + 8) * 136 + aw * 32 + d0]) =
                    make_float2(od[mt][nt][2], od[mt][nt][3]);
            }
        }
    }
    __syncthreads();

    // ---- Epilogue: out = g*attn_out + (1-g)*x, coalesced ----
    const float gm = gamma[0];
    const float g_ = 1.f / (1.f + __expf(-gm));
    const float g1 = 1.f - g_;
    #pragma unroll
    for (int it = 0; it < 4; ++it) {
        int i = tid + it * NTHREADS;
        int c = i >> 5, d = i & 31;
        size_t gaddr = base + ((size_t)c * D_DIM + d) * HW;
        float4 xv = *reinterpret_cast<const float4*>(x + gaddr);
        float4 r;
        r.x = g_ * sout[c * 136 +  0 + d] + g1 * xv.x;
        r.y = g_ * sout[c * 136 + 32 + d] + g1 * xv.y;
        r.z = g_ * sout[c * 136 + 64 + d] + g1 * xv.z;
        r.w = g_ * sout[c * 136 + 96 + d] + g1 * xv.w;
        *reinterpret_cast<float4*>(out + gaddr) = r;
    }
}

// ---------------------------------------------------------------------------
extern "C" void kernel_launch(void* const* d_in, const int* in_sizes, int n_in,
                              void* d_out, int out_size) {
    const float* x        = (const float*)d_in[0];
    const float* text_emb = (const float*)d_in[1];
    const float* wq       = (const float*)d_in[2];
    const float* bq       = (const float*)d_in[3];
    const float* wk       = (const float*)d_in[4];
    const float* bk       = (const float*)d_in[5];
    const float* wv       = (const float*)d_in[6];
    const float* bv       = (const float*)d_in[7];
    const float* wt       = (const float*)d_in[8];
    const float* bt       = (const float*)d_in[9];
    const float* pos      = (const float*)d_in[10];
    const float* gamma    = (const float*)d_in[11];
    float* out = (float*)d_out;

    cudaFuncSetAttribute(attn_kernel, cudaFuncAttributeMaxDynamicSharedMemorySize, SMEM_BYTES);

    setup_kernel<<<1, 256>>>(text_emb, wt, bt, wq, wk, wv);

    const int grid = B_DIM * H_DIM * (W_DIM / WT);  // 4608
    attn_kernel<<<grid, NTHREADS, SMEM_BYTES>>>(x, bq, bk, bv, pos, gamma, out);
}

// round 8
// speedup vs baseline: 1.1862x; 1.1862x over previous
#include <cuda_runtime.h>
#include <cuda_fp16.h>
#include <math.h>
#include <stdint.h>

// Problem constants
#define C_DIM 64
#define D_DIM 32
#define H_DIM 96
#define W_DIM 96
#define B_DIM 2
#define WT 4          // w-tile per block
#define NTHREADS 512

// smem layout (floats)
#define SX_OFF    0       // x tile [64][136] = 8704 ; after phase B: sout[c*136 + w*32 + d]
#define SQ_OFF    8704    // Q [4 w (*1185)][32 q (*36)][d] : 4740
#define SK_OFF    13444   // K : 4740
#define SVH_OFF   18184   // V fp16 pairs: uint32 [4 w (*1168)][16 epair (*72)][64 c] : 4672 words
#define SBIAS_OFF 22856   // 128
#define SPOS_OFF  22984   // 1024
#define SMEM_FLOATS 24008
#define SMEM_BYTES (SMEM_FLOATS * 4)   // 96032 B -> 2 CTAs/SM

__device__ float g_tb[32];
__device__ float g_wpack[8192];   // prepacked tf32 W in A-fragment order

__device__ __forceinline__ float tf32r(float x) {
    uint32_t u;
    asm("cvt.rna.tf32.f32 %0, %1;" : "=r"(u) : "f"(x));
    return __uint_as_float(u);
}

__device__ __forceinline__ void mma_tf32(float* d, const float4& a, uint32_t b0, uint32_t b1) {
    const uint32_t* A = reinterpret_cast<const uint32_t*>(&a);
    asm volatile(
        "mma.sync.aligned.m16n8k8.row.col.f32.tf32.tf32.f32 "
        "{%0,%1,%2,%3}, {%4,%5,%6,%7}, {%8,%9}, {%0,%1,%2,%3};"
        : "+f"(d[0]), "+f"(d[1]), "+f"(d[2]), "+f"(d[3])
        : "r"(A[0]), "r"(A[1]), "r"(A[2]), "r"(A[3]), "r"(b0), "r"(b1));
}

__device__ __forceinline__ void mma_f16(float* d, uint32_t a0, uint32_t a1, uint32_t a2,
                                        uint32_t a3, uint32_t b0, uint32_t b1) {
    asm volatile(
        "mma.sync.aligned.m16n8k16.row.col.f32.f16.f16.f32 "
        "{%0,%1,%2,%3}, {%4,%5,%6,%7}, {%8,%9}, {%0,%1,%2,%3};"
        : "+f"(d[0]), "+f"(d[1]), "+f"(d[2]), "+f"(d[3])
        : "r"(a0), "r"(a1), "r"(a2), "r"(a3), "r"(b0), "r"(b1));
}

__device__ __forceinline__ uint32_t h2pack(float lo, float hi) {
    __half2 h = __floats2half2_rn(lo, hi);
    return *reinterpret_cast<uint32_t*>(&h);
}

__device__ __forceinline__ void cp16(float* smem_dst, const float* gmem_src) {
    unsigned s = (unsigned)__cvta_generic_to_shared(smem_dst);
    asm volatile("cp.async.ca.shared.global [%0], [%1], 16;" :: "r"(s), "l"(gmem_src));
}

// ---------------------------------------------------------------------------
// Setup kernel: text bias + weight prepack (fragment order, tf32-rounded)
// ---------------------------------------------------------------------------
__global__ void setup_kernel(const float* __restrict__ text_emb,
                             const float* __restrict__ wt,
                             const float* __restrict__ bt,
                             const float* __restrict__ wq,
                             const float* __restrict__ wk,
                             const float* __restrict__ wv) {
    __shared__ float mcol[256];
    int t = threadIdx.x;
    float s = 0.f;
    #pragma unroll
    for (int r = 0; r < 32; ++r) s += text_emb[r * 256 + t];
    mcol[t] = s * (1.0f / 32.0f);
    __syncthreads();
    int warp = t >> 5, lane = t & 31;
    for (int q = warp; q < 32; q += 8) {
        float acc = 0.f;
        #pragma unroll
        for (int k = 0; k < 8; ++k) acc += wt[q * 256 + lane + k * 32] * mcol[lane + k * 32];
        #pragma unroll
        for (int o = 16; o > 0; o >>= 1) acc += __shfl_xor_sync(0xffffffffu, acc, o);
        if (lane == 0) g_tb[q] = acc + bt[q];
    }
    // g_wpack[((mt*8+kt)*32 + lane)*4 + v] = W[mt*16+g+(v&1)*8][kt*8+tt+(v>>1)*4]
    #pragma unroll
    for (int it = 0; it < 32; ++it) {
        int idx  = t + it * 256;
        int v    = idx & 3;
        int ln   = (idx >> 2) & 31;
        int kt   = (idx >> 7) & 7;
        int mt   = idx >> 10;
        int g = ln >> 2, tt = ln & 3;
        int o = mt * 16 + g + (v & 1) * 8;
        int c = kt * 8 + tt + (v >> 1) * 4;
        float wval;
        if (o < 32)       wval = wq[o * 64 + c];
        else if (o < 64)  wval = wk[(o - 32) * 64 + c];
        else              wval = wv[(o - 64) * 64 + c];
        g_wpack[idx] = tf32r(wval);
    }
}

// ---------------------------------------------------------------------------
// Main fused kernel: one block per (b, h, w-tile of 4); 512 threads, 2 CTA/SM
// ---------------------------------------------------------------------------
__global__ __launch_bounds__(NTHREADS, 2)
void attn_kernel(const float* __restrict__ x,
                 const float* __restrict__ bq, const float* __restrict__ bk,
                 const float* __restrict__ bv,
                 const float* __restrict__ pos, const float* __restrict__ gamma,
                 float* __restrict__ out) {
    extern __shared__ float sm[];
    float* sx    = sm + SX_OFF;    // x tile (A/B), sout afterwards
    float* sq    = sm + SQ_OFF;
    float* sk    = sm + SK_OFF;
    __half* sv_h = reinterpret_cast<__half*>(sm + SVH_OFF);
    uint32_t* sv32 = reinterpret_cast<uint32_t*>(sm + SVH_OFF);
    float* sbias = sm + SBIAS_OFF;
    float* spos  = sm + SPOS_OFF;
    float* sout  = sm + SX_OFF;    // staging reuse (x region dead after phase B)

    const int tid = threadIdx.x;
    const int bid = blockIdx.x;
    const int nwT = W_DIM / WT;   // 24
    const int b   = bid / (H_DIM * nwT);
    const int rem = bid % (H_DIM * nwT);
    const int h   = rem / nwT;
    const int w0  = (rem % nwT) * WT;

    const int HW = H_DIM * W_DIM; // 9216
    const size_t base = (size_t)b * C_DIM * D_DIM * HW + (size_t)h * W_DIM + w0;

    // ---- Phase A: async x tile load (raw fp32; HMMA.TF32 truncates) ----
    #pragma unroll
    for (int it = 0; it < 4; ++it) {
        int i = tid + it * NTHREADS;          // 2048 float4s
        int c = i >> 5, d = i & 31;
        cp16(&sx[c * 136 + d * 4], x + base + ((size_t)c * D_DIM + d) * HW);
    }
    if (tid < 128) {
        float bb;
        if (tid < 32)      bb = bq[tid] + g_tb[tid];
        else if (tid < 64) bb = bk[tid - 32] + g_tb[tid - 32];
        else               bb = bv[tid - 64];
        sbias[tid] = bb;
    }
    #pragma unroll
    for (int it = 0; it < 2; ++it) spos[tid + it * NTHREADS] = pos[tid + it * NTHREADS];
    asm volatile("cp.async.commit_group;");
    asm volatile("cp.async.wait_group 0;" ::: "memory");
    __syncthreads();                                     // barrier 1

    // ---- Phase B: tf32 MMA GEMM  C[128 o][128 n] = W[128,64] * X[64,128] ----
    const int warp = tid >> 5, lane = tid & 31;
    const int g = lane >> 2, t = lane & 3;
    const int mw = warp & 7;        // o-group of 16: 0,1:Q 2,3:K 4..7:V
    const int nh = warp >> 3;       // n half (64 wide)

    {
        float acc[8][4];
        #pragma unroll
        for (int nt = 0; nt < 8; ++nt)
            #pragma unroll
            for (int v = 0; v < 4; ++v) acc[nt][v] = 0.f;

        const float4* wp4 = reinterpret_cast<const float4*>(g_wpack);
        #pragma unroll
        for (int kt = 0; kt < 8; ++kt) {
            float4 a = __ldg(&wp4[(mw * 8 + kt) * 32 + lane]);
            const float* xb0 = &sx[(kt * 8 + t) * 136 + nh * 64 + g];
            const float* xb1 = &sx[(kt * 8 + t + 4) * 136 + nh * 64 + g];
            #pragma unroll
            for (int nt = 0; nt < 8; ++nt) {
                uint32_t b0 = __float_as_uint(xb0[nt * 8]);
                uint32_t b1 = __float_as_uint(xb1[nt * 8]);
                mma_tf32(acc[nt], a, b0, b1);
            }
        }

        if (mw < 4) {
            // Q/K epilogue: sq/sk[w*1185 + q*36 + d], scale folded into Q
            float* dst = (mw < 2) ? sq : sk;
            const int qb_ = (mw & 1) * 16;
            const int boff = (mw < 2) ? 0 : 32;
            const float qscale = (mw < 2) ? 0.17677669529663687f : 1.0f;
            #pragma unroll
            for (int nt = 0; nt < 8; ++nt) {
                #pragma unroll
                for (int v = 0; v < 4; ++v) {
                    int q = qb_ + g + (v >> 1) * 8;
                    int n = nh * 64 + nt * 8 + 2 * t + (v & 1);
                    int d = n >> 2, w = n & 3;
                    float val = acc[nt][v] + sbias[boff + q] + spos[q * 32 + d];
                    dst[w * 1185 + q * 36 + d] = tf32r(val * qscale);
                }
            }
        } else {
            // V epilogue: fp16 into B-fragment layout sv32[w*1168 + (e>>1)*72 + c] (e parity = half)
            const int cbb = (mw - 4) * 16;
            #pragma unroll
            for (int nt = 0; nt < 8; ++nt) {
                #pragma unroll
                for (int v = 0; v < 4; ++v) {
                    int c = cbb + g + (v >> 1) * 8;
                    int n = nh * 64 + nt * 8 + 2 * t + (v & 1);
                    int e = n >> 2, w = n & 3;
                    sv_h[(w * 1168 + (e >> 1) * 72 + c) * 2 + (e & 1)] =
                        __float2half_rn(acc[nt][v] + sbias[64 + c]);
                }
            }
        }
    }
    __syncthreads();                                     // barrier 2 (x reads done, Q/K/V ready)

    // ---- Phases C+D fused per warp: (w, d-half, c-half) ----
    const int aw = warp & 3;
    const int dh = ((warp >> 2) & 1) * 16;
    const int ch = (warp >> 3) * 32;
    {
        const float* qb = &sq[aw * 1185];   // [q*36 + d]
        const float* kb = &sk[aw * 1185];   // [q*36 + e]

        // scores S[16 d][32 e] via tf32 MMA
        float fs[4][4];
        #pragma unroll
        for (int nt = 0; nt < 4; ++nt)
            #pragma unroll
            for (int v = 0; v < 4; ++v) fs[nt][v] = 0.f;

        #pragma unroll
        for (int kt = 0; kt < 4; ++kt) {
            float4 afr;   // A[m=d][k=q]
            afr.x = qb[(kt * 8 + t) * 36 + dh + g];
            afr.y = qb[(kt * 8 + t) * 36 + dh + g + 8];
            afr.z = qb[(kt * 8 + t + 4) * 36 + dh + g];
            afr.w = qb[(kt * 8 + t + 4) * 36 + dh + g + 8];
            #pragma unroll
            for (int nt = 0; nt < 4; ++nt) {   // B[k=q][n=e]
                uint32_t b0 = __float_as_uint(kb[(kt * 8 + t) * 36 + nt * 8 + g]);
                uint32_t b1 = __float_as_uint(kb[(kt * 8 + t + 4) * 36 + nt * 8 + g]);
                mma_tf32(fs[nt], afr, b0, b1);
            }
        }
        // fs[nt][v]: S[d = dh + g + (v>>1)*8][e = nt*8 + 2t + (v&1)]

        // in-warp softmax over e (rows dh+g and dh+g+8; quad = lanes sharing g)
        float m0 = -1e30f, m1 = -1e30f;
        #pragma unroll
        for (int nt = 0; nt < 4; ++nt) {
            m0 = fmaxf(m0, fmaxf(fs[nt][0], fs[nt][1]));
            m1 = fmaxf(m1, fmaxf(fs[nt][2], fs[nt][3]));
        }
        m0 = fmaxf(m0, __shfl_xor_sync(0xffffffffu, m0, 1));
        m0 = fmaxf(m0, __shfl_xor_sync(0xffffffffu, m0, 2));
        m1 = fmaxf(m1, __shfl_xor_sync(0xffffffffu, m1, 1));
        m1 = fmaxf(m1, __shfl_xor_sync(0xffffffffu, m1, 2));

        float s0 = 0.f, s1 = 0.f;
        #pragma unroll
        for (int nt = 0; nt < 4; ++nt) {
            fs[nt][0] = __expf(fs[nt][0] - m0); s0 += fs[nt][0];
            fs[nt][1] = __expf(fs[nt][1] - m0); s0 += fs[nt][1];
            fs[nt][2] = __expf(fs[nt][2] - m1); s1 += fs[nt][2];
            fs[nt][3] = __expf(fs[nt][3] - m1); s1 += fs[nt][3];
        }
        s0 += __shfl_xor_sync(0xffffffffu, s0, 1);
        s0 += __shfl_xor_sync(0xffffffffu, s0, 2);
        s1 += __shfl_xor_sync(0xffffffffu, s1, 1);
        s1 += __shfl_xor_sync(0xffffffffu, s1, 2);
        float r0 = __fdividef(1.f, s0);
        float r1 = __fdividef(1.f, s1);

        // AV: out[16 d][32 c] = P[16 d][32 e] @ V[32 e][32 c], fp16 m16n8k16.
        // P fragments convert in-register: score C-frag pairs == f16 A-frag pairs.
        float od[4][4];
        #pragma unroll
        for (int nt = 0; nt < 4; ++nt)
            #pragma unroll
            for (int v = 0; v < 4; ++v) od[nt][v] = 0.f;

        const uint32_t* svw = &sv32[aw * 1168];
        #pragma unroll
        for (int ks = 0; ks < 2; ++ks) {
            uint32_t a0 = h2pack(fs[2 * ks][0] * r0, fs[2 * ks][1] * r0);
            uint32_t a1 = h2pack(fs[2 * ks][2] * r1, fs[2 * ks][3] * r1);
            uint32_t a2 = h2pack(fs[2 * ks + 1][0] * r0, fs[2 * ks + 1][1] * r0);
            uint32_t a3 = h2pack(fs[2 * ks + 1][2] * r1, fs[2 * ks + 1][3] * r1);
            #pragma unroll
            for (int ntd = 0; ntd < 4; ++ntd) {
                int col = ch + ntd * 8 + g;
                uint32_t b0 = svw[(8 * ks + t) * 72 + col];
                uint32_t b1 = svw[(8 * ks + t + 4) * 72 + col];
                mma_f16(od[ntd], a0, a1, a2, a3, b0, b1);
            }
        }
        // od[ntd][v]: out[d = dh + g + (v>>1)*8][c = ch + ntd*8 + 2t + (v&1)]

        #pragma unroll
        for (int ntd = 0; ntd < 4; ++ntd) {
            #pragma unroll
            for (int v = 0; v < 4; ++v) {
                int c = ch + ntd * 8 + 2 * t + (v & 1);
                int d = dh + g + (v >> 1) * 8;
                sout[c * 136 + aw * 32 + d] = od[ntd][v];
            }
        }
    }
    __syncthreads();                                     // barrier 3 (sout ready)

    // ---- Epilogue: out = g*attn_out + (1-g)*x, coalesced ----
    const float gm = gamma[0];
    const float g_ = 1.f / (1.f + __expf(-gm));
    const float g1 = 1.f - g_;
    #pragma unroll
    for (int it = 0; it < 4; ++it) {
        int i = tid + it * NTHREADS;
        int c = i >> 5, d = i & 31;
        size_t gaddr = base + ((size_t)c * D_DIM + d) * HW;
        float4 xv = *reinterpret_cast<const float4*>(x + gaddr);
        float4 r;
        r.x = g_ * sout[c * 136 +  0 + d] + g1 * xv.x;
        r.y = g_ * sout[c * 136 + 32 + d] + g1 * xv.y;
        r.z = g_ * sout[c * 136 + 64 + d] + g1 * xv.z;
        r.w = g_ * sout[c * 136 + 96 + d] + g1 * xv.w;
        *reinterpret_cast<float4*>(out + gaddr) = r;
    }
}

// ---------------------------------------------------------------------------
extern "C" void kernel_launch(void* const* d_in, const int* in_sizes, int n_in,
                              void* d_out, int out_size) {
    const float* x        = (const float*)d_in[0];
    const float* text_emb = (const float*)d_in[1];
    const float* wq       = (const float*)d_in[2];
    const float* bq       = (const float*)d_in[3];
    const float* wk       = (const float*)d_in[4];
    const float* bk       = (const float*)d_in[5];
    const float* wv       = (const float*)d_in[6];
    const float* bv       = (const float*)d_in[7];
    const float* wt       = (const float*)d_in[8];
    const float* bt       = (const float*)d_in[9];
    const float* pos      = (const float*)d_in[10];
    const float* gamma    = (const float*)d_in[11];
    float* out = (float*)d_out;

    cudaFuncSetAttribute(attn_kernel, cudaFuncAttributeMaxDynamicSharedMemorySize, SMEM_BYTES);

    setup_kernel<<<1, 256>>>(text_emb, wt, bt, wq, wk, wv);

    const int grid = B_DIM * H_DIM * (W_DIM / WT);  // 4608
    attn_kernel<<<grid, NTHREADS, SMEM_BYTES>>>(x, bq, bk, bv, pos, gamma, out);
}

// round 9
// speedup vs baseline: 1.3166x; 1.1100x over previous
#include <cuda_runtime.h>
#include <cuda_fp16.h>
#include <math.h>
#include <stdint.h>

// Problem constants
#define C_DIM 64
#define D_DIM 32
#define H_DIM 96
#define W_DIM 96
#define B_DIM 2
#define WT 4          // w-tile per block
#define NTHREADS 512

// smem layout (float units)
#define SX_OFF    0       // x tile [64][136] fp32 = 8704 ; after phase B: sout[c*136 + w*32 + d]
#define SQH_OFF   8704    // Q fp16 [4 w (*1288h)][32 d (*40h)][q] : 5152 halves = 2576 floats
#define SKH_OFF   11280   // K fp16 [4 w (*1288h)][32 e (*40h)][q] : 2576 floats
#define SVH_OFF   13856   // V fp16 pairs: uint32 [4 w (*1168)][16 epair (*72)][64 c] : 4672 words
#define SBIAS_OFF 18528   // 128
#define SPOS_OFF  18656   // 1024
#define SMEM_FLOATS 19680
#define SMEM_BYTES (SMEM_FLOATS * 4)   // 78720 B -> 2 CTAs/SM

__device__ float g_tb[32];
__device__ float g_wpack[8192];   // prepacked tf32 W in A-fragment order

__device__ __forceinline__ float tf32r(float x) {
    uint32_t u;
    asm("cvt.rna.tf32.f32 %0, %1;" : "=r"(u) : "f"(x));
    return __uint_as_float(u);
}

__device__ __forceinline__ void mma_tf32(float* d, const float4& a, uint32_t b0, uint32_t b1) {
    const uint32_t* A = reinterpret_cast<const uint32_t*>(&a);
    asm volatile(
        "mma.sync.aligned.m16n8k8.row.col.f32.tf32.tf32.f32 "
        "{%0,%1,%2,%3}, {%4,%5,%6,%7}, {%8,%9}, {%0,%1,%2,%3};"
        : "+f"(d[0]), "+f"(d[1]), "+f"(d[2]), "+f"(d[3])
        : "r"(A[0]), "r"(A[1]), "r"(A[2]), "r"(A[3]), "r"(b0), "r"(b1));
}

__device__ __forceinline__ void mma_f16(float* d, uint32_t a0, uint32_t a1, uint32_t a2,
                                        uint32_t a3, uint32_t b0, uint32_t b1) {
    asm volatile(
        "mma.sync.aligned.m16n8k16.row.col.f32.f16.f16.f32 "
        "{%0,%1,%2,%3}, {%4,%5,%6,%7}, {%8,%9}, {%0,%1,%2,%3};"
        : "+f"(d[0]), "+f"(d[1]), "+f"(d[2]), "+f"(d[3])
        : "r"(a0), "r"(a1), "r"(a2), "r"(a3), "r"(b0), "r"(b1));
}

__device__ __forceinline__ uint32_t h2pack(float lo, float hi) {
    __half2 h = __floats2half2_rn(lo, hi);
    return *reinterpret_cast<uint32_t*>(&h);
}

__device__ __forceinline__ void cp16(float* smem_dst, const float* gmem_src) {
    unsigned s = (unsigned)__cvta_generic_to_shared(smem_dst);
    asm volatile("cp.async.ca.shared.global [%0], [%1], 16;" :: "r"(s), "l"(gmem_src));
}

// ---------------------------------------------------------------------------
// Setup kernel: text bias + weight prepack (fragment order, tf32-rounded)
// ---------------------------------------------------------------------------
__global__ void setup_kernel(const float* __restrict__ text_emb,
                             const float* __restrict__ wt,
                             const float* __restrict__ bt,
                             const float* __restrict__ wq,
                             const float* __restrict__ wk,
                             const float* __restrict__ wv) {
    __shared__ float mcol[256];
    int t = threadIdx.x;
    float s = 0.f;
    #pragma unroll
    for (int r = 0; r < 32; ++r) s += text_emb[r * 256 + t];
    mcol[t] = s * (1.0f / 32.0f);
    __syncthreads();
    int warp = t >> 5, lane = t & 31;
    for (int q = warp; q < 32; q += 8) {
        float acc = 0.f;
        #pragma unroll
        for (int k = 0; k < 8; ++k) acc += wt[q * 256 + lane + k * 32] * mcol[lane + k * 32];
        #pragma unroll
        for (int o = 16; o > 0; o >>= 1) acc += __shfl_xor_sync(0xffffffffu, acc, o);
        if (lane == 0) g_tb[q] = acc + bt[q];
    }
    // g_wpack[((mt*8+kt)*32 + lane)*4 + v] = W[mt*16+g+(v&1)*8][kt*8+tt+(v>>1)*4]
    #pragma unroll
    for (int it = 0; it < 32; ++it) {
        int idx  = t + it * 256;
        int v    = idx & 3;
        int ln   = (idx >> 2) & 31;
        int kt   = (idx >> 7) & 7;
        int mt   = idx >> 10;
        int g = ln >> 2, tt = ln & 3;
        int o = mt * 16 + g + (v & 1) * 8;
        int c = kt * 8 + tt + (v >> 1) * 4;
        float wval;
        if (o < 32)       wval = wq[o * 64 + c];
        else if (o < 64)  wval = wk[(o - 32) * 64 + c];
        else              wval = wv[(o - 64) * 64 + c];
        g_wpack[idx] = tf32r(wval);
    }
}

// ---------------------------------------------------------------------------
// Main fused kernel: one block per (b, h, w-tile of 4); 512 threads, 2 CTA/SM
// ---------------------------------------------------------------------------
__global__ __launch_bounds__(NTHREADS, 2)
void attn_kernel(const float* __restrict__ x,
                 const float* __restrict__ bq, const float* __restrict__ bk,
                 const float* __restrict__ bv,
                 const float* __restrict__ pos, const float* __restrict__ gamma,
                 float* __restrict__ out) {
    extern __shared__ float sm[];
    float* sx    = sm + SX_OFF;    // x tile (A/B), sout afterwards
    __half* sqh  = reinterpret_cast<__half*>(sm + SQH_OFF);
    __half* skh  = reinterpret_cast<__half*>(sm + SKH_OFF);
    __half* sv_h = reinterpret_cast<__half*>(sm + SVH_OFF);
    uint32_t* sv32 = reinterpret_cast<uint32_t*>(sm + SVH_OFF);
    float* sbias = sm + SBIAS_OFF;
    float* spos  = sm + SPOS_OFF;
    float* sout  = sm + SX_OFF;    // staging reuse (x region dead after phase B)

    const int tid = threadIdx.x;
    const int bid = blockIdx.x;
    const int nwT = W_DIM / WT;   // 24
    const int b   = bid / (H_DIM * nwT);
    const int rem = bid % (H_DIM * nwT);
    const int h   = rem / nwT;
    const int w0  = (rem % nwT) * WT;

    const int HW = H_DIM * W_DIM; // 9216
    const size_t base = (size_t)b * C_DIM * D_DIM * HW + (size_t)h * W_DIM + w0;

    // ---- Phase A: async x tile load (raw fp32; HMMA.TF32 truncates) ----
    #pragma unroll
    for (int it = 0; it < 4; ++it) {
        int i = tid + it * NTHREADS;          // 2048 float4s
        int c = i >> 5, d = i & 31;
        cp16(&sx[c * 136 + d * 4], x + base + ((size_t)c * D_DIM + d) * HW);
    }
    if (tid < 128) {
        float bb;
        if (tid < 32)      bb = bq[tid] + g_tb[tid];
        else if (tid < 64) bb = bk[tid - 32] + g_tb[tid - 32];
        else               bb = bv[tid - 64];
        sbias[tid] = bb;
    }
    #pragma unroll
    for (int it = 0; it < 2; ++it) spos[tid + it * NTHREADS] = pos[tid + it * NTHREADS];
    asm volatile("cp.async.commit_group;");
    asm volatile("cp.async.wait_group 0;" ::: "memory");
    __syncthreads();                                     // barrier 1

    // ---- Phase B: tf32 MMA GEMM  C[128 o][128 n] = W[128,64] * X[64,128] ----
    // 16 warps = 4 o-groups of 32 (Q, K, V0, V1) x 4 n-quarters of 32.
    const int warp = tid >> 5, lane = tid & 31;
    const int g = lane >> 2, t = lane & 3;
    const int mw = warp & 3;        // 0:Q 1:K 2:V(c0-31) 3:V(c32-63)
    const int nq = warp >> 2;       // n quarter (32 wide)

    {
        float acc[2][4][4];
        #pragma unroll
        for (int s_ = 0; s_ < 2; ++s_)
            #pragma unroll
            for (int nt = 0; nt < 4; ++nt)
                #pragma unroll
                for (int v = 0; v < 4; ++v) acc[s_][nt][v] = 0.f;

        const float4* wp4 = reinterpret_cast<const float4*>(g_wpack);
        #pragma unroll
        for (int kt = 0; kt < 8; ++kt) {
            float4 a0 = __ldg(&wp4[((mw * 2 + 0) * 8 + kt) * 32 + lane]);
            float4 a1 = __ldg(&wp4[((mw * 2 + 1) * 8 + kt) * 32 + lane]);
            const float* xr0 = &sx[(kt * 8 + t) * 136 + nq * 32 + g];
            const float* xr1 = &sx[(kt * 8 + t + 4) * 136 + nq * 32 + g];
            #pragma unroll
            for (int nt = 0; nt < 4; ++nt) {
                uint32_t b0 = __float_as_uint(xr0[nt * 8]);
                uint32_t b1 = __float_as_uint(xr1[nt * 8]);
                mma_tf32(acc[0][nt], a0, b0, b1);
                mma_tf32(acc[1][nt], a1, b0, b1);
            }
        }

        if (mw < 2) {
            // Q -> sqh[w*1288 + d*40 + q] fp16 (scaled); K -> skh[w*1288 + e*40 + q]
            __half* dsth = (mw == 0) ? sqh : skh;
            const int boff = mw * 32;
            const float qscale = (mw == 0) ? 0.17677669529663687f : 1.0f;
            #pragma unroll
            for (int s_ = 0; s_ < 2; ++s_) {
                #pragma unroll
                for (int nt = 0; nt < 4; ++nt) {
                    #pragma unroll
                    for (int v = 0; v < 4; ++v) {
                        int q = s_ * 16 + g + (v >> 1) * 8;
                        int n = nq * 32 + nt * 8 + 2 * t + (v & 1);
                        int outer = n >> 2, w = n & 3;   // d for Q, e for K
                        float val = acc[s_][nt][v] + sbias[boff + q] + spos[q * 32 + outer];
                        dsth[w * 1288 + outer * 40 + q] = __float2half_rn(val * qscale);
                    }
                }
            }
        } else {
            // V -> fp16 B-fragment layout sv32[w*1168 + (e>>1)*72 + c], e-parity = half
            const int cbb = (mw - 2) * 32;
            #pragma unroll
            for (int s_ = 0; s_ < 2; ++s_) {
                #pragma unroll
                for (int nt = 0; nt < 4; ++nt) {
                    #pragma unroll
                    for (int v = 0; v < 4; ++v) {
                        int c = cbb + s_ * 16 + g + (v >> 1) * 8;
                        int n = nq * 32 + nt * 8 + 2 * t + (v & 1);
                        int e = n >> 2, w = n & 3;
                        sv_h[(w * 1168 + (e >> 1) * 72 + c) * 2 + (e & 1)] =
                            __float2half_rn(acc[s_][nt][v] + sbias[64 + c]);
                    }
                }
            }
        }
    }
    __syncthreads();                                     // barrier 2 (x reads done, Q/K/V ready)

    // ---- Phases C+D fused per warp: (w, d-half, c-half) ----
    const int aw = warp & 3;
    const int dh = ((warp >> 2) & 1) * 16;
    const int ch = (warp >> 3) * 32;
    {
        const __half* qh = &sqh[aw * 1288];   // [d*40 + q]
        const __half* kh = &skh[aw * 1288];   // [e*40 + q]

        // scores S[16 d][32 e] via fp16 m16n8k16 (fp32 accum)
        float fs[4][4];
        #pragma unroll
        for (int nt = 0; nt < 4; ++nt)
            #pragma unroll
            for (int v = 0; v < 4; ++v) fs[nt][v] = 0.f;

        #pragma unroll
        for (int ks = 0; ks < 2; ++ks) {
            uint32_t a0 = *reinterpret_cast<const uint32_t*>(&qh[(dh + g) * 40 + ks * 16 + 2 * t]);
            uint32_t a1 = *reinterpret_cast<const uint32_t*>(&qh[(dh + g + 8) * 40 + ks * 16 + 2 * t]);
            uint32_t a2 = *reinterpret_cast<const uint32_t*>(&qh[(dh + g) * 40 + ks * 16 + 2 * t + 8]);
            uint32_t a3 = *reinterpret_cast<const uint32_t*>(&qh[(dh + g + 8) * 40 + ks * 16 + 2 * t + 8]);
            #pragma unroll
            for (int nt = 0; nt < 4; ++nt) {
                uint32_t b0 = *reinterpret_cast<const uint32_t*>(&kh[(nt * 8 + g) * 40 + ks * 16 + 2 * t]);
                uint32_t b1 = *reinterpret_cast<const uint32_t*>(&kh[(nt * 8 + g) * 40 + ks * 16 + 2 * t + 8]);
                mma_f16(fs[nt], a0, a1, a2, a3, b0, b1);
            }
        }
        // fs[nt][v]: S[d = dh + g + (v>>1)*8][e = nt*8 + 2t + (v&1)]

        // in-warp softmax over e
        float m0 = -1e30f, m1 = -1e30f;
        #pragma unroll
        for (int nt = 0; nt < 4; ++nt) {
            m0 = fmaxf(m0, fmaxf(fs[nt][0], fs[nt][1]));
            m1 = fmaxf(m1, fmaxf(fs[nt][2], fs[nt][3]));
        }
        m0 = fmaxf(m0, __shfl_xor_sync(0xffffffffu, m0, 1));
        m0 = fmaxf(m0, __shfl_xor_sync(0xffffffffu, m0, 2));
        m1 = fmaxf(m1, __shfl_xor_sync(0xffffffffu, m1, 1));
        m1 = fmaxf(m1, __shfl_xor_sync(0xffffffffu, m1, 2));

        float s0 = 0.f, s1 = 0.f;
        #pragma unroll
        for (int nt = 0; nt < 4; ++nt) {
            fs[nt][0] = __expf(fs[nt][0] - m0); s0 += fs[nt][0];
            fs[nt][1] = __expf(fs[nt][1] - m0); s0 += fs[nt][1];
            fs[nt][2] = __expf(fs[nt][2] - m1); s1 += fs[nt][2];
            fs[nt][3] = __expf(fs[nt][3] - m1); s1 += fs[nt][3];
        }
        s0 += __shfl_xor_sync(0xffffffffu, s0, 1);
        s0 += __shfl_xor_sync(0xffffffffu, s0, 2);
        s1 += __shfl_xor_sync(0xffffffffu, s1, 1);
        s1 += __shfl_xor_sync(0xffffffffu, s1, 2);
        float r0 = __fdividef(1.f, s0);
        float r1 = __fdividef(1.f, s1);

        // AV: out[16 d][32 c] = P @ V, fp16 m16n8k16, P converted in-register
        float od[4][4];
        #pragma unroll
        for (int nt = 0; nt < 4; ++nt)
            #pragma unroll
            for (int v = 0; v < 4; ++v) od[nt][v] = 0.f;

        const uint32_t* svw = &sv32[aw * 1168];
        #pragma unroll
        for (int ks = 0; ks < 2; ++ks) {
            uint32_t a0 = h2pack(fs[2 * ks][0] * r0, fs[2 * ks][1] * r0);
            uint32_t a1 = h2pack(fs[2 * ks][2] * r1, fs[2 * ks][3] * r1);
            uint32_t a2 = h2pack(fs[2 * ks + 1][0] * r0, fs[2 * ks + 1][1] * r0);
            uint32_t a3 = h2pack(fs[2 * ks + 1][2] * r1, fs[2 * ks + 1][3] * r1);
            #pragma unroll
            for (int ntd = 0; ntd < 4; ++ntd) {
                int col = ch + ntd * 8 + g;
                uint32_t b0 = svw[(8 * ks + t) * 72 + col];
                uint32_t b1 = svw[(8 * ks + t + 4) * 72 + col];
                mma_f16(od[ntd], a0, a1, a2, a3, b0, b1);
            }
        }
        // od[ntd][v]: out[d = dh + g + (v>>1)*8][c = ch + ntd*8 + 2t + (v&1)]

        #pragma unroll
        for (int ntd = 0; ntd < 4; ++ntd) {
            #pragma unroll
            for (int v = 0; v < 4; ++v) {
                int c = ch + ntd * 8 + 2 * t + (v & 1);
                int d = dh + g + (v >> 1) * 8;
                sout[c * 136 + aw * 32 + d] = od[ntd][v];
            }
        }
    }
    __syncthreads();                                     // barrier 3 (sout ready)

    // ---- Epilogue: out = g*attn_out + (1-g)*x, coalesced ----
    const float gm = gamma[0];
    const float g_ = 1.f / (1.f + __expf(-gm));
    const float g1 = 1.f - g_;
    #pragma unroll
    for (int it = 0; it < 4; ++it) {
        int i = tid + it * NTHREADS;
        int c = i >> 5, d = i & 31;
        size_t gaddr = base + ((size_t)c * D_DIM + d) * HW;
        float4 xv = *reinterpret_cast<const float4*>(x + gaddr);
        float4 r;
        r.x = g_ * sout[c * 136 +  0 + d] + g1 * xv.x;
        r.y = g_ * sout[c * 136 + 32 + d] + g1 * xv.y;
        r.z = g_ * sout[c * 136 + 64 + d] + g1 * xv.z;
        r.w = g_ * sout[c * 136 + 96 + d] + g1 * xv.w;
        *reinterpret_cast<float4*>(out + gaddr) = r;
    }
}

// ---------------------------------------------------------------------------
extern "C" void kernel_launch(void* const* d_in, const int* in_sizes, int n_in,
                              void* d_out, int out_size) {
    const float* x        = (const float*)d_in[0];
    const float* text_emb = (const float*)d_in[1];
    const float* wq       = (const float*)d_in[2];
    const float* bq       = (const float*)d_in[3];
    const float* wk       = (const float*)d_in[4];
    const float* bk       = (const float*)d_in[5];
    const float* wv       = (const float*)d_in[6];
    const float* bv       = (const float*)d_in[7];
    const float* wt       = (const float*)d_in[8];
    const float* bt       = (const float*)d_in[9];
    const float* pos      = (const float*)d_in[10];
    const float* gamma    = (const float*)d_in[11];
    float* out = (float*)d_out;

    cudaFuncSetAttribute(attn_kernel, cudaFuncAttributeMaxDynamicSharedMemorySize, SMEM_BYTES);

    setup_kernel<<<1, 256>>>(text_emb, wt, bt, wq, wk, wv);

    const int grid = B_DIM * H_DIM * (W_DIM / WT);  // 4608
    attn_kernel<<<grid, NTHREADS, SMEM_BYTES>>>(x, bq, bk, bv, pos, gamma, out);
}

// round 10
// speedup vs baseline: 1.4306x; 1.0866x over previous
#include <cuda_runtime.h>
#include <cuda_fp16.h>
#include <math.h>
#include <stdint.h>

// Problem constants
#define C_DIM 64
#define D_DIM 32
#define H_DIM 96
#define W_DIM 96
#define B_DIM 2
#define WT 4          // w-tile per block
#define NTHREADS 512

// smem layout (float/word units)
#define SXW_OFF   0       // x fp16 c-pair words: [32 cp (*136)][128 n] : 4352 words
#define SQH_OFF   4352    // Q fp16 [4 w (*1288h)][32 d (*40h)][q] : 2576 floats
#define SKH_OFF   6928    // K fp16 [4 w (*1288h)][32 e (*40h)][q] : 2576 floats
#define SVH_OFF   9504    // V fp16 pairs: uint32 [4 w (*1168)][16 epair (*72)][64 c] : 4672 words
#define SOUT_OFF  14176   // out staging fp32 [64 c (*136)][4 w (*32)][32 d] : 8704
#define SBIAS_OFF 22880   // 128
#define SPOS_OFF  23008   // 1024
#define SMEM_FLOATS 24032
#define SMEM_BYTES (SMEM_FLOATS * 4)   // 96128 B -> 2 CTAs/SM

__device__ float g_tb[32];
__device__ uint32_t g_wpackh[4096];   // prepacked fp16 W in m16n8k16 A-fragment order

__device__ __forceinline__ void mma_f16(float* d, uint32_t a0, uint32_t a1, uint32_t a2,
                                        uint32_t a3, uint32_t b0, uint32_t b1) {
    asm volatile(
        "mma.sync.aligned.m16n8k16.row.col.f32.f16.f16.f32 "
        "{%0,%1,%2,%3}, {%4,%5,%6,%7}, {%8,%9}, {%0,%1,%2,%3};"
        : "+f"(d[0]), "+f"(d[1]), "+f"(d[2]), "+f"(d[3])
        : "r"(a0), "r"(a1), "r"(a2), "r"(a3), "r"(b0), "r"(b1));
}

__device__ __forceinline__ uint32_t h2pack(float lo, float hi) {
    __half2 h = __floats2half2_rn(lo, hi);
    return *reinterpret_cast<uint32_t*>(&h);
}

// ---------------------------------------------------------------------------
// Setup kernel: text bias + weight prepack (fp16 A-fragment order for k16)
// ---------------------------------------------------------------------------
__global__ void setup_kernel(const float* __restrict__ text_emb,
                             const float* __restrict__ wt,
                             const float* __restrict__ bt,
                             const float* __restrict__ wq,
                             const float* __restrict__ wk,
                             const float* __restrict__ wv) {
    __shared__ float mcol[256];
    int t = threadIdx.x;
    float s = 0.f;
    #pragma unroll
    for (int r = 0; r < 32; ++r) s += text_emb[r * 256 + t];
    mcol[t] = s * (1.0f / 32.0f);
    __syncthreads();
    int warp = t >> 5, lane = t & 31;
    for (int q = warp; q < 32; q += 8) {
        float acc = 0.f;
        #pragma unroll
        for (int k = 0; k < 8; ++k) acc += wt[q * 256 + lane + k * 32] * mcol[lane + k * 32];
        #pragma unroll
        for (int o = 16; o > 0; o >>= 1) acc += __shfl_xor_sync(0xffffffffu, acc, o);
        if (lane == 0) g_tb[q] = acc + bt[q];
    }
    // g_wpackh[((mt*4+ks)*32 + lane)*4 + j] = pair {W[o][k], W[o][k+1]}
    //   o = mt*16 + g + (j&1)*8 ; k = ks*16 + 2*tt + (j>>1)*8
    #pragma unroll
    for (int it = 0; it < 16; ++it) {
        int idx  = t + it * 256;    // 4096 words
        int j    = idx & 3;
        int ln   = (idx >> 2) & 31;
        int ks   = (idx >> 7) & 3;
        int mt   = idx >> 9;
        int g = ln >> 2, tt = ln & 3;
        int o = mt * 16 + g + (j & 1) * 8;
        int k = ks * 16 + 2 * tt + (j >> 1) * 8;
        float v0, v1;
        if (o < 32)       { v0 = wq[o * 64 + k];        v1 = wq[o * 64 + k + 1]; }
        else if (o < 64)  { v0 = wk[(o - 32) * 64 + k]; v1 = wk[(o - 32) * 64 + k + 1]; }
        else              { v0 = wv[(o - 64) * 64 + k]; v1 = wv[(o - 64) * 64 + k + 1]; }
        __half2 h = __floats2half2_rn(v0, v1);
        g_wpackh[idx] = *reinterpret_cast<uint32_t*>(&h);
    }
}

// ---------------------------------------------------------------------------
// Main fused kernel: one block per (b, h, w-tile of 4); 512 threads, 2 CTA/SM
// ---------------------------------------------------------------------------
__global__ __launch_bounds__(NTHREADS, 2)
void attn_kernel(const float* __restrict__ x,
                 const float* __restrict__ bq, const float* __restrict__ bk,
                 const float* __restrict__ bv,
                 const float* __restrict__ pos, const float* __restrict__ gamma,
                 float* __restrict__ out) {
    extern __shared__ float sm[];
    uint32_t* sxw  = reinterpret_cast<uint32_t*>(sm + SXW_OFF);   // x fp16 c-pair words
    __half* sqh    = reinterpret_cast<__half*>(sm + SQH_OFF);
    __half* skh    = reinterpret_cast<__half*>(sm + SKH_OFF);
    __half* sv_h   = reinterpret_cast<__half*>(sm + SVH_OFF);
    uint32_t* sv32 = reinterpret_cast<uint32_t*>(sm + SVH_OFF);
    float* sout    = sm + SOUT_OFF;
    float* sbias   = sm + SBIAS_OFF;
    float* spos    = sm + SPOS_OFF;

    const int tid = threadIdx.x;
    const int bid = blockIdx.x;
    const int nwT = W_DIM / WT;   // 24
    const int b   = bid / (H_DIM * nwT);
    const int rem = bid % (H_DIM * nwT);
    const int h   = rem / nwT;
    const int w0  = (rem % nwT) * WT;

    const int HW = H_DIM * W_DIM; // 9216
    const size_t base = (size_t)b * C_DIM * D_DIM * HW + (size_t)h * W_DIM + w0;

    const int warp = tid >> 5, lane = tid & 31;
    const int g = lane >> 2, t = lane & 3;

    // ---- Phase A: load x, pack fp16 c-pairs: sxw[cp*136 + n] = {x[2cp], x[2cp+1]} ----
    #pragma unroll
    for (int it = 0; it < 2; ++it) {
        int cp = warp + it * 16;            // c-pair 0..31
        int d  = lane;
        const float* p0 = x + base + ((size_t)(2 * cp) * D_DIM + d) * HW;
        const float* p1 = x + base + ((size_t)(2 * cp + 1) * D_DIM + d) * HW;
        float4 v0 = *reinterpret_cast<const float4*>(p0);
        float4 v1 = *reinterpret_cast<const float4*>(p1);
        uint4 wv_;
        wv_.x = h2pack(v0.x, v1.x);
        wv_.y = h2pack(v0.y, v1.y);
        wv_.z = h2pack(v0.z, v1.z);
        wv_.w = h2pack(v0.w, v1.w);
        *reinterpret_cast<uint4*>(&sxw[cp * 136 + d * 4]) = wv_;   // banks 4d+8cp: conflict-free
    }
    if (tid < 128) {
        float bb;
        if (tid < 32)      bb = bq[tid] + g_tb[tid];
        else if (tid < 64) bb = bk[tid - 32] + g_tb[tid - 32];
        else               bb = bv[tid - 64];
        sbias[tid] = bb;
    }
    #pragma unroll
    for (int it = 0; it < 2; ++it) spos[tid + it * NTHREADS] = pos[tid + it * NTHREADS];
    __syncthreads();                                     // barrier 1

    // ---- Phase B: fp16 MMA GEMM  C[128 o][128 n] = W[128,64] * X[64,128] ----
    // 16 warps = 4 o-groups of 32 (Q, K, V0, V1) x 4 n-quarters of 32. k16 x 4 steps.
    const int mw = warp & 3;        // 0:Q 1:K 2:V(c0-31) 3:V(c32-63)
    const int nq = warp >> 2;       // n quarter (32 wide)

    {
        float acc[2][4][4];
        #pragma unroll
        for (int s_ = 0; s_ < 2; ++s_)
            #pragma unroll
            for (int nt = 0; nt < 4; ++nt)
                #pragma unroll
                for (int v = 0; v < 4; ++v) acc[s_][nt][v] = 0.f;

        const uint4* wp4 = reinterpret_cast<const uint4*>(g_wpackh);
        #pragma unroll
        for (int ks = 0; ks < 4; ++ks) {
            uint4 a0 = __ldg(&wp4[((mw * 2 + 0) * 4 + ks) * 32 + lane]);
            uint4 a1 = __ldg(&wp4[((mw * 2 + 1) * 4 + ks) * 32 + lane]);
            const uint32_t* xr0 = &sxw[(ks * 8 + t) * 136 + nq * 32 + g];
            const uint32_t* xr1 = &sxw[(ks * 8 + t + 4) * 136 + nq * 32 + g];
            #pragma unroll
            for (int nt = 0; nt < 4; ++nt) {       // banks 8t+8nt+g: conflict-free
                uint32_t b0 = xr0[nt * 8];
                uint32_t b1 = xr1[nt * 8];
                mma_f16(acc[0][nt], a0.x, a0.y, a0.z, a0.w, b0, b1);
                mma_f16(acc[1][nt], a1.x, a1.y, a1.z, a1.w, b0, b1);
            }
        }

        if (mw < 2) {
            // Q -> sqh[w*1288 + d*40 + q] fp16 (scaled); K -> skh[w*1288 + e*40 + q]
            __half* dsth = (mw == 0) ? sqh : skh;
            const int boff = mw * 32;
            const float qscale = (mw == 0) ? 0.17677669529663687f : 1.0f;
            #pragma unroll
            for (int s_ = 0; s_ < 2; ++s_) {
                #pragma unroll
                for (int nt = 0; nt < 4; ++nt) {
                    #pragma unroll
                    for (int v = 0; v < 4; ++v) {
                        int q = s_ * 16 + g + (v >> 1) * 8;
                        int n = nq * 32 + nt * 8 + 2 * t + (v & 1);
                        int outer = n >> 2, w = n & 3;   // d for Q, e for K
                        float val = acc[s_][nt][v] + sbias[boff + q] + spos[q * 32 + outer];
                        dsth[w * 1288 + outer * 40 + q] = __float2half_rn(val * qscale);
                    }
                }
            }
        } else {
            // V -> fp16 B-fragment layout sv32[w*1168 + (e>>1)*72 + c], e-parity = half
            const int cbb = (mw - 2) * 32;
            #pragma unroll
            for (int s_ = 0; s_ < 2; ++s_) {
                #pragma unroll
                for (int nt = 0; nt < 4; ++nt) {
                    #pragma unroll
                    for (int v = 0; v < 4; ++v) {
                        int c = cbb + s_ * 16 + g + (v >> 1) * 8;
                        int n = nq * 32 + nt * 8 + 2 * t + (v & 1);
                        int e = n >> 2, w = n & 3;
                        sv_h[(w * 1168 + (e >> 1) * 72 + c) * 2 + (e & 1)] =
                            __float2half_rn(acc[s_][nt][v] + sbias[64 + c]);
                    }
                }
            }
        }
    }
    __syncthreads();                                     // barrier 2 (Q/K/V ready)

    // ---- Phases C+D fused per warp: (w, d-half, c-half) ----
    const int aw = warp & 3;
    const int dh = ((warp >> 2) & 1) * 16;
    const int ch = (warp >> 3) * 32;
    {
        const __half* qh = &sqh[aw * 1288];   // [d*40 + q]
        const __half* kh = &skh[aw * 1288];   // [e*40 + q]

        // scores S[16 d][32 e] via fp16 m16n8k16 (fp32 accum)
        float fs[4][4];
        #pragma unroll
        for (int nt = 0; nt < 4; ++nt)
            #pragma unroll
            for (int v = 0; v < 4; ++v) fs[nt][v] = 0.f;

        #pragma unroll
        for (int ks = 0; ks < 2; ++ks) {
            uint32_t a0 = *reinterpret_cast<const uint32_t*>(&qh[(dh + g) * 40 + ks * 16 + 2 * t]);
            uint32_t a1 = *reinterpret_cast<const uint32_t*>(&qh[(dh + g + 8) * 40 + ks * 16 + 2 * t]);
            uint32_t a2 = *reinterpret_cast<const uint32_t*>(&qh[(dh + g) * 40 + ks * 16 + 2 * t + 8]);
            uint32_t a3 = *reinterpret_cast<const uint32_t*>(&qh[(dh + g + 8) * 40 + ks * 16 + 2 * t + 8]);
            #pragma unroll
            for (int nt = 0; nt < 4; ++nt) {
                uint32_t b0 = *reinterpret_cast<const uint32_t*>(&kh[(nt * 8 + g) * 40 + ks * 16 + 2 * t]);
                uint32_t b1 = *reinterpret_cast<const uint32_t*>(&kh[(nt * 8 + g) * 40 + ks * 16 + 2 * t + 8]);
                mma_f16(fs[nt], a0, a1, a2, a3, b0, b1);
            }
        }
        // fs[nt][v]: S[d = dh + g + (v>>1)*8][e = nt*8 + 2t + (v&1)]

        // in-warp softmax over e
        float m0 = -1e30f, m1 = -1e30f;
        #pragma unroll
        for (int nt = 0; nt < 4; ++nt) {
            m0 = fmaxf(m0, fmaxf(fs[nt][0], fs[nt][1]));
            m1 = fmaxf(m1, fmaxf(fs[nt][2], fs[nt][3]));
        }
        m0 = fmaxf(m0, __shfl_xor_sync(0xffffffffu, m0, 1));
        m0 = fmaxf(m0, __shfl_xor_sync(0xffffffffu, m0, 2));
        m1 = fmaxf(m1, __shfl_xor_sync(0xffffffffu, m1, 1));
        m1 = fmaxf(m1, __shfl_xor_sync(0xffffffffu, m1, 2));

        float s0 = 0.f, s1 = 0.f;
        #pragma unroll
        for (int nt = 0; nt < 4; ++nt) {
            fs[nt][0] = __expf(fs[nt][0] - m0); s0 += fs[nt][0];
            fs[nt][1] = __expf(fs[nt][1] - m0); s0 += fs[nt][1];
            fs[nt][2] = __expf(fs[nt][2] - m1); s1 += fs[nt][2];
            fs[nt][3] = __expf(fs[nt][3] - m1); s1 += fs[nt][3];
        }
        s0 += __shfl_xor_sync(0xffffffffu, s0, 1);
        s0 += __shfl_xor_sync(0xffffffffu, s0, 2);
        s1 += __shfl_xor_sync(0xffffffffu, s1, 1);
        s1 += __shfl_xor_sync(0xffffffffu, s1, 2);
        float r0 = __fdividef(1.f, s0);
        float r1 = __fdividef(1.f, s1);

        // AV: out[16 d][32 c] = P @ V, fp16 m16n8k16, P converted in-register
        float od[4][4];
        #pragma unroll
        for (int nt = 0; nt < 4; ++nt)
            #pragma unroll
            for (int v = 0; v < 4; ++v) od[nt][v] = 0.f;

        const uint32_t* svw = &sv32[aw * 1168];
        #pragma unroll
        for (int ks = 0; ks < 2; ++ks) {
            uint32_t a0 = h2pack(fs[2 * ks][0] * r0, fs[2 * ks][1] * r0);
            uint32_t a1 = h2pack(fs[2 * ks][2] * r1, fs[2 * ks][3] * r1);
            uint32_t a2 = h2pack(fs[2 * ks + 1][0] * r0, fs[2 * ks + 1][1] * r0);
            uint32_t a3 = h2pack(fs[2 * ks + 1][2] * r1, fs[2 * ks + 1][3] * r1);
            #pragma unroll
            for (int ntd = 0; ntd < 4; ++ntd) {
                int col = ch + ntd * 8 + g;
                uint32_t b0 = svw[(8 * ks + t) * 72 + col];
                uint32_t b1 = svw[(8 * ks + t + 4) * 72 + col];
                mma_f16(od[ntd], a0, a1, a2, a3, b0, b1);
            }
        }
        // od[ntd][v]: out[d = dh + g + (v>>1)*8][c = ch + ntd*8 + 2t + (v&1)]

        #pragma unroll
        for (int ntd = 0; ntd < 4; ++ntd) {
            #pragma unroll
            for (int v = 0; v < 4; ++v) {
                int c = ch + ntd * 8 + 2 * t + (v & 1);
                int d = dh + g + (v >> 1) * 8;
                sout[c * 136 + aw * 32 + d] = od[ntd][v];
            }
        }
    }
    __syncthreads();                                     // barrier 3 (sout ready)

    // ---- Epilogue: out = g*attn_out + (1-g)*x, coalesced ----
    const float gm = gamma[0];
    const float g_ = 1.f / (1.f + __expf(-gm));
    const float g1 = 1.f - g_;
    #pragma unroll
    for (int it = 0; it < 4; ++it) {
        int i = tid + it * NTHREADS;
        int c = i >> 5, d = i & 31;
        size_t gaddr = base + ((size_t)c * D_DIM + d) * HW;
        float4 xv = *reinterpret_cast<const float4*>(x + gaddr);
        float4 r;
        r.x = g_ * sout[c * 136 +  0 + d] + g1 * xv.x;
        r.y = g_ * sout[c * 136 + 32 + d] + g1 * xv.y;
        r.z = g_ * sout[c * 136 + 64 + d] + g1 * xv.z;
        r.w = g_ * sout[c * 136 + 96 + d] + g1 * xv.w;
        *reinterpret_cast<float4*>(out + gaddr) = r;
    }
}

// ---------------------------------------------------------------------------
extern "C" void kernel_launch(void* const* d_in, const int* in_sizes, int n_in,
                              void* d_out, int out_size) {
    const float* x        = (const float*)d_in[0];
    const float* text_emb = (const float*)d_in[1];
    const float* wq       = (const float*)d_in[2];
    const float* bq       = (const float*)d_in[3];
    const float* wk       = (const float*)d_in[4];
    const float* bk       = (const float*)d_in[5];
    const float* wv       = (const float*)d_in[6];
    const float* bv       = (const float*)d_in[7];
    const float* wt       = (const float*)d_in[8];
    const float* bt       = (const float*)d_in[9];
    const float* pos      = (const float*)d_in[10];
    const float* gamma    = (const float*)d_in[11];
    float* out = (float*)d_out;

    cudaFuncSetAttribute(attn_kernel, cudaFuncAttributeMaxDynamicSharedMemorySize, SMEM_BYTES);

    setup_kernel<<<1, 256>>>(text_emb, wt, bt, wq, wk, wv);

    const int grid = B_DIM * H_DIM * (W_DIM / WT);  // 4608
    attn_kernel<<<grid, NTHREADS, SMEM_BYTES>>>(x, bq, bk, bv, pos, gamma, out);
}

// round 11
// speedup vs baseline: 1.4753x; 1.0312x over previous
#include <cuda_runtime.h>
#include <cuda_fp16.h>
#include <math.h>
#include <stdint.h>

// Problem constants
#define C_DIM 64
#define D_DIM 32
#define H_DIM 96
#define W_DIM 96
#define B_DIM 2
#define WT 4          // w-tile per block
#define NTHREADS 512

// smem layout (float/word units)
#define SXW_OFF   0       // x fp16 c-pair words: [32 cp (*136)][128 n] : 4352 words
#define SQH_OFF   4352    // Q fp16 [4 w (*1288h)][32 d (*40h)][q] : 2576 floats
#define SKH_OFF   6928    // K fp16 [4 w (*1288h)][32 e (*40h)][q] : 2576 floats
#define SVH_OFF   9504    // V fp16 pairs: uint32 [4 w (*1168)][16 epair (*72)][64 c] : 4672 words
#define SOUT_OFF  14176   // out staging fp32 [64 c (*132)][4 w (*32)][32 d] : 8448
#define SBIAS_OFF 22624   // 128
#define SPOS_OFF  22752   // 1024
#define SMEM_FLOATS 23776
#define SMEM_BYTES (SMEM_FLOATS * 4)   // 95104 B -> 2 CTAs/SM

__device__ float g_tb[32];
__device__ uint32_t g_wpackh[4096];   // prepacked fp16 W in m16n8k16 A-fragment order

__device__ __forceinline__ void mma_f16(float* d, uint32_t a0, uint32_t a1, uint32_t a2,
                                        uint32_t a3, uint32_t b0, uint32_t b1) {
    asm volatile(
        "mma.sync.aligned.m16n8k16.row.col.f32.f16.f16.f32 "
        "{%0,%1,%2,%3}, {%4,%5,%6,%7}, {%8,%9}, {%0,%1,%2,%3};"
        : "+f"(d[0]), "+f"(d[1]), "+f"(d[2]), "+f"(d[3])
        : "r"(a0), "r"(a1), "r"(a2), "r"(a3), "r"(b0), "r"(b1));
}

__device__ __forceinline__ uint32_t h2pack(float lo, float hi) {
    __half2 h = __floats2half2_rn(lo, hi);
    return *reinterpret_cast<uint32_t*>(&h);
}

__device__ __forceinline__ void ldsm_x4(uint32_t* r, const void* p) {
    uint32_t a = (uint32_t)__cvta_generic_to_shared(p);
    asm volatile("ldmatrix.sync.aligned.m8n8.x4.shared.b16 {%0,%1,%2,%3}, [%4];"
                 : "=r"(r[0]), "=r"(r[1]), "=r"(r[2]), "=r"(r[3]) : "r"(a));
}

// ---------------------------------------------------------------------------
// Setup kernel: text bias + weight prepack (fp16 A-fragment order for k16)
// ---------------------------------------------------------------------------
__global__ void setup_kernel(const float* __restrict__ text_emb,
                             const float* __restrict__ wt,
                             const float* __restrict__ bt,
                             const float* __restrict__ wq,
                             const float* __restrict__ wk,
                             const float* __restrict__ wv) {
    __shared__ float mcol[256];
    int t = threadIdx.x;
    float s = 0.f;
    #pragma unroll
    for (int r = 0; r < 32; ++r) s += text_emb[r * 256 + t];
    mcol[t] = s * (1.0f / 32.0f);
    __syncthreads();
    int warp = t >> 5, lane = t & 31;
    for (int q = warp; q < 32; q += 8) {
        float acc = 0.f;
        #pragma unroll
        for (int k = 0; k < 8; ++k) acc += wt[q * 256 + lane + k * 32] * mcol[lane + k * 32];
        #pragma unroll
        for (int o = 16; o > 0; o >>= 1) acc += __shfl_xor_sync(0xffffffffu, acc, o);
        if (lane == 0) g_tb[q] = acc + bt[q];
    }
    // g_wpackh[((mt*4+ks)*32 + lane)*4 + j] = pair {W[o][k], W[o][k+1]}
    //   o = mt*16 + g + (j&1)*8 ; k = ks*16 + 2*tt + (j>>1)*8
    #pragma unroll
    for (int it = 0; it < 16; ++it) {
        int idx  = t + it * 256;    // 4096 words
        int j    = idx & 3;
        int ln   = (idx >> 2) & 31;
        int ks   = (idx >> 7) & 3;
        int mt   = idx >> 9;
        int g = ln >> 2, tt = ln & 3;
        int o = mt * 16 + g + (j & 1) * 8;
        int k = ks * 16 + 2 * tt + (j >> 1) * 8;
        float v0, v1;
        if (o < 32)       { v0 = wq[o * 64 + k];        v1 = wq[o * 64 + k + 1]; }
        else if (o < 64)  { v0 = wk[(o - 32) * 64 + k]; v1 = wk[(o - 32) * 64 + k + 1]; }
        else              { v0 = wv[(o - 64) * 64 + k]; v1 = wv[(o - 64) * 64 + k + 1]; }
        __half2 h = __floats2half2_rn(v0, v1);
        g_wpackh[idx] = *reinterpret_cast<uint32_t*>(&h);
    }
}

// ---------------------------------------------------------------------------
// Main fused kernel: one block per (b, h, w-tile of 4); 512 threads, 2 CTA/SM
// ---------------------------------------------------------------------------
__global__ __launch_bounds__(NTHREADS, 2)
void attn_kernel(const float* __restrict__ x,
                 const float* __restrict__ bq, const float* __restrict__ bk,
                 const float* __restrict__ bv,
                 const float* __restrict__ pos, const float* __restrict__ gamma,
                 float* __restrict__ out) {
    extern __shared__ float sm[];
    uint32_t* sxw  = reinterpret_cast<uint32_t*>(sm + SXW_OFF);   // x fp16 c-pair words
    __half* sqh    = reinterpret_cast<__half*>(sm + SQH_OFF);
    __half* skh    = reinterpret_cast<__half*>(sm + SKH_OFF);
    __half* sv_h   = reinterpret_cast<__half*>(sm + SVH_OFF);
    uint32_t* sv32 = reinterpret_cast<uint32_t*>(sm + SVH_OFF);
    float* sout    = sm + SOUT_OFF;
    float* sbias   = sm + SBIAS_OFF;
    float* spos    = sm + SPOS_OFF;

    const int tid = threadIdx.x;
    const int bid = blockIdx.x;
    const int nwT = W_DIM / WT;   // 24
    const int b   = bid / (H_DIM * nwT);
    const int rem = bid % (H_DIM * nwT);
    const int h   = rem / nwT;
    const int w0  = (rem % nwT) * WT;

    const int HW = H_DIM * W_DIM; // 9216
    const size_t base = (size_t)b * C_DIM * D_DIM * HW + (size_t)h * W_DIM + w0;

    const int warp = tid >> 5, lane = tid & 31;
    const int g = lane >> 2, t = lane & 3;

    // ---- Phase A: load x, pack fp16 c-pairs: sxw[cp*136 + n] = {x[2cp], x[2cp+1]} ----
    #pragma unroll
    for (int it = 0; it < 2; ++it) {
        int cp = warp + it * 16;            // c-pair 0..31
        int d  = lane;
        const float* p0 = x + base + ((size_t)(2 * cp) * D_DIM + d) * HW;
        const float* p1 = x + base + ((size_t)(2 * cp + 1) * D_DIM + d) * HW;
        float4 v0 = *reinterpret_cast<const float4*>(p0);
        float4 v1 = *reinterpret_cast<const float4*>(p1);
        uint4 wv_;
        wv_.x = h2pack(v0.x, v1.x);
        wv_.y = h2pack(v0.y, v1.y);
        wv_.z = h2pack(v0.z, v1.z);
        wv_.w = h2pack(v0.w, v1.w);
        *reinterpret_cast<uint4*>(&sxw[cp * 136 + d * 4]) = wv_;   // banks 4d+8cp: conflict-free
    }
    if (tid < 128) {
        float bb;
        if (tid < 32)      bb = bq[tid] + g_tb[tid];
        else if (tid < 64) bb = bk[tid - 32] + g_tb[tid - 32];
        else               bb = bv[tid - 64];
        sbias[tid] = bb;
    }
    #pragma unroll
    for (int it = 0; it < 2; ++it) spos[tid + it * NTHREADS] = pos[tid + it * NTHREADS];
    __syncthreads();                                     // barrier 1

    // ---- Phase B: fp16 MMA GEMM  C[128 o][128 n] = W[128,64] * X[64,128] ----
    // 16 warps = 4 o-groups of 32 (Q, K, V0, V1) x 4 n-quarters of 32. k16 x 4 steps.
    const int mw = warp & 3;        // 0:Q 1:K 2:V(c0-31) 3:V(c32-63)
    const int nq = warp >> 2;       // n quarter (32 wide)

    {
        float acc[2][4][4];
        #pragma unroll
        for (int s_ = 0; s_ < 2; ++s_)
            #pragma unroll
            for (int nt = 0; nt < 4; ++nt)
                #pragma unroll
                for (int v = 0; v < 4; ++v) acc[s_][nt][v] = 0.f;

        const uint4* wp4 = reinterpret_cast<const uint4*>(g_wpackh);
        #pragma unroll
        for (int ks = 0; ks < 4; ++ks) {
            uint4 a0 = __ldg(&wp4[((mw * 2 + 0) * 4 + ks) * 32 + lane]);
            uint4 a1 = __ldg(&wp4[((mw * 2 + 1) * 4 + ks) * 32 + lane]);
            const uint32_t* xr0 = &sxw[(ks * 8 + t) * 136 + nq * 32 + g];
            const uint32_t* xr1 = &sxw[(ks * 8 + t + 4) * 136 + nq * 32 + g];
            #pragma unroll
            for (int nt = 0; nt < 4; ++nt) {       // banks 8t+8nt+g: conflict-free
                uint32_t b0 = xr0[nt * 8];
                uint32_t b1 = xr1[nt * 8];
                mma_f16(acc[0][nt], a0.x, a0.y, a0.z, a0.w, b0, b1);
                mma_f16(acc[1][nt], a1.x, a1.y, a1.z, a1.w, b0, b1);
            }
        }

        if (mw < 2) {
            // Q -> sqh[w*1288 + d*40 + q] fp16 (scaled); K -> skh[w*1288 + e*40 + q]
            __half* dsth = (mw == 0) ? sqh : skh;
            const int boff = mw * 32;
            const float qscale = (mw == 0) ? 0.17677669529663687f : 1.0f;
            #pragma unroll
            for (int s_ = 0; s_ < 2; ++s_) {
                #pragma unroll
                for (int nt = 0; nt < 4; ++nt) {
                    #pragma unroll
                    for (int v = 0; v < 4; ++v) {
                        int q = s_ * 16 + g + (v >> 1) * 8;
                        int n = nq * 32 + nt * 8 + 2 * t + (v & 1);
                        int outer = n >> 2, w = n & 3;   // d for Q, e for K
                        float val = acc[s_][nt][v] + sbias[boff + q] + spos[q * 32 + outer];
                        dsth[w * 1288 + outer * 40 + q] = __float2half_rn(val * qscale);
                    }
                }
            }
        } else {
            // V -> fp16 B-fragment layout sv32[w*1168 + (e>>1)*72 + c], e-parity = half
            const int cbb = (mw - 2) * 32;
            #pragma unroll
            for (int s_ = 0; s_ < 2; ++s_) {
                #pragma unroll
                for (int nt = 0; nt < 4; ++nt) {
                    #pragma unroll
                    for (int v = 0; v < 4; ++v) {
                        int c = cbb + s_ * 16 + g + (v >> 1) * 8;
                        int n = nq * 32 + nt * 8 + 2 * t + (v & 1);
                        int e = n >> 2, w = n & 3;
                        sv_h[(w * 1168 + (e >> 1) * 72 + c) * 2 + (e & 1)] =
                            __float2half_rn(acc[s_][nt][v] + sbias[64 + c]);
                    }
                }
            }
        }
    }
    __syncthreads();                                     // barrier 2 (Q/K/V ready)

    // ---- Phases C+D fused per warp: (w, d-half, c-half) ----
    const int aw = warp & 3;
    const int dh = ((warp >> 2) & 1) * 16;
    const int ch = (warp >> 3) * 32;
    float4 xv[4];   // epilogue x prefetch (hoisted above barrier 3)
    {
        const __half* qh = &sqh[aw * 1288];   // [d*40 + q]
        const __half* kh = &skh[aw * 1288];   // [e*40 + q]

        // Q A-fragments + K B-fragments via ldmatrix.x4 (stride 20 words: conflict-free)
        uint32_t qa[2][4];     // [ks] -> a0..a3
        uint32_t kb[2][2][4];  // [ks][nt-pair] -> {b0 nt0, b1 nt0, b0 nt1, b1 nt1}
        #pragma unroll
        for (int ks = 0; ks < 2; ++ks) {
            ldsm_x4(qa[ks],
                &qh[(dh + ((lane >> 3) & 1) * 8 + (lane & 7)) * 40 + ks * 16 + (lane >> 4) * 8]);
            #pragma unroll
            for (int p = 0; p < 2; ++p)
                ldsm_x4(kb[ks][p],
                    &kh[((p * 2 + (lane >> 4)) * 8 + (lane & 7)) * 40 + ks * 16 + ((lane >> 3) & 1) * 8]);
        }

        // scores S[16 d][32 e] via fp16 m16n8k16 (fp32 accum)
        float fs[4][4];
        #pragma unroll
        for (int nt = 0; nt < 4; ++nt)
            #pragma unroll
            for (int v = 0; v < 4; ++v) fs[nt][v] = 0.f;

        #pragma unroll
        for (int ks = 0; ks < 2; ++ks)
            #pragma unroll
            for (int nt = 0; nt < 4; ++nt)
                mma_f16(fs[nt], qa[ks][0], qa[ks][1], qa[ks][2], qa[ks][3],
                        kb[ks][nt >> 1][(nt & 1) * 2], kb[ks][nt >> 1][(nt & 1) * 2 + 1]);
        // fs[nt][v]: S[d = dh + g + (v>>1)*8][e = nt*8 + 2t + (v&1)]

        // in-warp softmax over e
        float m0 = -1e30f, m1 = -1e30f;
        #pragma unroll
        for (int nt = 0; nt < 4; ++nt) {
            m0 = fmaxf(m0, fmaxf(fs[nt][0], fs[nt][1]));
            m1 = fmaxf(m1, fmaxf(fs[nt][2], fs[nt][3]));
        }
        m0 = fmaxf(m0, __shfl_xor_sync(0xffffffffu, m0, 1));
        m0 = fmaxf(m0, __shfl_xor_sync(0xffffffffu, m0, 2));
        m1 = fmaxf(m1, __shfl_xor_sync(0xffffffffu, m1, 1));
        m1 = fmaxf(m1, __shfl_xor_sync(0xffffffffu, m1, 2));

        float s0 = 0.f, s1 = 0.f;
        #pragma unroll
        for (int nt = 0; nt < 4; ++nt) {
            fs[nt][0] = __expf(fs[nt][0] - m0); s0 += fs[nt][0];
            fs[nt][1] = __expf(fs[nt][1] - m0); s0 += fs[nt][1];
            fs[nt][2] = __expf(fs[nt][2] - m1); s1 += fs[nt][2];
            fs[nt][3] = __expf(fs[nt][3] - m1); s1 += fs[nt][3];
        }
        s0 += __shfl_xor_sync(0xffffffffu, s0, 1);
        s0 += __shfl_xor_sync(0xffffffffu, s0, 2);
        s1 += __shfl_xor_sync(0xffffffffu, s1, 1);
        s1 += __shfl_xor_sync(0xffffffffu, s1, 2);
        float r0 = __fdividef(1.f, s0);
        float r1 = __fdividef(1.f, s1);

        // AV: out[16 d][32 c] = P @ V, fp16 m16n8k16, P converted in-register
        float od[4][4];
        #pragma unroll
        for (int nt = 0; nt < 4; ++nt)
            #pragma unroll
            for (int v = 0; v < 4; ++v) od[nt][v] = 0.f;

        const uint32_t* svw = &sv32[aw * 1168];
        #pragma unroll
        for (int ks = 0; ks < 2; ++ks) {
            uint32_t a0 = h2pack(fs[2 * ks][0] * r0, fs[2 * ks][1] * r0);
            uint32_t a1 = h2pack(fs[2 * ks][2] * r1, fs[2 * ks][3] * r1);
            uint32_t a2 = h2pack(fs[2 * ks + 1][0] * r0, fs[2 * ks + 1][1] * r0);
            uint32_t a3 = h2pack(fs[2 * ks + 1][2] * r1, fs[2 * ks + 1][3] * r1);
            #pragma unroll
            for (int ntd = 0; ntd < 4; ++ntd) {
                int col = ch + ntd * 8 + g;
                uint32_t b0 = svw[(8 * ks + t) * 72 + col];
                uint32_t b1 = svw[(8 * ks + t + 4) * 72 + col];
                mma_f16(od[ntd], a0, a1, a2, a3, b0, b1);
            }
        }
        // od[ntd][v]: out[d = dh + g + (v>>1)*8][c = ch + ntd*8 + 2t + (v&1)]

        // sout stride 132: banks 4c + d -> 32-lane permutation, conflict-free
        #pragma unroll
        for (int ntd = 0; ntd < 4; ++ntd) {
            #pragma unroll
            for (int v = 0; v < 4; ++v) {
                int c = ch + ntd * 8 + 2 * t + (v & 1);
                int d = dh + g + (v >> 1) * 8;
                sout[c * 132 + aw * 32 + d] = od[ntd][v];
            }
        }

        // hoisted epilogue x loads: overlap L2 latency with barrier 3
        #pragma unroll
        for (int it = 0; it < 4; ++it) {
            int i = tid + it * NTHREADS;
            int c = i >> 5, d = i & 31;
            xv[it] = *reinterpret_cast<const float4*>(x + base + ((size_t)c * D_DIM + d) * HW);
        }
    }
    __syncthreads();                                     // barrier 3 (sout ready)

    // ---- Epilogue: out = g*attn_out + (1-g)*x, coalesced ----
    const float gm = gamma[0];
    const float g_ = 1.f / (1.f + __expf(-gm));
    const float g1 = 1.f - g_;
    #pragma unroll
    for (int it = 0; it < 4; ++it) {
        int i = tid + it * NTHREADS;
        int c = i >> 5, d = i & 31;
        size_t gaddr = base + ((size_t)c * D_DIM + d) * HW;
        float4 r;
        r.x = g_ * sout[c * 132 +  0 + d] + g1 * xv[it].x;
        r.y = g_ * sout[c * 132 + 32 + d] + g1 * xv[it].y;
        r.z = g_ * sout[c * 132 + 64 + d] + g1 * xv[it].z;
        r.w = g_ * sout[c * 132 + 96 + d] + g1 * xv[it].w;
        *reinterpret_cast<float4*>(out + gaddr) = r;
    }
}

// ---------------------------------------------------------------------------
extern "C" void kernel_launch(void* const* d_in, const int* in_sizes, int n_in,
                              void* d_out, int out_size) {
    const float* x        = (const float*)d_in[0];
    const float* text_emb = (const float*)d_in[1];
    const float* wq       = (const float*)d_in[2];
    const float* bq       = (const float*)d_in[3];
    const float* wk       = (const float*)d_in[4];
    const float* bk       = (const float*)d_in[5];
    const float* wv       = (const float*)d_in[6];
    const float* bv       = (const float*)d_in[7];
    const float* wt       = (const float*)d_in[8];
    const float* bt       = (const float*)d_in[9];
    const float* pos      = (const float*)d_in[10];
    const float* gamma    = (const float*)d_in[11];
    float* out = (float*)d_out;

    cudaFuncSetAttribute(attn_kernel, cudaFuncAttributeMaxDynamicSharedMemorySize, SMEM_BYTES);

    setup_kernel<<<1, 256>>>(text_emb, wt, bt, wq, wk, wv);

    const int grid = B_DIM * H_DIM * (W_DIM / WT);  // 4608
    attn_kernel<<<grid, NTHREADS, SMEM_BYTES>>>(x, bq, bk, bv, pos, gamma, out);
}

// round 12
// speedup vs baseline: 1.5630x; 1.0594x over previous
#include <cuda_runtime.h>
#include <cuda_fp16.h>
#include <math.h>
#include <stdint.h>

// Problem constants
#define C_DIM 64
#define D_DIM 32
#define H_DIM 96
#define W_DIM 96
#define B_DIM 2
#define WT 32         // w-tile per CTA (one full 128B line)
#define OW 8          // w per sub-round (octant)
#define NTHREADS 1024

// smem layout (float words)
#define SXW_OFF   0       // x fp16 c-pair words, 4 octs of [32 cp (*264)][256 n]; stride 8456/oct
#define OCT_S     8456    // ≡ 8 mod 32 (bank rotation per oct)
#define SQH_OFF   33824   // Q fp16 [8 w (*1288h)][32 d (*40h)][q] : 5152 words
#define SKH_OFF   38976   // K : 5152 words
#define SV_OFF    44128   // V fp16 pairs: uint32 [8 w (*1168)][16 epair (*72)][64 c] : 9344 words
#define SBIAS_OFF 53472   // 128
#define SPOS_OFF  53600   // 1024
#define SMEM_FLOATS 54624
#define SMEM_BYTES (SMEM_FLOATS * 4)   // 218496 B -> 1 CTA/SM

__device__ float g_tb[32];
__device__ uint32_t g_wpackh[4096];   // prepacked fp16 W in m16n8k16 A-fragment order

__device__ __forceinline__ void mma_f16(float* d, uint32_t a0, uint32_t a1, uint32_t a2,
                                        uint32_t a3, uint32_t b0, uint32_t b1) {
    asm volatile(
        "mma.sync.aligned.m16n8k16.row.col.f32.f16.f16.f32 "
        "{%0,%1,%2,%3}, {%4,%5,%6,%7}, {%8,%9}, {%0,%1,%2,%3};"
        : "+f"(d[0]), "+f"(d[1]), "+f"(d[2]), "+f"(d[3])
        : "r"(a0), "r"(a1), "r"(a2), "r"(a3), "r"(b0), "r"(b1));
}

__device__ __forceinline__ uint32_t h2pack(float lo, float hi) {
    __half2 h = __floats2half2_rn(lo, hi);
    return *reinterpret_cast<uint32_t*>(&h);
}

__device__ __forceinline__ void ldsm_x4(uint32_t* r, const void* p) {
    uint32_t a = (uint32_t)__cvta_generic_to_shared(p);
    asm volatile("ldmatrix.sync.aligned.m8n8.x4.shared.b16 {%0,%1,%2,%3}, [%4];"
                 : "=r"(r[0]), "=r"(r[1]), "=r"(r[2]), "=r"(r[3]) : "r"(a));
}

// ---------------------------------------------------------------------------
// Setup kernel: text bias + weight prepack (fp16 A-fragment order for k16)
// ---------------------------------------------------------------------------
__global__ void setup_kernel(const float* __restrict__ text_emb,
                             const float* __restrict__ wt,
                             const float* __restrict__ bt,
                             const float* __restrict__ wq,
                             const float* __restrict__ wk,
                             const float* __restrict__ wv) {
    __shared__ float mcol[256];
    int t = threadIdx.x;
    float s = 0.f;
    #pragma unroll
    for (int r = 0; r < 32; ++r) s += text_emb[r * 256 + t];
    mcol[t] = s * (1.0f / 32.0f);
    __syncthreads();
    int warp = t >> 5, lane = t & 31;
    for (int q = warp; q < 32; q += 8) {
        float acc = 0.f;
        #pragma unroll
        for (int k = 0; k < 8; ++k) acc += wt[q * 256 + lane + k * 32] * mcol[lane + k * 32];
        #pragma unroll
        for (int o = 16; o > 0; o >>= 1) acc += __shfl_xor_sync(0xffffffffu, acc, o);
        if (lane == 0) g_tb[q] = acc + bt[q];
    }
    // g_wpackh[((mt*4+ks)*32 + lane)*4 + j] = pair {W[o][k], W[o][k+1]}
    #pragma unroll
    for (int it = 0; it < 16; ++it) {
        int idx  = t + it * 256;    // 4096 words
        int j    = idx & 3;
        int ln   = (idx >> 2) & 31;
        int ks   = (idx >> 7) & 3;
        int mt   = idx >> 9;
        int g = ln >> 2, tt = ln & 3;
        int o = mt * 16 + g + (j & 1) * 8;
        int k = ks * 16 + 2 * tt + (j >> 1) * 8;
        float v0, v1;
        if (o < 32)       { v0 = wq[o * 64 + k];        v1 = wq[o * 64 + k + 1]; }
        else if (o < 64)  { v0 = wk[(o - 32) * 64 + k]; v1 = wk[(o - 32) * 64 + k + 1]; }
        else              { v0 = wv[(o - 64) * 64 + k]; v1 = wv[(o - 64) * 64 + k + 1]; }
        __half2 h = __floats2half2_rn(v0, v1);
        g_wpackh[idx] = *reinterpret_cast<uint32_t*>(&h);
    }
}

// ---------------------------------------------------------------------------
// Main fused kernel: one block per (b, h, 32-w line); 1024 threads, 1 CTA/SM
// ---------------------------------------------------------------------------
__global__ __launch_bounds__(NTHREADS, 1)
void attn_kernel(const float* __restrict__ x,
                 const float* __restrict__ bq, const float* __restrict__ bk,
                 const float* __restrict__ bv,
                 const float* __restrict__ pos, const float* __restrict__ gamma,
                 float* __restrict__ out) {
    extern __shared__ float sm[];
    uint32_t* sxw  = reinterpret_cast<uint32_t*>(sm + SXW_OFF);   // x fp16 words / sout overlay
    __half* sqh    = reinterpret_cast<__half*>(sm + SQH_OFF);
    __half* skh    = reinterpret_cast<__half*>(sm + SKH_OFF);
    __half* sv_h   = reinterpret_cast<__half*>(sm + SV_OFF);
    uint32_t* sv32 = reinterpret_cast<uint32_t*>(sm + SV_OFF);
    float* sbias   = sm + SBIAS_OFF;
    float* spos    = sm + SPOS_OFF;

    const int tid = threadIdx.x;
    const int bid = blockIdx.x;
    const int b   = bid / (H_DIM * 3);
    const int rem = bid % (H_DIM * 3);
    const int h   = rem / 3;
    const int w0  = (rem % 3) * WT;

    const int HW = H_DIM * W_DIM; // 9216
    const size_t base = (size_t)b * C_DIM * D_DIM * HW + (size_t)h * W_DIM + w0;

    const int warp = tid >> 5, lane = tid & 31;
    const int g = lane >> 2, t = lane & 3;

    // ---- Phase A: coalesced x load + fp16 c-pair pack ----
    // unit i: cp = i>>8, d = (i>>3)&31, w4 = i&7 (w4*4 = w within 32-w line)
    // dest: oct = w4>>1, n = d*8 + (w4&1)*4
    #pragma unroll
    for (int it = 0; it < 8; ++it) {
        int i  = tid + it * NTHREADS;
        int cp = i >> 8, d = (i >> 3) & 31, w4 = i & 7;
        const float* p0 = x + base + ((size_t)(2 * cp) * D_DIM + d) * HW + w4 * 4;
        const float* p1 = p0 + (size_t)D_DIM * HW;
        float4 v0 = *reinterpret_cast<const float4*>(p0);
        float4 v1 = *reinterpret_cast<const float4*>(p1);
        uint4 wv_;
        wv_.x = h2pack(v0.x, v1.x);
        wv_.y = h2pack(v0.y, v1.y);
        wv_.z = h2pack(v0.z, v1.z);
        wv_.w = h2pack(v0.w, v1.w);
        *reinterpret_cast<uint4*>(&sxw[(w4 >> 1) * OCT_S + cp * 264 + d * 8 + (w4 & 1) * 4]) = wv_;
    }
    if (tid < 128) {
        float bb;
        if (tid < 32)      bb = bq[tid] + g_tb[tid];
        else if (tid < 64) bb = bk[tid - 32] + g_tb[tid - 32];
        else               bb = bv[tid - 64];
        sbias[tid] = bb;
    }
    if (tid < 1024) spos[tid] = pos[tid];
    __syncthreads();

    // roles
    const int mw = warp & 3;        // phase B: 0:Q 1:K 2:V(c0-31) 3:V(c32-63)
    const int ns = warp >> 2;       // phase B: n slice of 32 (8 slices over 256 n)
    const int aw = warp & 7;        // phase C/D: w within oct
    const int dh = ((warp >> 3) & 1) * 16;
    const int ch = (warp >> 4) * 32;

    for (int oct = 0; oct < 4; ++oct) {
        uint32_t* sxo = sxw + oct * OCT_S;

        // ---- Phase B: fp16 MMA GEMM  C[128 o][256 n] = W[128,64] * X[64,256] ----
        {
            float acc[2][4][4];
            #pragma unroll
            for (int s_ = 0; s_ < 2; ++s_)
                #pragma unroll
                for (int nt = 0; nt < 4; ++nt)
                    #pragma unroll
                    for (int v = 0; v < 4; ++v) acc[s_][nt][v] = 0.f;

            const uint4* wp4 = reinterpret_cast<const uint4*>(g_wpackh);
            #pragma unroll
            for (int ks = 0; ks < 4; ++ks) {
                uint4 a0 = __ldg(&wp4[((mw * 2 + 0) * 4 + ks) * 32 + lane]);
                uint4 a1 = __ldg(&wp4[((mw * 2 + 1) * 4 + ks) * 32 + lane]);
                const uint32_t* xr0 = &sxo[(ks * 8 + t) * 264 + ns * 32 + g];
                const uint32_t* xr1 = &sxo[(ks * 8 + t + 4) * 264 + ns * 32 + g];
                #pragma unroll
                for (int nt = 0; nt < 4; ++nt) {
                    uint32_t b0 = xr0[nt * 8];
                    uint32_t b1 = xr1[nt * 8];
                    mma_f16(acc[0][nt], a0.x, a0.y, a0.z, a0.w, b0, b1);
                    mma_f16(acc[1][nt], a1.x, a1.y, a1.z, a1.w, b0, b1);
                }
            }

            if (mw < 2) {
                // Q -> sqh[w*1288 + d*40 + q] (scaled); K -> skh[w*1288 + e*40 + q]
                __half* dsth = (mw == 0) ? sqh : skh;
                const int boff = mw * 32;
                const float qscale = (mw == 0) ? 0.17677669529663687f : 1.0f;
                #pragma unroll
                for (int s_ = 0; s_ < 2; ++s_) {
                    #pragma unroll
                    for (int nt = 0; nt < 4; ++nt) {
                        #pragma unroll
                        for (int v = 0; v < 4; ++v) {
                            int q = s_ * 16 + g + (v >> 1) * 8;
                            int n = ns * 32 + nt * 8 + 2 * t + (v & 1);
                            int outer = n >> 3, w = n & 7;   // d for Q, e for K
                            float val = acc[s_][nt][v] + sbias[boff + q] + spos[q * 32 + outer];
                            dsth[w * 1288 + outer * 40 + q] = __float2half_rn(val * qscale);
                        }
                    }
                }
            } else {
                // V -> sv32[w*1168 + (e>>1)*72 + c], e-parity = half
                const int cbb = (mw - 2) * 32;
                #pragma unroll
                for (int s_ = 0; s_ < 2; ++s_) {
                    #pragma unroll
                    for (int nt = 0; nt < 4; ++nt) {
                        #pragma unroll
                        for (int v = 0; v < 4; ++v) {
                            int c = cbb + s_ * 16 + g + (v >> 1) * 8;
                            int n = ns * 32 + nt * 8 + 2 * t + (v & 1);
                            int e = n >> 3, w = n & 7;
                            sv_h[(w * 1168 + (e >> 1) * 72 + c) * 2 + (e & 1)] =
                                __float2half_rn(acc[s_][nt][v] + sbias[64 + c]);
                        }
                    }
                }
            }
        }
        __syncthreads();   // QKV(oct) ready; x-oct reads done -> sout may overwrite

        // ---- Phases C+D fused per warp: (w, d-half, c-half) ----
        {
            const __half* qh = &sqh[aw * 1288];   // [d*40 + q]
            const __half* kh = &skh[aw * 1288];   // [e*40 + q]

            uint32_t qa[2][4];
            uint32_t kb[2][2][4];
            #pragma unroll
            for (int ks = 0; ks < 2; ++ks) {
                ldsm_x4(qa[ks],
                    &qh[(dh + ((lane >> 3) & 1) * 8 + (lane & 7)) * 40 + ks * 16 + (lane >> 4) * 8]);
                #pragma unroll
                for (int p = 0; p < 2; ++p)
                    ldsm_x4(kb[ks][p],
                        &kh[((p * 2 + (lane >> 4)) * 8 + (lane & 7)) * 40 + ks * 16 + ((lane >> 3) & 1) * 8]);
            }

            float fs[4][4];
            #pragma unroll
            for (int nt = 0; nt < 4; ++nt)
                #pragma unroll
                for (int v = 0; v < 4; ++v) fs[nt][v] = 0.f;

            #pragma unroll
            for (int ks = 0; ks < 2; ++ks)
                #pragma unroll
                for (int nt = 0; nt < 4; ++nt)
                    mma_f16(fs[nt], qa[ks][0], qa[ks][1], qa[ks][2], qa[ks][3],
                            kb[ks][nt >> 1][(nt & 1) * 2], kb[ks][nt >> 1][(nt & 1) * 2 + 1]);
            // fs[nt][v]: S[d = dh + g + (v>>1)*8][e = nt*8 + 2t + (v&1)]

            float m0 = -1e30f, m1 = -1e30f;
            #pragma unroll
            for (int nt = 0; nt < 4; ++nt) {
                m0 = fmaxf(m0, fmaxf(fs[nt][0], fs[nt][1]));
                m1 = fmaxf(m1, fmaxf(fs[nt][2], fs[nt][3]));
            }
            m0 = fmaxf(m0, __shfl_xor_sync(0xffffffffu, m0, 1));
            m0 = fmaxf(m0, __shfl_xor_sync(0xffffffffu, m0, 2));
            m1 = fmaxf(m1, __shfl_xor_sync(0xffffffffu, m1, 1));
            m1 = fmaxf(m1, __shfl_xor_sync(0xffffffffu, m1, 2));

            float s0 = 0.f, s1 = 0.f;
            #pragma unroll
            for (int nt = 0; nt < 4; ++nt) {
                fs[nt][0] = __expf(fs[nt][0] - m0); s0 += fs[nt][0];
                fs[nt][1] = __expf(fs[nt][1] - m0); s0 += fs[nt][1];
                fs[nt][2] = __expf(fs[nt][2] - m1); s1 += fs[nt][2];
                fs[nt][3] = __expf(fs[nt][3] - m1); s1 += fs[nt][3];
            }
            s0 += __shfl_xor_sync(0xffffffffu, s0, 1);
            s0 += __shfl_xor_sync(0xffffffffu, s0, 2);
            s1 += __shfl_xor_sync(0xffffffffu, s1, 1);
            s1 += __shfl_xor_sync(0xffffffffu, s1, 2);
            float r0 = __fdividef(1.f, s0);
            float r1 = __fdividef(1.f, s1);

            float od[4][4];
            #pragma unroll
            for (int nt = 0; nt < 4; ++nt)
                #pragma unroll
                for (int v = 0; v < 4; ++v) od[nt][v] = 0.f;

            const uint32_t* svw = &sv32[aw * 1168];
            #pragma unroll
            for (int ks = 0; ks < 2; ++ks) {
                uint32_t a0 = h2pack(fs[2 * ks][0] * r0, fs[2 * ks][1] * r0);
                uint32_t a1 = h2pack(fs[2 * ks][2] * r1, fs[2 * ks][3] * r1);
                uint32_t a2 = h2pack(fs[2 * ks + 1][0] * r0, fs[2 * ks + 1][1] * r0);
                uint32_t a3 = h2pack(fs[2 * ks + 1][2] * r1, fs[2 * ks + 1][3] * r1);
                #pragma unroll
                for (int ntd = 0; ntd < 4; ++ntd) {
                    int col = ch + ntd * 8 + g;
                    uint32_t b0 = svw[(8 * ks + t) * 72 + col];
                    uint32_t b1 = svw[(8 * ks + t + 4) * 72 + col];
                    mma_f16(od[ntd], a0, a1, a2, a3, b0, b1);
                }
            }
            // od[ntd][v]: out[d = dh + g + (v>>1)*8][c = ch + ntd*8 + 2t + (v&1)]

            // sout (fp16 c-pairs) overlays x-oct: word = cp*264 + w*33 + d
            #pragma unroll
            for (int ntd = 0; ntd < 4; ++ntd) {
                int cp = (ch >> 1) + ntd * 4 + t;
                sxo[cp * 264 + aw * 33 + dh + g]     = h2pack(od[ntd][0], od[ntd][1]);
                sxo[cp * 264 + aw * 33 + dh + g + 8] = h2pack(od[ntd][2], od[ntd][3]);
            }
        }
        __syncthreads();   // sout(oct) complete; QKV buffers free for next oct
    }

    // ---- Epilogue: out = g*attn_out + (1-g)*x, fully coalesced ----
    const float gm = gamma[0];
    const float g_ = 1.f / (1.f + __expf(-gm));
    const float g1 = 1.f - g_;
    #pragma unroll
    for (int it = 0; it < 8; ++it) {
        int i  = tid + it * NTHREADS;
        int cp = i >> 8, d = (i >> 3) & 31, w4 = i & 7;
        const uint32_t* so = sxw + (w4 >> 1) * OCT_S;
        int wl = (w4 & 1) * 4;
        float o0[4], o1[4];
        #pragma unroll
        for (int j = 0; j < 4; ++j) {
            uint32_t pw = so[cp * 264 + (wl + j) * 33 + d];
            float2 f = __half22float2(*reinterpret_cast<__half2*>(&pw));
            o0[j] = f.x;   // c = 2cp
            o1[j] = f.y;   // c = 2cp+1
        }
        size_t ga0 = base + ((size_t)(2 * cp) * D_DIM + d) * HW + w4 * 4;
        size_t ga1 = ga0 + (size_t)D_DIM * HW;
        float4 xv0 = *reinterpret_cast<const float4*>(x + ga0);
        float4 xv1 = *reinterpret_cast<const float4*>(x + ga1);
        float4 r0, r1;
        r0.x = g_ * o0[0] + g1 * xv0.x;  r0.y = g_ * o0[1] + g1 * xv0.y;
        r0.z = g_ * o0[2] + g1 * xv0.z;  r0.w = g_ * o0[3] + g1 * xv0.w;
        r1.x = g_ * o1[0] + g1 * xv1.x;  r1.y = g_ * o1[1] + g1 * xv1.y;
        r1.z = g_ * o1[2] + g1 * xv1.z;  r1.w = g_ * o1[3] + g1 * xv1.w;
        *reinterpret_cast<float4*>(out + ga0) = r0;
        *reinterpret_cast<float4*>(out + ga1) = r1;
    }
}

// ---------------------------------------------------------------------------
extern "C" void kernel_launch(void* const* d_in, const int* in_sizes, int n_in,
                              void* d_out, int out_size) {
    const float* x        = (const float*)d_in[0];
    const float* text_emb = (const float*)d_in[1];
    const float* wq       = (const float*)d_in[2];
    const float* bq       = (const float*)d_in[3];
    const float* wk       = (const float*)d_in[4];
    const float* bk       = (const float*)d_in[5];
    const float* wv       = (const float*)d_in[6];
    const float* bv       = (const float*)d_in[7];
    const float* wt       = (const float*)d_in[8];
    const float* bt       = (const float*)d_in[9];
    const float* pos      = (const float*)d_in[10];
    const float* gamma    = (const float*)d_in[11];
    float* out = (float*)d_out;

    cudaFuncSetAttribute(attn_kernel, cudaFuncAttributeMaxDynamicSharedMemorySize, SMEM_BYTES);

    setup_kernel<<<1, 256>>>(text_emb, wt, bt, wq, wk, wv);

    const int grid = B_DIM * H_DIM * (W_DIM / WT);  // 576
    attn_kernel<<<grid, NTHREADS, SMEM_BYTES>>>(x, bq, bk, bv, pos, gamma, out);
}

// round 13
// speedup vs baseline: 1.9010x; 1.2162x over previous
#include <cuda_runtime.h>
#include <cuda_fp16.h>
#include <math.h>
#include <stdint.h>

// Problem constants
#define C_DIM 64
#define D_DIM 32
#define H_DIM 96
#define W_DIM 96
#define B_DIM 2
#define WT 32         // w-tile per CTA (one full 128B line)
#define NTHREADS 1024

// smem layout (float words)
#define SXW_OFF   0       // x fp16 c-pair words, 4 octs of [32 cp (*264)][256 n]; stride 8456/oct
#define OCT_S     8456    // ≡ 8 mod 32 (bank rotation per oct)
#define SQH_OFF   33824   // Q fp16 [8 w (*1288h)][32 d (*40h)][q] : 5152 words
#define SKH_OFF   38976   // K : 5152 words
#define SV_OFF    44128   // V fp16 pairs: uint32 [8 w (*1168)][16 epair (*72)][64 c] : 9344 words
#define SBIAS_OFF 53472   // 128
#define SPOS_OFF  53600   // 1024
#define SMEM_FLOATS 54624
#define SMEM_BYTES (SMEM_FLOATS * 4)   // 218496 B -> 1 CTA/SM

__device__ float g_tb[32];
__device__ uint32_t g_wpackh[4096];   // prepacked fp16 W in m16n8k16 A-fragment order

__device__ __forceinline__ void mma_f16(float* d, uint32_t a0, uint32_t a1, uint32_t a2,
                                        uint32_t a3, uint32_t b0, uint32_t b1) {
    asm volatile(
        "mma.sync.aligned.m16n8k16.row.col.f32.f16.f16.f32 "
        "{%0,%1,%2,%3}, {%4,%5,%6,%7}, {%8,%9}, {%0,%1,%2,%3};"
        : "+f"(d[0]), "+f"(d[1]), "+f"(d[2]), "+f"(d[3])
        : "r"(a0), "r"(a1), "r"(a2), "r"(a3), "r"(b0), "r"(b1));
}

__device__ __forceinline__ uint32_t h2pack(float lo, float hi) {
    __half2 h = __floats2half2_rn(lo, hi);
    return *reinterpret_cast<uint32_t*>(&h);
}

__device__ __forceinline__ void ldsm_x4(uint32_t* r, const void* p) {
    uint32_t a = (uint32_t)__cvta_generic_to_shared(p);
    asm volatile("ldmatrix.sync.aligned.m8n8.x4.shared.b16 {%0,%1,%2,%3}, [%4];"
                 : "=r"(r[0]), "=r"(r[1]), "=r"(r[2]), "=r"(r[3]) : "r"(a));
}

// ---------------------------------------------------------------------------
// Setup kernel: text bias + weight prepack (fp16 A-fragment order for k16)
// ---------------------------------------------------------------------------
__global__ void setup_kernel(const float* __restrict__ text_emb,
                             const float* __restrict__ wt,
                             const float* __restrict__ bt,
                             const float* __restrict__ wq,
                             const float* __restrict__ wk,
                             const float* __restrict__ wv) {
    __shared__ float mcol[256];
    int t = threadIdx.x;
    float s = 0.f;
    #pragma unroll
    for (int r = 0; r < 32; ++r) s += text_emb[r * 256 + t];
    mcol[t] = s * (1.0f / 32.0f);
    __syncthreads();
    int warp = t >> 5, lane = t & 31;
    for (int q = warp; q < 32; q += 8) {
        float acc = 0.f;
        #pragma unroll
        for (int k = 0; k < 8; ++k) acc += wt[q * 256 + lane + k * 32] * mcol[lane + k * 32];
        #pragma unroll
        for (int o = 16; o > 0; o >>= 1) acc += __shfl_xor_sync(0xffffffffu, acc, o);
        if (lane == 0) g_tb[q] = acc + bt[q];
    }
    // g_wpackh[((mt*4+ks)*32 + lane)*4 + j] = pair {W[o][k], W[o][k+1]}
    #pragma unroll
    for (int it = 0; it < 16; ++it) {
        int idx  = t + it * 256;    // 4096 words
        int j    = idx & 3;
        int ln   = (idx >> 2) & 31;
        int ks   = (idx >> 7) & 3;
        int mt   = idx >> 9;
        int g = ln >> 2, tt = ln & 3;
        int o = mt * 16 + g + (j & 1) * 8;
        int k = ks * 16 + 2 * tt + (j >> 1) * 8;
        float v0, v1;
        if (o < 32)       { v0 = wq[o * 64 + k];        v1 = wq[o * 64 + k + 1]; }
        else if (o < 64)  { v0 = wk[(o - 32) * 64 + k]; v1 = wk[(o - 32) * 64 + k + 1]; }
        else              { v0 = wv[(o - 64) * 64 + k]; v1 = wv[(o - 64) * 64 + k + 1]; }
        __half2 h = __floats2half2_rn(v0, v1);
        g_wpackh[idx] = *reinterpret_cast<uint32_t*>(&h);
    }
}

// ---------------------------------------------------------------------------
// Main fused kernel: one block per (b, h, 32-w line); 1024 threads, 1 CTA/SM
// ---------------------------------------------------------------------------
__global__ __launch_bounds__(NTHREADS, 1)
void attn_kernel(const float* __restrict__ x,
                 const float* __restrict__ bq, const float* __restrict__ bk,
                 const float* __restrict__ bv,
                 const float* __restrict__ pos, const float* __restrict__ gamma,
                 float* __restrict__ out) {
    extern __shared__ float sm[];
    uint32_t* sxw  = reinterpret_cast<uint32_t*>(sm + SXW_OFF);   // x fp16 words / sout overlay
    __half* sqh    = reinterpret_cast<__half*>(sm + SQH_OFF);
    __half* skh    = reinterpret_cast<__half*>(sm + SKH_OFF);
    __half* sv_h   = reinterpret_cast<__half*>(sm + SV_OFF);
    uint32_t* sv32 = reinterpret_cast<uint32_t*>(sm + SV_OFF);
    float* sbias   = sm + SBIAS_OFF;
    float* spos    = sm + SPOS_OFF;

    const int tid = threadIdx.x;
    const int bid = blockIdx.x;
    const int b   = bid / (H_DIM * 3);
    const int rem = bid % (H_DIM * 3);
    const int h   = rem / 3;
    const int w0  = (rem % 3) * WT;

    const int HW = H_DIM * W_DIM; // 9216
    const size_t base = (size_t)b * C_DIM * D_DIM * HW + (size_t)h * W_DIM + w0;

    const int warp = tid >> 5, lane = tid & 31;
    const int g = lane >> 2, t = lane & 3;

    // gate (uniform; load early to overlap)
    const float gm = gamma[0];
    const float gg = 1.f / (1.f + __expf(-gm));
    const float g1 = 1.f - gg;

    // ---- Phase A: coalesced x load + fp16 c-pair pack ----
    #pragma unroll
    for (int it = 0; it < 8; ++it) {
        int i  = tid + it * NTHREADS;
        int cp = i >> 8, d = (i >> 3) & 31, w4 = i & 7;
        const float* p0 = x + base + ((size_t)(2 * cp) * D_DIM + d) * HW + w4 * 4;
        const float* p1 = p0 + (size_t)D_DIM * HW;
        float4 v0 = *reinterpret_cast<const float4*>(p0);
        float4 v1 = *reinterpret_cast<const float4*>(p1);
        uint4 wv_;
        wv_.x = h2pack(v0.x, v1.x);
        wv_.y = h2pack(v0.y, v1.y);
        wv_.z = h2pack(v0.z, v1.z);
        wv_.w = h2pack(v0.w, v1.w);
        *reinterpret_cast<uint4*>(&sxw[(w4 >> 1) * OCT_S + cp * 264 + d * 8 + (w4 & 1) * 4]) = wv_;
    }
    if (tid < 128) {
        float bb;
        if (tid < 32)      bb = bq[tid] + g_tb[tid];
        else if (tid < 64) bb = bk[tid - 32] + g_tb[tid - 32];
        else               bb = bv[tid - 64];
        sbias[tid] = bb;
    }
    spos[tid] = pos[tid];
    __syncthreads();

    // roles
    const int mw = warp & 3;        // phase B: 0:Q 1:K 2:V(c0-31) 3:V(c32-63)
    const int ns = warp >> 2;       // phase B: n slice of 32 (8 slices over 256 n)
    const int aw = warp & 7;        // phase C/D: w within oct
    const int dh = ((warp >> 3) & 1) * 16;
    const int ch = (warp >> 4) * 32;

    for (int oct = 0; oct < 4; ++oct) {
        uint32_t* sxo = sxw + oct * OCT_S;

        // ---- Phase B: fp16 MMA GEMM  C[128 o][256 n] = W[128,64] * X[64,256] ----
        {
            float acc[2][4][4];
            #pragma unroll
            for (int s_ = 0; s_ < 2; ++s_)
                #pragma unroll
                for (int nt = 0; nt < 4; ++nt)
                    #pragma unroll
                    for (int v = 0; v < 4; ++v) acc[s_][nt][v] = 0.f;

            const uint4* wp4 = reinterpret_cast<const uint4*>(g_wpackh);
            #pragma unroll
            for (int ks = 0; ks < 4; ++ks) {
                uint4 a0 = __ldg(&wp4[((mw * 2 + 0) * 4 + ks) * 32 + lane]);
                uint4 a1 = __ldg(&wp4[((mw * 2 + 1) * 4 + ks) * 32 + lane]);
                const uint32_t* xr0 = &sxo[(ks * 8 + t) * 264 + ns * 32 + g];
                const uint32_t* xr1 = &sxo[(ks * 8 + t + 4) * 264 + ns * 32 + g];
                #pragma unroll
                for (int nt = 0; nt < 4; ++nt) {
                    uint32_t b0 = xr0[nt * 8];
                    uint32_t b1 = xr1[nt * 8];
                    mma_f16(acc[0][nt], a0.x, a0.y, a0.z, a0.w, b0, b1);
                    mma_f16(acc[1][nt], a1.x, a1.y, a1.z, a1.w, b0, b1);
                }
            }

            if (mw < 2) {
                __half* dsth = (mw == 0) ? sqh : skh;
                const int boff = mw * 32;
                const float qscale = (mw == 0) ? 0.17677669529663687f : 1.0f;
                #pragma unroll
                for (int s_ = 0; s_ < 2; ++s_) {
                    #pragma unroll
                    for (int nt = 0; nt < 4; ++nt) {
                        #pragma unroll
                        for (int v = 0; v < 4; ++v) {
                            int q = s_ * 16 + g + (v >> 1) * 8;
                            int n = ns * 32 + nt * 8 + 2 * t + (v & 1);
                            int outer = n >> 3, w = n & 7;   // d for Q, e for K
                            float val = acc[s_][nt][v] + sbias[boff + q] + spos[q * 32 + outer];
                            dsth[w * 1288 + outer * 40 + q] = __float2half_rn(val * qscale);
                        }
                    }
                }
            } else {
                const int cbb = (mw - 2) * 32;
                #pragma unroll
                for (int s_ = 0; s_ < 2; ++s_) {
                    #pragma unroll
                    for (int nt = 0; nt < 4; ++nt) {
                        #pragma unroll
                        for (int v = 0; v < 4; ++v) {
                            int c = cbb + s_ * 16 + g + (v >> 1) * 8;
                            int n = ns * 32 + nt * 8 + 2 * t + (v & 1);
                            int e = n >> 3, w = n & 7;
                            sv_h[(w * 1168 + (e >> 1) * 72 + c) * 2 + (e & 1)] =
                                __float2half_rn(acc[s_][nt][v] + sbias[64 + c]);
                        }
                    }
                }
            }
        }
        __syncthreads();   // barrier 1: QKV(oct) ready; x-oct GEMM reads done

        // ---- Phases C+D fused per warp: (w, d-half, c-half) + in-register blend ----
        uint32_t pk2[4][2];   // final blended fp16 pairs
        {
            const __half* qh = &sqh[aw * 1288];   // [d*40 + q]
            const __half* kh = &skh[aw * 1288];   // [e*40 + q]

            uint32_t qa[2][4];
            uint32_t kb[2][2][4];
            #pragma unroll
            for (int ks = 0; ks < 2; ++ks) {
                ldsm_x4(qa[ks],
                    &qh[(dh + ((lane >> 3) & 1) * 8 + (lane & 7)) * 40 + ks * 16 + (lane >> 4) * 8]);
                #pragma unroll
                for (int p = 0; p < 2; ++p)
                    ldsm_x4(kb[ks][p],
                        &kh[((p * 2 + (lane >> 4)) * 8 + (lane & 7)) * 40 + ks * 16 + ((lane >> 3) & 1) * 8]);
            }

            float fs[4][4];
            #pragma unroll
            for (int nt = 0; nt < 4; ++nt)
                #pragma unroll
                for (int v = 0; v < 4; ++v) fs[nt][v] = 0.f;

            #pragma unroll
            for (int ks = 0; ks < 2; ++ks)
                #pragma unroll
                for (int nt = 0; nt < 4; ++nt)
                    mma_f16(fs[nt], qa[ks][0], qa[ks][1], qa[ks][2], qa[ks][3],
                            kb[ks][nt >> 1][(nt & 1) * 2], kb[ks][nt >> 1][(nt & 1) * 2 + 1]);
            // fs[nt][v]: S[d = dh + g + (v>>1)*8][e = nt*8 + 2t + (v&1)]

            float m0 = -1e30f, m1 = -1e30f;
            #pragma unroll
            for (int nt = 0; nt < 4; ++nt) {
                m0 = fmaxf(m0, fmaxf(fs[nt][0], fs[nt][1]));
                m1 = fmaxf(m1, fmaxf(fs[nt][2], fs[nt][3]));
            }
            m0 = fmaxf(m0, __shfl_xor_sync(0xffffffffu, m0, 1));
            m0 = fmaxf(m0, __shfl_xor_sync(0xffffffffu, m0, 2));
            m1 = fmaxf(m1, __shfl_xor_sync(0xffffffffu, m1, 1));
            m1 = fmaxf(m1, __shfl_xor_sync(0xffffffffu, m1, 2));

            float s0 = 0.f, s1 = 0.f;
            #pragma unroll
            for (int nt = 0; nt < 4; ++nt) {
                fs[nt][0] = __expf(fs[nt][0] - m0); s0 += fs[nt][0];
                fs[nt][1] = __expf(fs[nt][1] - m0); s0 += fs[nt][1];
                fs[nt][2] = __expf(fs[nt][2] - m1); s1 += fs[nt][2];
                fs[nt][3] = __expf(fs[nt][3] - m1); s1 += fs[nt][3];
            }
            s0 += __shfl_xor_sync(0xffffffffu, s0, 1);
            s0 += __shfl_xor_sync(0xffffffffu, s0, 2);
            s1 += __shfl_xor_sync(0xffffffffu, s1, 1);
            s1 += __shfl_xor_sync(0xffffffffu, s1, 2);
            float r0 = __fdividef(1.f, s0);
            float r1 = __fdividef(1.f, s1);

            float od[4][4];
            #pragma unroll
            for (int nt = 0; nt < 4; ++nt)
                #pragma unroll
                for (int v = 0; v < 4; ++v) od[nt][v] = 0.f;

            const uint32_t* svw = &sv32[aw * 1168];
            #pragma unroll
            for (int ks = 0; ks < 2; ++ks) {
                uint32_t a0 = h2pack(fs[2 * ks][0] * r0, fs[2 * ks][1] * r0);
                uint32_t a1 = h2pack(fs[2 * ks][2] * r1, fs[2 * ks][3] * r1);
                uint32_t a2 = h2pack(fs[2 * ks + 1][0] * r0, fs[2 * ks + 1][1] * r0);
                uint32_t a3 = h2pack(fs[2 * ks + 1][2] * r1, fs[2 * ks + 1][3] * r1);
                #pragma unroll
                for (int ntd = 0; ntd < 4; ++ntd) {
                    int col = ch + ntd * 8 + g;
                    uint32_t b0 = svw[(8 * ks + t) * 72 + col];
                    uint32_t b1 = svw[(8 * ks + t + 4) * 72 + col];
                    mma_f16(od[ntd], a0, a1, a2, a3, b0, b1);
                }
            }
            // od[ntd][v]: out[d = dh + g + (v>>1)*8][c = ch + ntd*8 + 2t + (v&1)]

            // blend with fp16 x (still intact in x-oct region): final = g*out + (1-g)*x
            #pragma unroll
            for (int ntd = 0; ntd < 4; ++ntd) {
                int cp = (ch >> 1) + ntd * 4 + t;
                uint32_t xwa = sxo[cp * 264 + (dh + g) * 8 + aw];
                uint32_t xwb = sxo[cp * 264 + (dh + g + 8) * 8 + aw];
                float2 xa = __half22float2(*reinterpret_cast<__half2*>(&xwa));
                float2 xb = __half22float2(*reinterpret_cast<__half2*>(&xwb));
                pk2[ntd][0] = h2pack(gg * od[ntd][0] + g1 * xa.x,
                                     gg * od[ntd][1] + g1 * xa.y);
                pk2[ntd][1] = h2pack(gg * od[ntd][2] + g1 * xb.x,
                                     gg * od[ntd][3] + g1 * xb.y);
            }
        }
        __syncthreads();   // barrier 2: all x-blend reads + QKV reads done

        // sout (final fp16 values) overlays x-oct: word = cp*264 + w*33 + d
        #pragma unroll
        for (int ntd = 0; ntd < 4; ++ntd) {
            int cp = (ch >> 1) + ntd * 4 + t;
            sxo[cp * 264 + aw * 33 + dh + g]     = pk2[ntd][0];
            sxo[cp * 264 + aw * 33 + dh + g + 8] = pk2[ntd][1];
        }
        // next oct's phase B touches only x-oct(j+1) + QKV: disjoint from these writes
    }
    __syncthreads();   // all sout writes complete

    // ---- Epilogue: convert + store, fully coalesced (no x reload) ----
    #pragma unroll
    for (int it = 0; it < 8; ++it) {
        int i  = tid + it * NTHREADS;
        int cp = i >> 8, d = (i >> 3) & 31, w4 = i & 7;
        const uint32_t* so = sxw + (w4 >> 1) * OCT_S;
        int wl = (w4 & 1) * 4;
        float o0[4], o1[4];
        #pragma unroll
        for (int j = 0; j < 4; ++j) {
            uint32_t pw = so[cp * 264 + (wl + j) * 33 + d];
            float2 f = __half22float2(*reinterpret_cast<__half2*>(&pw));
            o0[j] = f.x;   // c = 2cp
            o1[j] = f.y;   // c = 2cp+1
        }
        size_t ga0 = base + ((size_t)(2 * cp) * D_DIM + d) * HW + w4 * 4;
        size_t ga1 = ga0 + (size_t)D_DIM * HW;
        float4 r0 = make_float4(o0[0], o0[1], o0[2], o0[3]);
        float4 r1 = make_float4(o1[0], o1[1], o1[2], o1[3]);
        *reinterpret_cast<float4*>(out + ga0) = r0;
        *reinterpret_cast<float4*>(out + ga1) = r1;
    }
}

// ---------------------------------------------------------------------------
extern "C" void kernel_launch(void* const* d_in, const int* in_sizes, int n_in,
                              void* d_out, int out_size) {
    const float* x        = (const float*)d_in[0];
    const float* text_emb = (const float*)d_in[1];
    const float* wq       = (const float*)d_in[2];
    const float* bq       = (const float*)d_in[3];
    const float* wk       = (const float*)d_in[4];
    const float* bk       = (const float*)d_in[5];
    const float* wv       = (const float*)d_in[6];
    const float* bv       = (const float*)d_in[7];
    const float* wt       = (const float*)d_in[8];
    const float* bt       = (const float*)d_in[9];
    const float* pos      = (const float*)d_in[10];
    const float* gamma    = (const float*)d_in[11];
    float* out = (float*)d_out;

    cudaFuncSetAttribute(attn_kernel, cudaFuncAttributeMaxDynamicSharedMemorySize, SMEM_BYTES);

    setup_kernel<<<1, 256>>>(text_emb, wt, bt, wq, wk, wv);

    const int grid = B_DIM * H_DIM * (W_DIM / WT);  // 576
    attn_kernel<<<grid, NTHREADS, SMEM_BYTES>>>(x, bq, bk, bv, pos, gamma, out);
}

// round 14
// speedup vs baseline: 1.9394x; 1.0202x over previous
#include <cuda_runtime.h>
#include <cuda_fp16.h>
#include <math.h>
#include <stdint.h>

// Problem constants
#define C_DIM 64
#define D_DIM 32
#define H_DIM 96
#define W_DIM 96
#define B_DIM 2
#define WT 32         // w-tile per CTA (one full 128B line)
#define NTHREADS 1024

// smem layout (float words)
#define SXW_OFF   0       // x fp16 c-pair words, 4 octs of [32 cp (*264)][d*8 + (w^(d&7))]
#define OCT_S     8456    // ≡ 8 mod 32 (bank rotation per oct)
#define SQH_OFF   33824   // Q fp16 [8 w (*1288h)][32 d (*40h)][q] : 5152 words
#define SKH_OFF   38976   // K : 5152 words
#define SV_OFF    44128   // V fp16 pairs: uint32 [8 w (*1172)][16 epair (*72)][64 c] : 9376 words
#define SBIAS_OFF 53504   // 128
#define SPOS_OFF  53632   // 1024
#define SMEM_FLOATS 54656
#define SMEM_BYTES (SMEM_FLOATS * 4)   // 218624 B -> 1 CTA/SM

__device__ float g_tb[32];
__device__ uint32_t g_wpackh[4096];   // prepacked fp16 W in m16n8k16 A-fragment order

__device__ __forceinline__ void mma_f16(float* d, uint32_t a0, uint32_t a1, uint32_t a2,
                                        uint32_t a3, uint32_t b0, uint32_t b1) {
    asm volatile(
        "mma.sync.aligned.m16n8k16.row.col.f32.f16.f16.f32 "
        "{%0,%1,%2,%3}, {%4,%5,%6,%7}, {%8,%9}, {%0,%1,%2,%3};"
        : "+f"(d[0]), "+f"(d[1]), "+f"(d[2]), "+f"(d[3])
        : "r"(a0), "r"(a1), "r"(a2), "r"(a3), "r"(b0), "r"(b1));
}

__device__ __forceinline__ uint32_t h2pack(float lo, float hi) {
    __half2 h = __floats2half2_rn(lo, hi);
    return *reinterpret_cast<uint32_t*>(&h);
}

__device__ __forceinline__ void ldsm_x4(uint32_t* r, const void* p) {
    uint32_t a = (uint32_t)__cvta_generic_to_shared(p);
    asm volatile("ldmatrix.sync.aligned.m8n8.x4.shared.b16 {%0,%1,%2,%3}, [%4];"
                 : "=r"(r[0]), "=r"(r[1]), "=r"(r[2]), "=r"(r[3]) : "r"(a));
}

// ---------------------------------------------------------------------------
// Setup kernel: text bias + weight prepack (fp16 A-fragment order for k16)
// ---------------------------------------------------------------------------
__global__ void setup_kernel(const float* __restrict__ text_emb,
                             const float* __restrict__ wt,
                             const float* __restrict__ bt,
                             const float* __restrict__ wq,
                             const float* __restrict__ wk,
                             const float* __restrict__ wv) {
    __shared__ float mcol[256];
    int t = threadIdx.x;
    float s = 0.f;
    #pragma unroll
    for (int r = 0; r < 32; ++r) s += text_emb[r * 256 + t];
    mcol[t] = s * (1.0f / 32.0f);
    __syncthreads();
    int warp = t >> 5, lane = t & 31;
    for (int q = warp; q < 32; q += 8) {
        float acc = 0.f;
        #pragma unroll
        for (int k = 0; k < 8; ++k) acc += wt[q * 256 + lane + k * 32] * mcol[lane + k * 32];
        #pragma unroll
        for (int o = 16; o > 0; o >>= 1) acc += __shfl_xor_sync(0xffffffffu, acc, o);
        if (lane == 0) g_tb[q] = acc + bt[q];
    }
    // g_wpackh[((mt*4+ks)*32 + lane)*4 + j] = pair {W[o][k], W[o][k+1]}
    #pragma unroll
    for (int it = 0; it < 16; ++it) {
        int idx  = t + it * 256;    // 4096 words
        int j    = idx & 3;
        int ln   = (idx >> 2) & 31;
        int ks   = (idx >> 7) & 3;
        int mt   = idx >> 9;
        int g = ln >> 2, tt = ln & 3;
        int o = mt * 16 + g + (j & 1) * 8;
        int k = ks * 16 + 2 * tt + (j >> 1) * 8;
        float v0, v1;
        if (o < 32)       { v0 = wq[o * 64 + k];        v1 = wq[o * 64 + k + 1]; }
        else if (o < 64)  { v0 = wk[(o - 32) * 64 + k]; v1 = wk[(o - 32) * 64 + k + 1]; }
        else              { v0 = wv[(o - 64) * 64 + k]; v1 = wv[(o - 64) * 64 + k + 1]; }
        __half2 h = __floats2half2_rn(v0, v1);
        g_wpackh[idx] = *reinterpret_cast<uint32_t*>(&h);
    }
}

// ---------------------------------------------------------------------------
// Main fused kernel: one block per (b, h, 32-w line); 1024 threads, 1 CTA/SM
// ---------------------------------------------------------------------------
__global__ __launch_bounds__(NTHREADS, 1)
void attn_kernel(const float* __restrict__ x,
                 const float* __restrict__ bq, const float* __restrict__ bk,
                 const float* __restrict__ bv,
                 const float* __restrict__ pos, const float* __restrict__ gamma,
                 float* __restrict__ out) {
    extern __shared__ float sm[];
    uint32_t* sxw  = reinterpret_cast<uint32_t*>(sm + SXW_OFF);   // x fp16 words / sout overlay
    __half* sqh    = reinterpret_cast<__half*>(sm + SQH_OFF);
    __half* skh    = reinterpret_cast<__half*>(sm + SKH_OFF);
    __half* sv_h   = reinterpret_cast<__half*>(sm + SV_OFF);
    uint32_t* sv32 = reinterpret_cast<uint32_t*>(sm + SV_OFF);
    float* sbias   = sm + SBIAS_OFF;
    float* spos    = sm + SPOS_OFF;

    const int tid = threadIdx.x;
    const int bid = blockIdx.x;
    const int b   = bid / (H_DIM * 3);
    const int rem = bid % (H_DIM * 3);
    const int h   = rem / 3;
    const int w0  = (rem % 3) * WT;

    const int HW = H_DIM * W_DIM; // 9216
    const size_t base = (size_t)b * C_DIM * D_DIM * HW + (size_t)h * W_DIM + w0;

    const int warp = tid >> 5, lane = tid & 31;
    const int g = lane >> 2, t = lane & 3;

    // gate (uniform; load early to overlap)
    const float gm = gamma[0];
    const float gg = 1.f / (1.f + __expf(-gm));
    const float g1 = 1.f - gg;

    // ---- Phase A: coalesced x load + fp16 c-pair pack, XOR-swizzled store ----
    // x element (cp, d, lw in oct) -> word cp*264 + d*8 + (lw ^ (d&7)); conflict-free scalar STS
    #pragma unroll
    for (int it = 0; it < 8; ++it) {
        int i  = tid + it * NTHREADS;
        int cp = i >> 8, d = (i >> 3) & 31, w4 = i & 7;
        const float* p0 = x + base + ((size_t)(2 * cp) * D_DIM + d) * HW + w4 * 4;
        const float* p1 = p0 + (size_t)D_DIM * HW;
        float4 v0 = *reinterpret_cast<const float4*>(p0);
        float4 v1 = *reinterpret_cast<const float4*>(p1);
        uint32_t wvp[4];
        wvp[0] = h2pack(v0.x, v1.x);
        wvp[1] = h2pack(v0.y, v1.y);
        wvp[2] = h2pack(v0.z, v1.z);
        wvp[3] = h2pack(v0.w, v1.w);
        uint32_t* dst = &sxw[(w4 >> 1) * OCT_S + cp * 264 + d * 8];
        const int key = d & 7;
        const int lwb = (w4 & 1) * 4;
        #pragma unroll
        for (int j = 0; j < 4; ++j) dst[(lwb + j) ^ key] = wvp[j];
    }
    if (tid < 128) {
        float bb;
        if (tid < 32)      bb = bq[tid] + g_tb[tid];
        else if (tid < 64) bb = bk[tid - 32] + g_tb[tid - 32];
        else               bb = bv[tid - 64];
        sbias[tid] = bb;
    }
    spos[tid] = pos[tid];
    __syncthreads();

    // roles
    const int mw = warp & 3;        // phase B: 0:Q 1:K 2:V(c0-31) 3:V(c32-63)
    const int ns = warp >> 2;       // phase B: n slice of 32 (8 slices over 256 n)
    const int aw = warp & 7;        // phase C/D: w within oct
    const int dh = ((warp >> 3) & 1) * 16;
    const int ch = (warp >> 4) * 32;

    // phase-B swizzled column offsets (logical col n = ns*32 + nt*8 + g -> d = ns*4+nt, w = g)
    const int g2 = g ^ ((ns & 1) * 4);
    int bcol[4];
    #pragma unroll
    for (int nt = 0; nt < 4; ++nt) bcol[nt] = (ns * 4 + nt) * 8 + (g2 ^ nt);

    for (int oct = 0; oct < 4; ++oct) {
        uint32_t* sxo = sxw + oct * OCT_S;

        // ---- Phase B: fp16 MMA GEMM  C[128 o][256 n] = W[128,64] * X[64,256] ----
        {
            float acc[2][4][4];
            #pragma unroll
            for (int s_ = 0; s_ < 2; ++s_)
                #pragma unroll
                for (int nt = 0; nt < 4; ++nt)
                    #pragma unroll
                    for (int v = 0; v < 4; ++v) acc[s_][nt][v] = 0.f;

            const uint4* wp4 = reinterpret_cast<const uint4*>(g_wpackh);
            #pragma unroll
            for (int ks = 0; ks < 4; ++ks) {
                uint4 a0 = __ldg(&wp4[((mw * 2 + 0) * 4 + ks) * 32 + lane]);
                uint4 a1 = __ldg(&wp4[((mw * 2 + 1) * 4 + ks) * 32 + lane]);
                const uint32_t* xr0 = &sxo[(ks * 8 + t) * 264];
                const uint32_t* xr1 = &sxo[(ks * 8 + t + 4) * 264];
                #pragma unroll
                for (int nt = 0; nt < 4; ++nt) {
                    uint32_t b0 = xr0[bcol[nt]];
                    uint32_t b1 = xr1[bcol[nt]];
                    mma_f16(acc[0][nt], a0.x, a0.y, a0.z, a0.w, b0, b1);
                    mma_f16(acc[1][nt], a1.x, a1.y, a1.z, a1.w, b0, b1);
                }
            }

            if (mw < 2) {
                __half* dsth = (mw == 0) ? sqh : skh;
                const int boff = mw * 32;
                const float qscale = (mw == 0) ? 0.17677669529663687f : 1.0f;
                #pragma unroll
                for (int s_ = 0; s_ < 2; ++s_) {
                    #pragma unroll
                    for (int nt = 0; nt < 4; ++nt) {
                        #pragma unroll
                        for (int v = 0; v < 4; ++v) {
                            int q = s_ * 16 + g + (v >> 1) * 8;
                            int n = ns * 32 + nt * 8 + 2 * t + (v & 1);
                            int outer = n >> 3, w = n & 7;   // d for Q, e for K
                            float val = acc[s_][nt][v] + sbias[boff + q] + spos[q * 32 + outer];
                            dsth[w * 1288 + outer * 40 + q] = __float2half_rn(val * qscale);
                        }
                    }
                }
            } else {
                const int cbb = (mw - 2) * 32;
                #pragma unroll
                for (int s_ = 0; s_ < 2; ++s_) {
                    #pragma unroll
                    for (int nt = 0; nt < 4; ++nt) {
                        #pragma unroll
                        for (int v = 0; v < 4; ++v) {
                            int c = cbb + s_ * 16 + g + (v >> 1) * 8;
                            int n = ns * 32 + nt * 8 + 2 * t + (v & 1);
                            int e = n >> 3, w = n & 7;
                            sv_h[(w * 1172 + (e >> 1) * 72 + c) * 2 + (e & 1)] =
                                __float2half_rn(acc[s_][nt][v] + sbias[64 + c]);
                        }
                    }
                }
            }
        }
        __syncthreads();   // barrier 1: QKV(oct) ready; x-oct GEMM reads done

        // ---- Phases C+D fused per warp: (w, d-half, c-half) + in-register blend ----
        uint32_t pk2[4][2];   // final blended fp16 pairs
        {
            const __half* qh = &sqh[aw * 1288];   // [d*40 + q]
            const __half* kh = &skh[aw * 1288];   // [e*40 + q]

            uint32_t qa[2][4];
            uint32_t kb[2][2][4];
            #pragma unroll
            for (int ks = 0; ks < 2; ++ks) {
                ldsm_x4(qa[ks],
                    &qh[(dh + ((lane >> 3) & 1) * 8 + (lane & 7)) * 40 + ks * 16 + (lane >> 4) * 8]);
                #pragma unroll
                for (int p = 0; p < 2; ++p)
                    ldsm_x4(kb[ks][p],
                        &kh[((p * 2 + (lane >> 4)) * 8 + (lane & 7)) * 40 + ks * 16 + ((lane >> 3) & 1) * 8]);
            }

            float fs[4][4];
            #pragma unroll
            for (int nt = 0; nt < 4; ++nt)
                #pragma unroll
                for (int v = 0; v < 4; ++v) fs[nt][v] = 0.f;

            #pragma unroll
            for (int ks = 0; ks < 2; ++ks)
                #pragma unroll
                for (int nt = 0; nt < 4; ++nt)
                    mma_f16(fs[nt], qa[ks][0], qa[ks][1], qa[ks][2], qa[ks][3],
                            kb[ks][nt >> 1][(nt & 1) * 2], kb[ks][nt >> 1][(nt & 1) * 2 + 1]);
            // fs[nt][v]: S[d = dh + g + (v>>1)*8][e = nt*8 + 2t + (v&1)]

            float m0 = -1e30f, m1 = -1e30f;
            #pragma unroll
            for (int nt = 0; nt < 4; ++nt) {
                m0 = fmaxf(m0, fmaxf(fs[nt][0], fs[nt][1]));
                m1 = fmaxf(m1, fmaxf(fs[nt][2], fs[nt][3]));
            }
            m0 = fmaxf(m0, __shfl_xor_sync(0xffffffffu, m0, 1));
            m0 = fmaxf(m0, __shfl_xor_sync(0xffffffffu, m0, 2));
            m1 = fmaxf(m1, __shfl_xor_sync(0xffffffffu, m1, 1));
            m1 = fmaxf(m1, __shfl_xor_sync(0xffffffffu, m1, 2));

            float s0 = 0.f, s1 = 0.f;
            #pragma unroll
            for (int nt = 0; nt < 4; ++nt) {
                fs[nt][0] = __expf(fs[nt][0] - m0); s0 += fs[nt][0];
                fs[nt][1] = __expf(fs[nt][1] - m0); s0 += fs[nt][1];
                fs[nt][2] = __expf(fs[nt][2] - m1); s1 += fs[nt][2];
                fs[nt][3] = __expf(fs[nt][3] - m1); s1 += fs[nt][3];
            }
            s0 += __shfl_xor_sync(0xffffffffu, s0, 1);
            s0 += __shfl_xor_sync(0xffffffffu, s0, 2);
            s1 += __shfl_xor_sync(0xffffffffu, s1, 1);
            s1 += __shfl_xor_sync(0xffffffffu, s1, 2);
            float r0 = __fdividef(1.f, s0);
            float r1 = __fdividef(1.f, s1);

            float od[4][4];
            #pragma unroll
            for (int nt = 0; nt < 4; ++nt)
                #pragma unroll
                for (int v = 0; v < 4; ++v) od[nt][v] = 0.f;

            const uint32_t* svw = &sv32[aw * 1172];
            #pragma unroll
            for (int ks = 0; ks < 2; ++ks) {
                uint32_t a0 = h2pack(fs[2 * ks][0] * r0, fs[2 * ks][1] * r0);
                uint32_t a1 = h2pack(fs[2 * ks][2] * r1, fs[2 * ks][3] * r1);
                uint32_t a2 = h2pack(fs[2 * ks + 1][0] * r0, fs[2 * ks + 1][1] * r0);
                uint32_t a3 = h2pack(fs[2 * ks + 1][2] * r1, fs[2 * ks + 1][3] * r1);
                #pragma unroll
                for (int ntd = 0; ntd < 4; ++ntd) {
                    int col = ch + ntd * 8 + g;
                    uint32_t b0 = svw[(8 * ks + t) * 72 + col];
                    uint32_t b1 = svw[(8 * ks + t + 4) * 72 + col];
                    mma_f16(od[ntd], a0, a1, a2, a3, b0, b1);
                }
            }
            // od[ntd][v]: out[d = dh + g + (v>>1)*8][c = ch + ntd*8 + 2t + (v&1)]

            // blend with fp16 x (swizzled reads, conflict-free: bank 8((t+g)&3) + (aw^g))
            #pragma unroll
            for (int ntd = 0; ntd < 4; ++ntd) {
                int cp = (ch >> 1) + ntd * 4 + t;
                uint32_t xwa = sxo[cp * 264 + (dh + g) * 8 + (aw ^ g)];
                uint32_t xwb = sxo[cp * 264 + (dh + g + 8) * 8 + (aw ^ g)];
                float2 xa = __half22float2(*reinterpret_cast<__half2*>(&xwa));
                float2 xb = __half22float2(*reinterpret_cast<__half2*>(&xwb));
                pk2[ntd][0] = h2pack(gg * od[ntd][0] + g1 * xa.x,
                                     gg * od[ntd][1] + g1 * xa.y);
                pk2[ntd][1] = h2pack(gg * od[ntd][2] + g1 * xb.x,
                                     gg * od[ntd][3] + g1 * xb.y);
            }
        }
        __syncthreads();   // barrier 2: all x-blend reads + QKV reads done

        // sout (final fp16 values) overlays x-oct: word = cp*264 + w*33 + d (conflict-free)
        #pragma unroll
        for (int ntd = 0; ntd < 4; ++ntd) {
            int cp = (ch >> 1) + ntd * 4 + t;
            sxo[cp * 264 + aw * 33 + dh + g]     = pk2[ntd][0];
            sxo[cp * 264 + aw * 33 + dh + g + 8] = pk2[ntd][1];
        }
        // next oct's phase B touches only x-oct(j+1) + QKV: disjoint from these writes
    }
    __syncthreads();   // all sout writes complete

    // ---- Epilogue: convert + store, fully coalesced (no x reload) ----
    #pragma unroll
    for (int it = 0; it < 8; ++it) {
        int i  = tid + it * NTHREADS;
        int cp = i >> 8, d = (i >> 3) & 31, w4 = i & 7;
        const uint32_t* so = sxw + (w4 >> 1) * OCT_S;
        int wl = (w4 & 1) * 4;
        float o0[4], o1[4];
        #pragma unroll
        for (int j = 0; j < 4; ++j) {
            uint32_t pw = so[cp * 264 + (wl + j) * 33 + d];
            float2 f = __half22float2(*reinterpret_cast<__half2*>(&pw));
            o0[j] = f.x;   // c = 2cp
            o1[j] = f.y;   // c = 2cp+1
        }
        size_t ga0 = base + ((size_t)(2 * cp) * D_DIM + d) * HW + w4 * 4;
        size_t ga1 = ga0 + (size_t)D_DIM * HW;
        float4 r0 = make_float4(o0[0], o0[1], o0[2], o0[3]);
        float4 r1 = make_float4(o1[0], o1[1], o1[2], o1[3]);
        *reinterpret_cast<float4*>(out + ga0) = r0;
        *reinterpret_cast<float4*>(out + ga1) = r1;
    }
}

// ---------------------------------------------------------------------------
extern "C" void kernel_launch(void* const* d_in, const int* in_sizes, int n_in,
                              void* d_out, int out_size) {
    const float* x        = (const float*)d_in[0];
    const float* text_emb = (const float*)d_in[1];
    const float* wq       = (const float*)d_in[2];
    const float* bq       = (const float*)d_in[3];
    const float* wk       = (const float*)d_in[4];
    const float* bk       = (const float*)d_in[5];
    const float* wv       = (const float*)d_in[6];
    const float* bv       = (const float*)d_in[7];
    const float* wt       = (const float*)d_in[8];
    const float* bt       = (const float*)d_in[9];
    const float* pos      = (const float*)d_in[10];
    const float* gamma    = (const float*)d_in[11];
    float* out = (float*)d_out;

    cudaFuncSetAttribute(attn_kernel, cudaFuncAttributeMaxDynamicSharedMemorySize, SMEM_BYTES);

    setup_kernel<<<1, 256>>>(text_emb, wt, bt, wq, wk, wv);

    const int grid = B_DIM * H_DIM * (W_DIM / WT);  // 576
    attn_kernel<<<grid, NTHREADS, SMEM_BYTES>>>(x, bq, bk, bv, pos, gamma, out);
}

// round 15
// speedup vs baseline: 2.0308x; 1.0471x over previous
#include <cuda_runtime.h>
#include <cuda_fp16.h>
#include <math.h>
#include <stdint.h>

// Problem constants
#define C_DIM 64
#define D_DIM 32
#define H_DIM 96
#define W_DIM 96
#define B_DIM 2
#define WT 16         // w-tile per CTA (64B strips: full sectors)
#define NTHREADS 512

// smem layout (float words)
#define SXW_OFF   0       // x fp16 c-pair words, 4 octs (4w each) of [32 cp (*136)][d*4 + (w^swz)]
#define OCT_S     4360    // 32*136 + 8 pad, ≡ 8 mod 32
#define SQH_OFF   17440   // Q fp16 [4 w (*1288h)][32 d (*40h)][q] : 2576 words
#define SKH_OFF   20016   // K : 2576 words
#define SV_OFF    22592   // V fp16 pairs: uint32 [4 w (*1172)][16 epair (*72)][64 c] : 4688 words
#define SBIAS_OFF 27280   // 128
#define SPOS_OFF  27408   // 1024
#define SMEM_FLOATS 28432
#define SMEM_BYTES (SMEM_FLOATS * 4)   // 113728 B -> 2 CTAs/SM

__device__ float g_tb[32];
__device__ uint32_t g_wpackh[4096];   // prepacked fp16 W in m16n8k16 A-fragment order

__device__ __forceinline__ void mma_f16(float* d, uint32_t a0, uint32_t a1, uint32_t a2,
                                        uint32_t a3, uint32_t b0, uint32_t b1) {
    asm volatile(
        "mma.sync.aligned.m16n8k16.row.col.f32.f16.f16.f32 "
        "{%0,%1,%2,%3}, {%4,%5,%6,%7}, {%8,%9}, {%0,%1,%2,%3};"
        : "+f"(d[0]), "+f"(d[1]), "+f"(d[2]), "+f"(d[3])
        : "r"(a0), "r"(a1), "r"(a2), "r"(a3), "r"(b0), "r"(b1));
}

__device__ __forceinline__ uint32_t h2pack(float lo, float hi) {
    __half2 h = __floats2half2_rn(lo, hi);
    return *reinterpret_cast<uint32_t*>(&h);
}

__device__ __forceinline__ void ldsm_x4(uint32_t* r, const void* p) {
    uint32_t a = (uint32_t)__cvta_generic_to_shared(p);
    asm volatile("ldmatrix.sync.aligned.m8n8.x4.shared.b16 {%0,%1,%2,%3}, [%4];"
                 : "=r"(r[0]), "=r"(r[1]), "=r"(r[2]), "=r"(r[3]) : "r"(a));
}

// ---------------------------------------------------------------------------
// Setup kernel: text bias + weight prepack (fp16 A-fragment order for k16)
// ---------------------------------------------------------------------------
__global__ void setup_kernel(const float* __restrict__ text_emb,
                             const float* __restrict__ wt,
                             const float* __restrict__ bt,
                             const float* __restrict__ wq,
                             const float* __restrict__ wk,
                             const float* __restrict__ wv) {
    __shared__ float mcol[256];
    int t = threadIdx.x;
    float s = 0.f;
    #pragma unroll
    for (int r = 0; r < 32; ++r) s += text_emb[r * 256 + t];
    mcol[t] = s * (1.0f / 32.0f);
    __syncthreads();
    int warp = t >> 5, lane = t & 31;
    for (int q = warp; q < 32; q += 8) {
        float acc = 0.f;
        #pragma unroll
        for (int k = 0; k < 8; ++k) acc += wt[q * 256 + lane + k * 32] * mcol[lane + k * 32];
        #pragma unroll
        for (int o = 16; o > 0; o >>= 1) acc += __shfl_xor_sync(0xffffffffu, acc, o);
        if (lane == 0) g_tb[q] = acc + bt[q];
    }
    // g_wpackh[((mt*4+ks)*32 + lane)*4 + j] = pair {W[o][k], W[o][k+1]}
    #pragma unroll
    for (int it = 0; it < 16; ++it) {
        int idx  = t + it * 256;    // 4096 words
        int j    = idx & 3;
        int ln   = (idx >> 2) & 31;
        int ks   = (idx >> 7) & 3;
        int mt   = idx >> 9;
        int g = ln >> 2, tt = ln & 3;
        int o = mt * 16 + g + (j & 1) * 8;
        int k = ks * 16 + 2 * tt + (j >> 1) * 8;
        float v0, v1;
        if (o < 32)       { v0 = wq[o * 64 + k];        v1 = wq[o * 64 + k + 1]; }
        else if (o < 64)  { v0 = wk[(o - 32) * 64 + k]; v1 = wk[(o - 32) * 64 + k + 1]; }
        else              { v0 = wv[(o - 64) * 64 + k]; v1 = wv[(o - 64) * 64 + k + 1]; }
        __half2 h = __floats2half2_rn(v0, v1);
        g_wpackh[idx] = *reinterpret_cast<uint32_t*>(&h);
    }
}

// ---------------------------------------------------------------------------
// Main fused kernel: one block per (b, h, 16-w strip); 512 threads, 2 CTA/SM
// ---------------------------------------------------------------------------
__global__ __launch_bounds__(NTHREADS, 2)
void attn_kernel(const float* __restrict__ x,
                 const float* __restrict__ bq, const float* __restrict__ bk,
                 const float* __restrict__ bv,
                 const float* __restrict__ pos, const float* __restrict__ gamma,
                 float* __restrict__ out) {
    extern __shared__ float sm[];
    uint32_t* sxw  = reinterpret_cast<uint32_t*>(sm + SXW_OFF);   // x fp16 words / sout overlay
    __half* sqh    = reinterpret_cast<__half*>(sm + SQH_OFF);
    __half* skh    = reinterpret_cast<__half*>(sm + SKH_OFF);
    uint32_t* sv32 = reinterpret_cast<uint32_t*>(sm + SV_OFF);
    float* sbias   = sm + SBIAS_OFF;
    float* spos    = sm + SPOS_OFF;

    const int tid = threadIdx.x;
    const int bid = blockIdx.x;
    const int nwT = W_DIM / WT;   // 6
    const int b   = bid / (H_DIM * nwT);
    const int rem = bid % (H_DIM * nwT);
    const int h   = rem / nwT;
    const int w0  = (rem % nwT) * WT;

    const int HW = H_DIM * W_DIM; // 9216
    const size_t base = (size_t)b * C_DIM * D_DIM * HW + (size_t)h * W_DIM + w0;

    const int warp = tid >> 5, lane = tid & 31;
    const int g = lane >> 2, t = lane & 3;

    // gate (uniform; load early to overlap)
    const float gm = gamma[0];
    const float gg = 1.f / (1.f + __expf(-gm));
    const float g1 = 1.f - gg;

    // ---- Phase A: coalesced (64B strips) x load + fp16 c-pair pack, swizzled ----
    // word(cp, d, oct, w-in-oct j) = oct*4360 + cp*136 + d*4 + (j ^ ((d + (d>>2)) & 3))
    #pragma unroll
    for (int it = 0; it < 8; ++it) {
        int i  = tid + it * NTHREADS;       // 4096 units
        int cp = i >> 7, d = (i >> 2) & 31, w4 = i & 3;   // w4 = oct
        const float* p0 = x + base + ((size_t)(2 * cp) * D_DIM + d) * HW + w4 * 4;
        const float* p1 = p0 + (size_t)D_DIM * HW;
        float4 v0 = *reinterpret_cast<const float4*>(p0);
        float4 v1 = *reinterpret_cast<const float4*>(p1);
        uint32_t wvp[4];
        wvp[0] = h2pack(v0.x, v1.x);
        wvp[1] = h2pack(v0.y, v1.y);
        wvp[2] = h2pack(v0.z, v1.z);
        wvp[3] = h2pack(v0.w, v1.w);
        uint32_t* dst = &sxw[w4 * OCT_S + cp * 136 + d * 4];
        const int key = (d + (d >> 2)) & 3;
        #pragma unroll
        for (int j = 0; j < 4; ++j) dst[j ^ key] = wvp[j];
    }
    if (tid < 128) {
        float bb;
        if (tid < 32)      bb = bq[tid] + g_tb[tid];
        else if (tid < 64) bb = bk[tid - 32] + g_tb[tid - 32];
        else               bb = bv[tid - 64];
        sbias[tid] = bb;
    }
    #pragma unroll
    for (int it = 0; it < 2; ++it) spos[tid + it * NTHREADS] = pos[tid + it * NTHREADS];
    __syncthreads();

    // roles
    const int mw = warp & 3;        // phase B: 0:Q 1:K 2:V(c0-31) 3:V(c32-63)
    const int ns = warp >> 2;       // phase B: n slice of 32 = w index (n = w*32 + d)
    const int aw = warp & 3;        // phase C/D: w within oct
    const int dh = ((warp >> 2) & 1) * 16;
    const int ch = (warp >> 3) * 32;

    for (int oct = 0; oct < 4; ++oct) {
        uint32_t* sxo = sxw + oct * OCT_S;

        // ---- Phase B: fp16 MMA GEMM  C[128 o][128 n] = W[128,64] * X[64,128] ----
        // n = w*32 + d; warp (mw, ns=w)
        {
            float acc[2][4][4];
            #pragma unroll
            for (int s_ = 0; s_ < 2; ++s_)
                #pragma unroll
                for (int nt = 0; nt < 4; ++nt)
                    #pragma unroll
                    for (int v = 0; v < 4; ++v) acc[s_][nt][v] = 0.f;

            // swizzled column offsets: d = nt*8 + g
            int bcol[4];
            #pragma unroll
            for (int nt = 0; nt < 4; ++nt) {
                int d_ = nt * 8 + g;
                bcol[nt] = d_ * 4 + (ns ^ ((d_ + (d_ >> 2)) & 3));
            }

            const uint4* wp4 = reinterpret_cast<const uint4*>(g_wpackh);
            #pragma unroll
            for (int ks = 0; ks < 4; ++ks) {
                uint4 a0 = __ldg(&wp4[((mw * 2 + 0) * 4 + ks) * 32 + lane]);
                uint4 a1 = __ldg(&wp4[((mw * 2 + 1) * 4 + ks) * 32 + lane]);
                const uint32_t* xr0 = &sxo[(ks * 8 + t) * 136];
                const uint32_t* xr1 = &sxo[(ks * 8 + t + 4) * 136];
                #pragma unroll
                for (int nt = 0; nt < 4; ++nt) {
                    uint32_t b0 = xr0[bcol[nt]];
                    uint32_t b1 = xr1[bcol[nt]];
                    mma_f16(acc[0][nt], a0.x, a0.y, a0.z, a0.w, b0, b1);
                    mma_f16(acc[1][nt], a1.x, a1.y, a1.z, a1.w, b0, b1);
                }
            }

            if (mw < 2) {
                // Q/K -> [w=ns][outer][q] fp16, outer = nt*8 + 2t + (v&1)
                __half* dsth = ((mw == 0) ? sqh : skh) + ns * 1288;
                const int boff = mw * 32;
                const float qscale = (mw == 0) ? 0.17677669529663687f : 1.0f;
                #pragma unroll
                for (int s_ = 0; s_ < 2; ++s_) {
                    #pragma unroll
                    for (int nt = 0; nt < 4; ++nt) {
                        #pragma unroll
                        for (int v = 0; v < 4; ++v) {
                            int q = s_ * 16 + g + (v >> 1) * 8;
                            int outer = nt * 8 + 2 * t + (v & 1);
                            float val = acc[s_][nt][v] + sbias[boff + q] + spos[q * 32 + outer];
                            dsth[outer * 40 + q] = __float2half_rn(val * qscale);
                        }
                    }
                }
            } else {
                // V -> sv32[w*1172 + epair*72 + c], epair = nt*4 + t; halves = e parity (v&1)
                const int cbb = (mw - 2) * 32;
                uint32_t* svd = &sv32[ns * 1172];
                #pragma unroll
                for (int s_ = 0; s_ < 2; ++s_) {
                    #pragma unroll
                    for (int nt = 0; nt < 4; ++nt) {
                        #pragma unroll
                        for (int cg = 0; cg < 2; ++cg) {
                            int c = cbb + s_ * 16 + g + cg * 8;
                            float bia = sbias[64 + c];
                            svd[(nt * 4 + t) * 72 + c] =
                                h2pack(acc[s_][nt][cg * 2] + bia, acc[s_][nt][cg * 2 + 1] + bia);
                        }
                    }
                }
            }
        }
        __syncthreads();   // barrier 1: QKV(oct) ready; x-oct GEMM reads done

        // ---- Phases C+D fused per warp: (w, d-half, c-half) + in-register blend ----
        uint32_t pk2[4][2];   // final blended fp16 pairs
        {
            const __half* qh = &sqh[aw * 1288];   // [d*40 + q]
            const __half* kh = &skh[aw * 1288];   // [e*40 + q]

            uint32_t qa[2][4];
            uint32_t kb[2][2][4];
            #pragma unroll
            for (int ks = 0; ks < 2; ++ks) {
                ldsm_x4(qa[ks],
                    &qh[(dh + ((lane >> 3) & 1) * 8 + (lane & 7)) * 40 + ks * 16 + (lane >> 4) * 8]);
                #pragma unroll
                for (int p = 0; p < 2; ++p)
                    ldsm_x4(kb[ks][p],
                        &kh[((p * 2 + (lane >> 4)) * 8 + (lane & 7)) * 40 + ks * 16 + ((lane >> 3) & 1) * 8]);
            }

            float fs[4][4];
            #pragma unroll
            for (int nt = 0; nt < 4; ++nt)
                #pragma unroll
                for (int v = 0; v < 4; ++v) fs[nt][v] = 0.f;

            #pragma unroll
            for (int ks = 0; ks < 2; ++ks)
                #pragma unroll
                for (int nt = 0; nt < 4; ++nt)
                    mma_f16(fs[nt], qa[ks][0], qa[ks][1], qa[ks][2], qa[ks][3],
                            kb[ks][nt >> 1][(nt & 1) * 2], kb[ks][nt >> 1][(nt & 1) * 2 + 1]);
            // fs[nt][v]: S[d = dh + g + (v>>1)*8][e = nt*8 + 2t + (v&1)]

            float m0 = -1e30f, m1 = -1e30f;
            #pragma unroll
            for (int nt = 0; nt < 4; ++nt) {
                m0 = fmaxf(m0, fmaxf(fs[nt][0], fs[nt][1]));
                m1 = fmaxf(m1, fmaxf(fs[nt][2], fs[nt][3]));
            }
            m0 = fmaxf(m0, __shfl_xor_sync(0xffffffffu, m0, 1));
            m0 = fmaxf(m0, __shfl_xor_sync(0xffffffffu, m0, 2));
            m1 = fmaxf(m1, __shfl_xor_sync(0xffffffffu, m1, 1));
            m1 = fmaxf(m1, __shfl_xor_sync(0xffffffffu, m1, 2));

            float s0 = 0.f, s1 = 0.f;
            #pragma unroll
            for (int nt = 0; nt < 4; ++nt) {
                fs[nt][0] = __expf(fs[nt][0] - m0); s0 += fs[nt][0];
                fs[nt][1] = __expf(fs[nt][1] - m0); s0 += fs[nt][1];
                fs[nt][2] = __expf(fs[nt][2] - m1); s1 += fs[nt][2];
                fs[nt][3] = __expf(fs[nt][3] - m1); s1 += fs[nt][3];
            }
            s0 += __shfl_xor_sync(0xffffffffu, s0, 1);
            s0 += __shfl_xor_sync(0xffffffffu, s0, 2);
            s1 += __shfl_xor_sync(0xffffffffu, s1, 1);
            s1 += __shfl_xor_sync(0xffffffffu, s1, 2);
            float r0 = __fdividef(1.f, s0);
            float r1 = __fdividef(1.f, s1);

            float od[4][4];
            #pragma unroll
            for (int nt = 0; nt < 4; ++nt)
                #pragma unroll
                for (int v = 0; v < 4; ++v) od[nt][v] = 0.f;

            const uint32_t* svw = &sv32[aw * 1172];
            #pragma unroll
            for (int ks = 0; ks < 2; ++ks) {
                uint32_t a0 = h2pack(fs[2 * ks][0] * r0, fs[2 * ks][1] * r0);
                uint32_t a1 = h2pack(fs[2 * ks][2] * r1, fs[2 * ks][3] * r1);
                uint32_t a2 = h2pack(fs[2 * ks + 1][0] * r0, fs[2 * ks + 1][1] * r0);
                uint32_t a3 = h2pack(fs[2 * ks + 1][2] * r1, fs[2 * ks + 1][3] * r1);
                #pragma unroll
                for (int ntd = 0; ntd < 4; ++ntd) {
                    int col = ch + ntd * 8 + g;
                    uint32_t b0 = svw[(8 * ks + t) * 72 + col];
                    uint32_t b1 = svw[(8 * ks + t + 4) * 72 + col];
                    mma_f16(od[ntd], a0, a1, a2, a3, b0, b1);
                }
            }
            // od[ntd][v]: out[d = dh + g + (v>>1)*8][c = ch + ntd*8 + 2t + (v&1)]

            // blend with fp16 x (swizzled reads, conflict-free)
            #pragma unroll
            for (int ntd = 0; ntd < 4; ++ntd) {
                int cp = (ch >> 1) + ntd * 4 + t;
                int da = dh + g, db = dh + g + 8;
                uint32_t xwa = sxo[cp * 136 + da * 4 + (aw ^ ((da + (da >> 2)) & 3))];
                uint32_t xwb = sxo[cp * 136 + db * 4 + (aw ^ ((db + (db >> 2)) & 3))];
                float2 xa = __half22float2(*reinterpret_cast<__half2*>(&xwa));
                float2 xb = __half22float2(*reinterpret_cast<__half2*>(&xwb));
                pk2[ntd][0] = h2pack(gg * od[ntd][0] + g1 * xa.x,
                                     gg * od[ntd][1] + g1 * xa.y);
                pk2[ntd][1] = h2pack(gg * od[ntd][2] + g1 * xb.x,
                                     gg * od[ntd][3] + g1 * xb.y);
            }
        }
        __syncthreads();   // barrier 2: all x-blend reads + QKV reads done

        // sout (final fp16 values) overlays x-oct: word = cp*136 + w*34 + d (conflict-free)
        #pragma unroll
        for (int ntd = 0; ntd < 4; ++ntd) {
            int cp = (ch >> 1) + ntd * 4 + t;
            sxo[cp * 136 + aw * 34 + dh + g]     = pk2[ntd][0];
            sxo[cp * 136 + aw * 34 + dh + g + 8] = pk2[ntd][1];
        }
        // next oct's phase B touches only x-oct(j+1) + QKV: disjoint from these writes
    }
    __syncthreads();   // all sout writes complete

    // ---- Epilogue: convert + store, coalesced 64B strips (no x reload) ----
    #pragma unroll
    for (int it = 0; it < 8; ++it) {
        int i  = tid + it * NTHREADS;
        int cp = i >> 7, d = (i >> 2) & 31, w4 = i & 3;
        const uint32_t* so = sxw + w4 * OCT_S;
        float o0[4], o1[4];
        #pragma unroll
        for (int j = 0; j < 4; ++j) {
            uint32_t pw = so[cp * 136 + j * 34 + d];
            float2 f = __half22float2(*reinterpret_cast<__half2*>(&pw));
            o0[j] = f.x;   // c = 2cp
            o1[j] = f.y;   // c = 2cp+1
        }
        size_t ga0 = base + ((size_t)(2 * cp) * D_DIM + d) * HW + w4 * 4;
        size_t ga1 = ga0 + (size_t)D_DIM * HW;
        float4 r0 = make_float4(o0[0], o0[1], o0[2], o0[3]);
        float4 r1 = make_float4(o1[0], o1[1], o1[2], o1[3]);
        *reinterpret_cast<float4*>(out + ga0) = r0;
        *reinterpret_cast<float4*>(out + ga1) = r1;
    }
}

// ---------------------------------------------------------------------------
extern "C" void kernel_launch(void* const* d_in, const int* in_sizes, int n_in,
                              void* d_out, int out_size) {
    const float* x        = (const float*)d_in[0];
    const float* text_emb = (const float*)d_in[1];
    const float* wq       = (const float*)d_in[2];
    const float* bq       = (const float*)d_in[3];
    const float* wk       = (const float*)d_in[4];
    const float* bk       = (const float*)d_in[5];
    const float* wv       = (const float*)d_in[6];
    const float* bv       = (const float*)d_in[7];
    const float* wt       = (const float*)d_in[8];
    const float* bt       = (const float*)d_in[9];
    const float* pos      = (const float*)d_in[10];
    const float* gamma    = (const float*)d_in[11];
    float* out = (float*)d_out;

    cudaFuncSetAttribute(attn_kernel, cudaFuncAttributeMaxDynamicSharedMemorySize, SMEM_BYTES);

    setup_kernel<<<1, 256>>>(text_emb, wt, bt, wq, wk, wv);

    const int grid = B_DIM * H_DIM * (W_DIM / WT);  // 1152
    attn_kernel<<<grid, NTHREADS, SMEM_BYTES>>>(x, bq, bk, bv, pos, gamma, out);
}

// round 16
// speedup vs baseline: 2.5523x; 1.2568x over previous
#include <cuda_runtime.h>
#include <cuda_fp16.h>
#include <math.h>
#include <stdint.h>

// Problem constants
#define C_DIM 64
#define D_DIM 32
#define H_DIM 96
#define W_DIM 96
#define B_DIM 2
#define WT 16         // w-tile per CTA (64B strips: full sectors)
#define NTHREADS 512
#define QSCALE 0.17677669529663687f

// smem layout (word units)
#define SXW_OFF   0       // x fp16 c-pair words, 4 octs (4w each) of [32 cp (*136)][d*4 + (w^swz)]
#define OCT_S     4360    // 32*136 + 8 pad, ≡ 8 mod 32
#define SQ32_OFF  17440   // Q fp16 pairs: uint32 [4 w (*644)][32 q (*20)][16 dpair]
#define SK32_OFF  20016   // K same, outer = e
#define SV_OFF    22592   // V fp16 pairs: uint32 [4 w (*1172)][16 epair (*72)][64 c]
#define SBIAS_OFF 27280   // 64 (V bias only)
#define SQA_OFF   27344   // qadd table: uint32 [32 q (*20)][16 dpair] = 640
#define SKA_OFF   27984   // kadd table: 640
#define SMEM_FLOATS 28624
#define SMEM_BYTES (SMEM_FLOATS * 4)   // 114496 B -> 2 CTAs/SM

__device__ uint32_t g_wpackh[4096];   // prepacked fp16 W (Q rows pre-scaled)
__device__ uint32_t g_qadd2[512];     // fp16 pairs: (bq+tb+pos)*QSCALE
__device__ uint32_t g_kadd2[512];     // fp16 pairs: bk+tb+pos

__device__ __forceinline__ void mma_f16(float* d, uint32_t a0, uint32_t a1, uint32_t a2,
                                        uint32_t a3, uint32_t b0, uint32_t b1) {
    asm volatile(
        "mma.sync.aligned.m16n8k16.row.col.f32.f16.f16.f32 "
        "{%0,%1,%2,%3}, {%4,%5,%6,%7}, {%8,%9}, {%0,%1,%2,%3};"
        : "+f"(d[0]), "+f"(d[1]), "+f"(d[2]), "+f"(d[3])
        : "r"(a0), "r"(a1), "r"(a2), "r"(a3), "r"(b0), "r"(b1));
}

__device__ __forceinline__ uint32_t h2pack(float lo, float hi) {
    __half2 h = __floats2half2_rn(lo, hi);
    return *reinterpret_cast<uint32_t*>(&h);
}

__device__ __forceinline__ void ldsm_x4_trans(uint32_t* r, const void* p) {
    uint32_t a = (uint32_t)__cvta_generic_to_shared(p);
    asm volatile("ldmatrix.sync.aligned.m8n8.x4.trans.shared.b16 {%0,%1,%2,%3}, [%4];"
                 : "=r"(r[0]), "=r"(r[1]), "=r"(r[2]), "=r"(r[3]) : "r"(a));
}

// ---------------------------------------------------------------------------
// Setup kernel: text bias, fused bias+pos tables, weight prepack (Q pre-scaled)
// ---------------------------------------------------------------------------
__global__ void setup_kernel(const float* __restrict__ text_emb,
                             const float* __restrict__ wt,
                             const float* __restrict__ bt,
                             const float* __restrict__ wq,
                             const float* __restrict__ wk,
                             const float* __restrict__ wv,
                             const float* __restrict__ bq,
                             const float* __restrict__ bk,
                             const float* __restrict__ pos) {
    __shared__ float mcol[256];
    __shared__ float stb[32];
    int t = threadIdx.x;
    float s = 0.f;
    #pragma unroll
    for (int r = 0; r < 32; ++r) s += text_emb[r * 256 + t];
    mcol[t] = s * (1.0f / 32.0f);
    __syncthreads();
    int warp = t >> 5, lane = t & 31;
    for (int q = warp; q < 32; q += 8) {
        float acc = 0.f;
        #pragma unroll
        for (int k = 0; k < 8; ++k) acc += wt[q * 256 + lane + k * 32] * mcol[lane + k * 32];
        #pragma unroll
        for (int o = 16; o > 0; o >>= 1) acc += __shfl_xor_sync(0xffffffffu, acc, o);
        if (lane == 0) stb[q] = acc + bt[q];
    }
    // weight prepack; Q rows scaled by QSCALE
    #pragma unroll
    for (int it = 0; it < 16; ++it) {
        int idx  = t + it * 256;    // 4096 words
        int j    = idx & 3;
        int ln   = (idx >> 2) & 31;
        int ks   = (idx >> 7) & 3;
        int mt   = idx >> 9;
        int g = ln >> 2, tt = ln & 3;
        int o = mt * 16 + g + (j & 1) * 8;
        int k = ks * 16 + 2 * tt + (j >> 1) * 8;
        float v0, v1;
        if (o < 32)       { v0 = wq[o * 64 + k] * QSCALE; v1 = wq[o * 64 + k + 1] * QSCALE; }
        else if (o < 64)  { v0 = wk[(o - 32) * 64 + k];   v1 = wk[(o - 32) * 64 + k + 1]; }
        else              { v0 = wv[(o - 64) * 64 + k];   v1 = wv[(o - 64) * 64 + k + 1]; }
        g_wpackh[idx] = h2pack(v0, v1);
    }
    __syncthreads();
    // fused bias+pos tables (fp16 d-pairs)
    for (int i = t; i < 512; i += 256) {
        int q = i >> 4, dp = i & 15, d0 = dp * 2;
        float qb = bq[q] + stb[q];
        float kb_ = bk[q] + stb[q];
        float p0 = pos[q * 32 + d0], p1 = pos[q * 32 + d0 + 1];
        g_qadd2[i] = h2pack((qb + p0) * QSCALE, (qb + p1) * QSCALE);
        g_kadd2[i] = h2pack(kb_ + p0, kb_ + p1);
    }
}

// ---------------------------------------------------------------------------
// Main fused kernel: one block per (b, h, 16-w strip); 512 threads, 2 CTA/SM
// ---------------------------------------------------------------------------
__global__ __launch_bounds__(NTHREADS, 2)
void attn_kernel(const float* __restrict__ x,
                 const float* __restrict__ bv,
                 const float* __restrict__ gamma,
                 float* __restrict__ out) {
    extern __shared__ float sm[];
    uint32_t* sxw  = reinterpret_cast<uint32_t*>(sm + SXW_OFF);   // x fp16 words / sout overlay
    uint32_t* sq32 = reinterpret_cast<uint32_t*>(sm + SQ32_OFF);
    uint32_t* sk32 = reinterpret_cast<uint32_t*>(sm + SK32_OFF);
    uint32_t* sv32 = reinterpret_cast<uint32_t*>(sm + SV_OFF);
    float* sbias   = sm + SBIAS_OFF;
    uint32_t* sqa  = reinterpret_cast<uint32_t*>(sm + SQA_OFF);
    uint32_t* ska  = reinterpret_cast<uint32_t*>(sm + SKA_OFF);

    const int tid = threadIdx.x;
    const int bid = blockIdx.x;
    const int nwT = W_DIM / WT;   // 6
    const int b   = bid / (H_DIM * nwT);
    const int rem = bid % (H_DIM * nwT);
    const int h   = rem / nwT;
    const int w0  = (rem % nwT) * WT;

    const int HW = H_DIM * W_DIM; // 9216
    const size_t base = (size_t)b * C_DIM * D_DIM * HW + (size_t)h * W_DIM + w0;

    const int warp = tid >> 5, lane = tid & 31;
    const int g = lane >> 2, t = lane & 3;

    // gate (uniform)
    const float gm = gamma[0];
    const float gg = 1.f / (1.f + __expf(-gm));
    const float g1 = 1.f - gg;

    // ---- Phase A: coalesced (64B strips) x load + fp16 c-pair pack, swizzled ----
    #pragma unroll
    for (int it = 0; it < 8; ++it) {
        int i  = tid + it * NTHREADS;       // 4096 units
        int cp = i >> 7, d = (i >> 2) & 31, w4 = i & 3;   // w4 = oct
        const float* p0 = x + base + ((size_t)(2 * cp) * D_DIM + d) * HW + w4 * 4;
        const float* p1 = p0 + (size_t)D_DIM * HW;
        float4 v0 = *reinterpret_cast<const float4*>(p0);
        float4 v1 = *reinterpret_cast<const float4*>(p1);
        uint32_t wvp[4];
        wvp[0] = h2pack(v0.x, v1.x);
        wvp[1] = h2pack(v0.y, v1.y);
        wvp[2] = h2pack(v0.z, v1.z);
        wvp[3] = h2pack(v0.w, v1.w);
        uint32_t* dst = &sxw[w4 * OCT_S + cp * 136 + d * 4];
        const int key = (d + (d >> 2)) & 3;
        #pragma unroll
        for (int j = 0; j < 4; ++j) dst[j ^ key] = wvp[j];
    }
    if (tid < 512) {   // fused bias+pos tables -> padded smem (pad 20, conflict-free)
        int q = tid >> 4, dp = tid & 15;
        sqa[q * 20 + dp] = g_qadd2[tid];
        ska[q * 20 + dp] = g_kadd2[tid];
    }
    if (tid < 64) sbias[tid] = bv[tid];
    __syncthreads();

    // roles
    const int mw = warp & 3;        // phase B: 0:Q 1:K 2:V(c0-31) 3:V(c32-63)
    const int ns = warp >> 2;       // phase B: n slice of 32 = w index (n = w*32 + d)
    const int aw = warp & 3;        // phase C/D: w within oct
    const int dh = ((warp >> 2) & 1) * 16;
    const int ch = (warp >> 3) * 32;

    for (int oct = 0; oct < 4; ++oct) {
        uint32_t* sxo = sxw + oct * OCT_S;

        // ---- Phase B: fp16 MMA GEMM  C[128 o][128 n] = W[128,64] * X[64,128] ----
        {
            float acc[2][4][4];
            #pragma unroll
            for (int s_ = 0; s_ < 2; ++s_)
                #pragma unroll
                for (int nt = 0; nt < 4; ++nt)
                    #pragma unroll
                    for (int v = 0; v < 4; ++v) acc[s_][nt][v] = 0.f;

            int bcol[4];
            #pragma unroll
            for (int nt = 0; nt < 4; ++nt) {
                int d_ = nt * 8 + g;
                bcol[nt] = d_ * 4 + (ns ^ ((d_ + (d_ >> 2)) & 3));
            }

            const uint4* wp4 = reinterpret_cast<const uint4*>(g_wpackh);
            #pragma unroll
            for (int ks = 0; ks < 4; ++ks) {
                uint4 a0 = __ldg(&wp4[((mw * 2 + 0) * 4 + ks) * 32 + lane]);
                uint4 a1 = __ldg(&wp4[((mw * 2 + 1) * 4 + ks) * 32 + lane]);
                const uint32_t* xr0 = &sxo[(ks * 8 + t) * 136];
                const uint32_t* xr1 = &sxo[(ks * 8 + t + 4) * 136];
                #pragma unroll
                for (int nt = 0; nt < 4; ++nt) {
                    uint32_t b0 = xr0[bcol[nt]];
                    uint32_t b1 = xr1[bcol[nt]];
                    mma_f16(acc[0][nt], a0.x, a0.y, a0.z, a0.w, b0, b1);
                    mma_f16(acc[1][nt], a1.x, a1.y, a1.z, a1.w, b0, b1);
                }
            }

            if (mw < 2) {
                // Q/K -> [w=ns][q (*20)][dpair]: packed STS.32, fused table add (HADD2)
                uint32_t* dst32 = ((mw == 0) ? sq32 : sk32) + ns * 644;
                const uint32_t* tab = (mw == 0) ? sqa : ska;
                #pragma unroll
                for (int s_ = 0; s_ < 2; ++s_) {
                    #pragma unroll
                    for (int nt = 0; nt < 4; ++nt) {
                        #pragma unroll
                        for (int vh = 0; vh < 2; ++vh) {
                            int q = s_ * 16 + g + vh * 8;
                            int dp = nt * 4 + t;
                            __half2 hacc = __floats2half2_rn(acc[s_][nt][2 * vh],
                                                             acc[s_][nt][2 * vh + 1]);
                            uint32_t tw = tab[q * 20 + dp];
                            __half2 r = __hadd2(hacc, *reinterpret_cast<__half2*>(&tw));
                            dst32[q * 20 + dp] = *reinterpret_cast<uint32_t*>(&r);
                        }
                    }
                }
            } else {
                // V -> sv32[w*1172 + epair*72 + c]
                const int cbb = (mw - 2) * 32;
                uint32_t* svd = &sv32[ns * 1172];
                #pragma unroll
                for (int s_ = 0; s_ < 2; ++s_) {
                    #pragma unroll
                    for (int nt = 0; nt < 4; ++nt) {
                        #pragma unroll
                        for (int cg = 0; cg < 2; ++cg) {
                            int c = cbb + s_ * 16 + g + cg * 8;
                            float bia = sbias[c];
                            svd[(nt * 4 + t) * 72 + c] =
                                h2pack(acc[s_][nt][cg * 2] + bia, acc[s_][nt][cg * 2 + 1] + bia);
                        }
                    }
                }
            }
        }
        __syncthreads();   // barrier 1: QKV(oct) ready; x-oct GEMM reads done

        // ---- Phases C+D fused per warp: (w, d-half, c-half) + in-register blend ----
        uint32_t pk2[4][2];   // final blended fp16 pairs
        {
            const uint32_t* qw = sq32 + aw * 644;   // [q*20 + dpair]
            const uint32_t* kw = sk32 + aw * 644;   // [q*20 + epair]

            // Q A-frag [m=d][k=q] via trans-LDSM of [q][d] storage
            // K B-frag (col-major [e][q]) via trans-LDSM of [q][e] storage
            uint32_t qa[2][4];
            uint32_t kb[2][2][4];
            #pragma unroll
            for (int ks = 0; ks < 2; ++ks) {
                ldsm_x4_trans(qa[ks],
                    &qw[(ks * 16 + ((lane >> 4) & 1) * 8 + (lane & 7)) * 20
                        + dh / 2 + ((lane >> 3) & 1) * 4]);
                #pragma unroll
                for (int p = 0; p < 2; ++p)
                    ldsm_x4_trans(kb[ks][p],
                        &kw[(ks * 16 + ((lane >> 3) & 1) * 8 + (lane & 7)) * 20
                            + p * 8 + ((lane >> 4) & 1) * 4]);
            }

            float fs[4][4];
            #pragma unroll
            for (int nt = 0; nt < 4; ++nt)
                #pragma unroll
                for (int v = 0; v < 4; ++v) fs[nt][v] = 0.f;

            #pragma unroll
            for (int ks = 0; ks < 2; ++ks)
                #pragma unroll
                for (int nt = 0; nt < 4; ++nt)
                    mma_f16(fs[nt], qa[ks][0], qa[ks][1], qa[ks][2], qa[ks][3],
                            kb[ks][nt >> 1][(nt & 1) * 2], kb[ks][nt >> 1][(nt & 1) * 2 + 1]);
            // fs[nt][v]: S[d = dh + g + (v>>1)*8][e = nt*8 + 2t + (v&1)]

            float m0 = -1e30f, m1 = -1e30f;
            #pragma unroll
            for (int nt = 0; nt < 4; ++nt) {
                m0 = fmaxf(m0, fmaxf(fs[nt][0], fs[nt][1]));
                m1 = fmaxf(m1, fmaxf(fs[nt][2], fs[nt][3]));
            }
            m0 = fmaxf(m0, __shfl_xor_sync(0xffffffffu, m0, 1));
            m0 = fmaxf(m0, __shfl_xor_sync(0xffffffffu, m0, 2));
            m1 = fmaxf(m1, __shfl_xor_sync(0xffffffffu, m1, 1));
            m1 = fmaxf(m1, __shfl_xor_sync(0xffffffffu, m1, 2));

            float s0 = 0.f, s1 = 0.f;
            #pragma unroll
            for (int nt = 0; nt < 4; ++nt) {
                fs[nt][0] = __expf(fs[nt][0] - m0); s0 += fs[nt][0];
                fs[nt][1] = __expf(fs[nt][1] - m0); s0 += fs[nt][1];
                fs[nt][2] = __expf(fs[nt][2] - m1); s1 += fs[nt][2];
                fs[nt][3] = __expf(fs[nt][3] - m1); s1 += fs[nt][3];
            }
            s0 += __shfl_xor_sync(0xffffffffu, s0, 1);
            s0 += __shfl_xor_sync(0xffffffffu, s0, 2);
            s1 += __shfl_xor_sync(0xffffffffu, s1, 1);
            s1 += __shfl_xor_sync(0xffffffffu, s1, 2);
            float r0 = __fdividef(1.f, s0);
            float r1 = __fdividef(1.f, s1);

            float od[4][4];
            #pragma unroll
            for (int nt = 0; nt < 4; ++nt)
                #pragma unroll
                for (int v = 0; v < 4; ++v) od[nt][v] = 0.f;

            const uint32_t* svw = &sv32[aw * 1172];
            #pragma unroll
            for (int ks = 0; ks < 2; ++ks) {
                uint32_t a0 = h2pack(fs[2 * ks][0] * r0, fs[2 * ks][1] * r0);
                uint32_t a1 = h2pack(fs[2 * ks][2] * r1, fs[2 * ks][3] * r1);
                uint32_t a2 = h2pack(fs[2 * ks + 1][0] * r0, fs[2 * ks + 1][1] * r0);
                uint32_t a3 = h2pack(fs[2 * ks + 1][2] * r1, fs[2 * ks + 1][3] * r1);
                #pragma unroll
                for (int ntd = 0; ntd < 4; ++ntd) {
                    int col = ch + ntd * 8 + g;
                    uint32_t b0 = svw[(8 * ks + t) * 72 + col];
                    uint32_t b1 = svw[(8 * ks + t + 4) * 72 + col];
                    mma_f16(od[ntd], a0, a1, a2, a3, b0, b1);
                }
            }
            // od[ntd][v]: out[d = dh + g + (v>>1)*8][c = ch + ntd*8 + 2t + (v&1)]

            // blend with fp16 x (swizzled reads, conflict-free)
            #pragma unroll
            for (int ntd = 0; ntd < 4; ++ntd) {
                int cp = (ch >> 1) + ntd * 4 + t;
                int da = dh + g, db = dh + g + 8;
                uint32_t xwa = sxo[cp * 136 + da * 4 + (aw ^ ((da + (da >> 2)) & 3))];
                uint32_t xwb = sxo[cp * 136 + db * 4 + (aw ^ ((db + (db >> 2)) & 3))];
                float2 xa = __half22float2(*reinterpret_cast<__half2*>(&xwa));
                float2 xb = __half22float2(*reinterpret_cast<__half2*>(&xwb));
                pk2[ntd][0] = h2pack(gg * od[ntd][0] + g1 * xa.x,
                                     gg * od[ntd][1] + g1 * xa.y);
                pk2[ntd][1] = h2pack(gg * od[ntd][2] + g1 * xb.x,
                                     gg * od[ntd][3] + g1 * xb.y);
            }
        }
        __syncthreads();   // barrier 2: all x-blend reads + QKV reads done

        // sout (final fp16 values) overlays x-oct: word = cp*136 + w*34 + d (conflict-free)
        #pragma unroll
        for (int ntd = 0; ntd < 4; ++ntd) {
            int cp = (ch >> 1) + ntd * 4 + t;
            sxo[cp * 136 + aw * 34 + dh + g]     = pk2[ntd][0];
            sxo[cp * 136 + aw * 34 + dh + g + 8] = pk2[ntd][1];
        }
    }
    __syncthreads();   // all sout writes complete

    // ---- Epilogue: convert + store, coalesced 64B strips (no x reload) ----
    #pragma unroll
    for (int it = 0; it < 8; ++it) {
        int i  = tid + it * NTHREADS;
        int cp = i >> 7, d = (i >> 2) & 31, w4 = i & 3;
        const uint32_t* so = sxw + w4 * OCT_S;
        float o0[4], o1[4];
        #pragma unroll
        for (int j = 0; j < 4; ++j) {
            uint32_t pw = so[cp * 136 + j * 34 + d];
            float2 f = __half22float2(*reinterpret_cast<__half2*>(&pw));
            o0[j] = f.x;   // c = 2cp
            o1[j] = f.y;   // c = 2cp+1
        }
        size_t ga0 = base + ((size_t)(2 * cp) * D_DIM + d) * HW + w4 * 4;
        size_t ga1 = ga0 + (size_t)D_DIM * HW;
        float4 r0 = make_float4(o0[0], o0[1], o0[2], o0[3]);
        float4 r1 = make_float4(o1[0], o1[1], o1[2], o1[3]);
        *reinterpret_cast<float4*>(out + ga0) = r0;
        *reinterpret_cast<float4*>(out + ga1) = r1;
    }
}

// ---------------------------------------------------------------------------
extern "C" void kernel_launch(void* const* d_in, const int* in_sizes, int n_in,
                              void* d_out, int out_size) {
    const float* x        = (const float*)d_in[0];
    const float* text_emb = (const float*)d_in[1];
    const float* wq       = (const float*)d_in[2];
    const float* bq       = (const float*)d_in[3];
    const float* wk       = (const float*)d_in[4];
    const float* bk       = (const float*)d_in[5];
    const float* wv       = (const float*)d_in[6];
    const float* bv       = (const float*)d_in[7];
    const float* wt       = (const float*)d_in[8];
    const float* bt       = (const float*)d_in[9];
    const float* pos      = (const float*)d_in[10];
    const float* gamma    = (const float*)d_in[11];
    float* out = (float*)d_out;

    cudaFuncSetAttribute(attn_kernel, cudaFuncAttributeMaxDynamicSharedMemorySize, SMEM_BYTES);

    setup_kernel<<<1, 256>>>(text_emb, wt, bt, wq, wk, wv, bq, bk, pos);

    const int grid = B_DIM * H_DIM * (W_DIM / WT);  // 1152
    attn_kernel<<<grid, NTHREADS, SMEM_BYTES>>>(x, bv, gamma, out);
}

// round 17
// speedup vs baseline: 2.8015x; 1.0976x over previous
#include <cuda_runtime.h>
#include <cuda_fp16.h>
#include <math.h>
#include <stdint.h>

// Problem constants
#define C_DIM 64
#define D_DIM 32
#define H_DIM 96
#define W_DIM 96
#define B_DIM 2
#define WT 16         // w-tile per CTA (64B strips: full sectors)
#define NTHREADS 512
#define QSCALE 0.17677669529663687f

// smem layout (word units)
#define SXW_OFF   0       // x fp16 c-pair words, 4 octs (4w each) of [32 cp (*136)][d*4 + (w^swz)]
#define OCT_S     4360    // 32*136 + 8 pad, ≡ 8 mod 32
#define SQ32_OFF  17440   // Q fp16 pairs: uint32 [4 w (*644)][32 q (*20)][16 dpair]
#define SK32_OFF  20016   // K same, outer = e
#define SV_OFF    22592   // V fp16 pairs: uint32 [4 w (*1172)][16 epair (*72)][64 c]
#define SBIAS_OFF 27280   // 64 (V bias only)
#define SQA_OFF   27344   // qadd table: uint32 [32 q (*20)][16 dpair] = 640
#define SKA_OFF   27984   // kadd table: 640
#define SMEM_FLOATS 28624
#define SMEM_BYTES (SMEM_FLOATS * 4)   // 114496 B -> 2 CTAs/SM

__device__ uint32_t g_wpackh[4096];   // prepacked fp16 W (Q rows pre-scaled)
__device__ uint32_t g_qadd2[512];     // fp16 pairs: (bq+tb+pos)*QSCALE
__device__ uint32_t g_kadd2[512];     // fp16 pairs: bk+tb+pos

__device__ __forceinline__ void mma_f16(float* d, uint32_t a0, uint32_t a1, uint32_t a2,
                                        uint32_t a3, uint32_t b0, uint32_t b1) {
    asm volatile(
        "mma.sync.aligned.m16n8k16.row.col.f32.f16.f16.f32 "
        "{%0,%1,%2,%3}, {%4,%5,%6,%7}, {%8,%9}, {%0,%1,%2,%3};"
        : "+f"(d[0]), "+f"(d[1]), "+f"(d[2]), "+f"(d[3])
        : "r"(a0), "r"(a1), "r"(a2), "r"(a3), "r"(b0), "r"(b1));
}

__device__ __forceinline__ uint32_t h2pack(float lo, float hi) {
    __half2 h = __floats2half2_rn(lo, hi);
    return *reinterpret_cast<uint32_t*>(&h);
}

__device__ __forceinline__ void ldsm_x4_trans(uint32_t* r, const void* p) {
    uint32_t a = (uint32_t)__cvta_generic_to_shared(p);
    asm volatile("ldmatrix.sync.aligned.m8n8.x4.trans.shared.b16 {%0,%1,%2,%3}, [%4];"
                 : "=r"(r[0]), "=r"(r[1]), "=r"(r[2]), "=r"(r[3]) : "r"(a));
}

// ---------------------------------------------------------------------------
// Setup kernel: text bias, fused bias+pos tables, weight prepack (Q pre-scaled)
// ---------------------------------------------------------------------------
__global__ void setup_kernel(const float* __restrict__ text_emb,
                             const float* __restrict__ wt,
                             const float* __restrict__ bt,
                             const float* __restrict__ wq,
                             const float* __restrict__ wk,
                             const float* __restrict__ wv,
                             const float* __restrict__ bq,
                             const float* __restrict__ bk,
                             const float* __restrict__ pos) {
    __shared__ float mcol[256];
    __shared__ float stb[32];
    int t = threadIdx.x;
    float s = 0.f;
    #pragma unroll
    for (int r = 0; r < 32; ++r) s += text_emb[r * 256 + t];
    mcol[t] = s * (1.0f / 32.0f);
    __syncthreads();
    int warp = t >> 5, lane = t & 31;
    for (int q = warp; q < 32; q += 8) {
        float acc = 0.f;
        #pragma unroll
        for (int k = 0; k < 8; ++k) acc += wt[q * 256 + lane + k * 32] * mcol[lane + k * 32];
        #pragma unroll
        for (int o = 16; o > 0; o >>= 1) acc += __shfl_xor_sync(0xffffffffu, acc, o);
        if (lane == 0) stb[q] = acc + bt[q];
    }
    // weight prepack; Q rows scaled by QSCALE
    #pragma unroll
    for (int it = 0; it < 16; ++it) {
        int idx  = t + it * 256;    // 4096 words
        int j    = idx & 3;
        int ln   = (idx >> 2) & 31;
        int ks   = (idx >> 7) & 3;
        int mt   = idx >> 9;
        int g = ln >> 2, tt = ln & 3;
        int o = mt * 16 + g + (j & 1) * 8;
        int k = ks * 16 + 2 * tt + (j >> 1) * 8;
        float v0, v1;
        if (o < 32)       { v0 = wq[o * 64 + k] * QSCALE; v1 = wq[o * 64 + k + 1] * QSCALE; }
        else if (o < 64)  { v0 = wk[(o - 32) * 64 + k];   v1 = wk[(o - 32) * 64 + k + 1]; }
        else              { v0 = wv[(o - 64) * 64 + k];   v1 = wv[(o - 64) * 64 + k + 1]; }
        g_wpackh[idx] = h2pack(v0, v1);
    }
    __syncthreads();
    // fused bias+pos tables (fp16 d-pairs)
    for (int i = t; i < 512; i += 256) {
        int q = i >> 4, dp = i & 15, d0 = dp * 2;
        float qb = bq[q] + stb[q];
        float kb_ = bk[q] + stb[q];
        float p0 = pos[q * 32 + d0], p1 = pos[q * 32 + d0 + 1];
        g_qadd2[i] = h2pack((qb + p0) * QSCALE, (qb + p1) * QSCALE);
        g_kadd2[i] = h2pack(kb_ + p0, kb_ + p1);
    }
}

// ---------------------------------------------------------------------------
// Main fused kernel: one block per (b, h, 16-w strip); 512 threads, 2 CTA/SM
// ---------------------------------------------------------------------------
__global__ __launch_bounds__(NTHREADS, 2)
void attn_kernel(const float* __restrict__ x,
                 const float* __restrict__ bv,
                 const float* __restrict__ gamma,
                 float* __restrict__ out) {
    extern __shared__ float sm[];
    uint32_t* sxw  = reinterpret_cast<uint32_t*>(sm + SXW_OFF);   // x fp16 words / sout overlay
    uint32_t* sq32 = reinterpret_cast<uint32_t*>(sm + SQ32_OFF);
    uint32_t* sk32 = reinterpret_cast<uint32_t*>(sm + SK32_OFF);
    uint32_t* sv32 = reinterpret_cast<uint32_t*>(sm + SV_OFF);
    float* sbias   = sm + SBIAS_OFF;
    uint32_t* sqa  = reinterpret_cast<uint32_t*>(sm + SQA_OFF);
    uint32_t* ska  = reinterpret_cast<uint32_t*>(sm + SKA_OFF);

    const int tid = threadIdx.x;
    const int bid = blockIdx.x;
    const int nwT = W_DIM / WT;   // 6
    const int b   = bid / (H_DIM * nwT);
    const int rem = bid % (H_DIM * nwT);
    const int h   = rem / nwT;
    const int w0  = (rem % nwT) * WT;

    const int HW = H_DIM * W_DIM; // 9216
    const size_t base = (size_t)b * C_DIM * D_DIM * HW + (size_t)h * W_DIM + w0;

    const int warp = tid >> 5, lane = tid & 31;
    const int g = lane >> 2, t = lane & 3;

    // gate (uniform)
    const float gm = gamma[0];
    const float gg = 1.f / (1.f + __expf(-gm));
    const float g1 = 1.f - gg;

    // ---- Phase A: coalesced (64B strips) x load + fp16 c-pair pack, swizzled ----
    #pragma unroll
    for (int it = 0; it < 8; ++it) {
        int i  = tid + it * NTHREADS;       // 4096 units
        int cp = i >> 7, d = (i >> 2) & 31, w4 = i & 3;   // w4 = oct
        const float* p0 = x + base + ((size_t)(2 * cp) * D_DIM + d) * HW + w4 * 4;
        const float* p1 = p0 + (size_t)D_DIM * HW;
        float4 v0 = *reinterpret_cast<const float4*>(p0);
        float4 v1 = *reinterpret_cast<const float4*>(p1);
        uint32_t wvp[4];
        wvp[0] = h2pack(v0.x, v1.x);
        wvp[1] = h2pack(v0.y, v1.y);
        wvp[2] = h2pack(v0.z, v1.z);
        wvp[3] = h2pack(v0.w, v1.w);
        uint32_t* dst = &sxw[w4 * OCT_S + cp * 136 + d * 4];
        const int key = (d + (d >> 2)) & 3;
        #pragma unroll
        for (int j = 0; j < 4; ++j) dst[j ^ key] = wvp[j];
    }
    {   // fused bias+pos tables -> padded smem (pad 20, conflict-free)
        int q = tid >> 4, dp = tid & 15;
        sqa[q * 20 + dp] = g_qadd2[tid];
        ska[q * 20 + dp] = g_kadd2[tid];
    }
    if (tid < 64) sbias[tid] = bv[tid];
    __syncthreads();

    // roles
    const int mw = warp & 3;        // phase B: 0:Q 1:K 2:V(c0-31) 3:V(c32-63)
    const int ns = warp >> 2;       // phase B: n slice of 32 = w index (n = w*32 + d)
    const int aw = warp & 3;        // phase C/D: w within oct
    const int dh = ((warp >> 2) & 1) * 16;
    const int ch = (warp >> 3) * 32;

    // ---- oct-invariant hoisting ----
    int bcol[4];
    #pragma unroll
    for (int nt = 0; nt < 4; ++nt) {
        int d_ = nt * 8 + g;
        bcol[nt] = d_ * 4 + (ns ^ ((d_ + (d_ >> 2)) & 3));
    }
    const uint4* wprow0 = reinterpret_cast<const uint4*>(g_wpackh) + (mw * 2 + 0) * 4 * 32 + lane;
    const uint4* wprow1 = reinterpret_cast<const uint4*>(g_wpackh) + (mw * 2 + 1) * 4 * 32 + lane;
    // Q/K epilogue pointers (mw<2)
    uint32_t* qkdst = ((mw == 0) ? sq32 : sk32) + ns * 644;
    const uint32_t* qktab = (mw == 0) ? sqa : ska;
    // V epilogue: destination + hoisted biases (mw>=2)
    uint32_t* svd = &sv32[ns * 1172];
    const int cbb = (mw - 2) * 32;
    float vbia[2][2];
    if (mw >= 2) {
        #pragma unroll
        for (int s_ = 0; s_ < 2; ++s_)
            #pragma unroll
            for (int cg = 0; cg < 2; ++cg)
                vbia[s_][cg] = sbias[cbb + s_ * 16 + g + cg * 8];
    }
    // CD-phase hoisted pointers
    const uint32_t* qw = sq32 + aw * 644;
    const uint32_t* kw = sk32 + aw * 644;
    const uint32_t* svw = &sv32[aw * 1172];
    const int keya = ((dh + g) + ((dh + g) >> 2)) & 3;
    const int keyb = ((dh + g + 8) + ((dh + g + 8) >> 2)) & 3;

    #pragma unroll
    for (int oct = 0; oct < 4; ++oct) {
        uint32_t* sxo = sxw + oct * OCT_S;

        // ---- Phase B: fp16 MMA GEMM  C[128 o][128 n] = W[128,64] * X[64,128] ----
        {
            float acc[2][4][4];
            #pragma unroll
            for (int s_ = 0; s_ < 2; ++s_)
                #pragma unroll
                for (int nt = 0; nt < 4; ++nt)
                    #pragma unroll
                    for (int v = 0; v < 4; ++v) acc[s_][nt][v] = 0.f;

            #pragma unroll
            for (int ks = 0; ks < 4; ++ks) {
                uint4 a0 = __ldg(wprow0 + ks * 32);
                uint4 a1 = __ldg(wprow1 + ks * 32);
                const uint32_t* xr0 = &sxo[(ks * 8 + t) * 136];
                const uint32_t* xr1 = &sxo[(ks * 8 + t + 4) * 136];
                #pragma unroll
                for (int nt = 0; nt < 4; ++nt) {
                    uint32_t b0 = xr0[bcol[nt]];
                    uint32_t b1 = xr1[bcol[nt]];
                    mma_f16(acc[0][nt], a0.x, a0.y, a0.z, a0.w, b0, b1);
                    mma_f16(acc[1][nt], a1.x, a1.y, a1.z, a1.w, b0, b1);
                }
            }

            if (mw < 2) {
                // Q/K -> [w=ns][q (*20)][dpair]: packed STS.32, fused table add (HADD2)
                #pragma unroll
                for (int s_ = 0; s_ < 2; ++s_) {
                    #pragma unroll
                    for (int nt = 0; nt < 4; ++nt) {
                        #pragma unroll
                        for (int vh = 0; vh < 2; ++vh) {
                            int q = s_ * 16 + g + vh * 8;
                            int dp = nt * 4 + t;
                            __half2 hacc = __floats2half2_rn(acc[s_][nt][2 * vh],
                                                             acc[s_][nt][2 * vh + 1]);
                            uint32_t tw = qktab[q * 20 + dp];
                            __half2 r = __hadd2(hacc, *reinterpret_cast<__half2*>(&tw));
                            qkdst[q * 20 + dp] = *reinterpret_cast<uint32_t*>(&r);
                        }
                    }
                }
            } else {
                // V -> sv32[w*1172 + epair*72 + c], biases hoisted
                #pragma unroll
                for (int s_ = 0; s_ < 2; ++s_) {
                    #pragma unroll
                    for (int nt = 0; nt < 4; ++nt) {
                        #pragma unroll
                        for (int cg = 0; cg < 2; ++cg) {
                            int c = cbb + s_ * 16 + g + cg * 8;
                            float bia = vbia[s_][cg];
                            svd[(nt * 4 + t) * 72 + c] =
                                h2pack(acc[s_][nt][cg * 2] + bia, acc[s_][nt][cg * 2 + 1] + bia);
                        }
                    }
                }
            }
        }
        __syncthreads();   // barrier 1: QKV(oct) ready; x-oct GEMM reads done

        // ---- Phases C+D fused per warp: (w, d-half, c-half) + in-register blend ----
        uint32_t pk2[4][2];   // final blended fp16 pairs
        {
            // Q A-frag [m=d][k=q] via trans-LDSM of [q][d] storage
            // K B-frag (col-major [e][q]) via trans-LDSM of [q][e] storage
            uint32_t qa[2][4];
            uint32_t kb[2][2][4];
            #pragma unroll
            for (int ks = 0; ks < 2; ++ks) {
                ldsm_x4_trans(qa[ks],
                    &qw[(ks * 16 + ((lane >> 4) & 1) * 8 + (lane & 7)) * 20
                        + dh / 2 + ((lane >> 3) & 1) * 4]);
                #pragma unroll
                for (int p = 0; p < 2; ++p)
                    ldsm_x4_trans(kb[ks][p],
                        &kw[(ks * 16 + ((lane >> 3) & 1) * 8 + (lane & 7)) * 20
                            + p * 8 + ((lane >> 4) & 1) * 4]);
            }

            float fs[4][4];
            #pragma unroll
            for (int nt = 0; nt < 4; ++nt)
                #pragma unroll
                for (int v = 0; v < 4; ++v) fs[nt][v] = 0.f;

            #pragma unroll
            for (int ks = 0; ks < 2; ++ks)
                #pragma unroll
                for (int nt = 0; nt < 4; ++nt)
                    mma_f16(fs[nt], qa[ks][0], qa[ks][1], qa[ks][2], qa[ks][3],
                            kb[ks][nt >> 1][(nt & 1) * 2], kb[ks][nt >> 1][(nt & 1) * 2 + 1]);
            // fs[nt][v]: S[d = dh + g + (v>>1)*8][e = nt*8 + 2t + (v&1)]

            float m0 = -1e30f, m1 = -1e30f;
            #pragma unroll
            for (int nt = 0; nt < 4; ++nt) {
                m0 = fmaxf(m0, fmaxf(fs[nt][0], fs[nt][1]));
                m1 = fmaxf(m1, fmaxf(fs[nt][2], fs[nt][3]));
            }
            m0 = fmaxf(m0, __shfl_xor_sync(0xffffffffu, m0, 1));
            m0 = fmaxf(m0, __shfl_xor_sync(0xffffffffu, m0, 2));
            m1 = fmaxf(m1, __shfl_xor_sync(0xffffffffu, m1, 1));
            m1 = fmaxf(m1, __shfl_xor_sync(0xffffffffu, m1, 2));

            float s0 = 0.f, s1 = 0.f;
            #pragma unroll
            for (int nt = 0; nt < 4; ++nt) {
                fs[nt][0] = __expf(fs[nt][0] - m0); s0 += fs[nt][0];
                fs[nt][1] = __expf(fs[nt][1] - m0); s0 += fs[nt][1];
                fs[nt][2] = __expf(fs[nt][2] - m1); s1 += fs[nt][2];
                fs[nt][3] = __expf(fs[nt][3] - m1); s1 += fs[nt][3];
            }
            s0 += __shfl_xor_sync(0xffffffffu, s0, 1);
            s0 += __shfl_xor_sync(0xffffffffu, s0, 2);
            s1 += __shfl_xor_sync(0xffffffffu, s1, 1);
            s1 += __shfl_xor_sync(0xffffffffu, s1, 2);
            float r0 = __fdividef(1.f, s0);
            float r1 = __fdividef(1.f, s1);

            float od[4][4];
            #pragma unroll
            for (int nt = 0; nt < 4; ++nt)
                #pragma unroll
                for (int v = 0; v < 4; ++v) od[nt][v] = 0.f;

            #pragma unroll
            for (int ks = 0; ks < 2; ++ks) {
                uint32_t a0 = h2pack(fs[2 * ks][0] * r0, fs[2 * ks][1] * r0);
                uint32_t a1 = h2pack(fs[2 * ks][2] * r1, fs[2 * ks][3] * r1);
                uint32_t a2 = h2pack(fs[2 * ks + 1][0] * r0, fs[2 * ks + 1][1] * r0);
                uint32_t a3 = h2pack(fs[2 * ks + 1][2] * r1, fs[2 * ks + 1][3] * r1);
                #pragma unroll
                for (int ntd = 0; ntd < 4; ++ntd) {
                    int col = ch + ntd * 8 + g;
                    uint32_t b0 = svw[(8 * ks + t) * 72 + col];
                    uint32_t b1 = svw[(8 * ks + t + 4) * 72 + col];
                    mma_f16(od[ntd], a0, a1, a2, a3, b0, b1);
                }
            }
            // od[ntd][v]: out[d = dh + g + (v>>1)*8][c = ch + ntd*8 + 2t + (v&1)]

            // blend with fp16 x (swizzled reads, conflict-free)
            #pragma unroll
            for (int ntd = 0; ntd < 4; ++ntd) {
                int cp = (ch >> 1) + ntd * 4 + t;
                uint32_t xwa = sxo[cp * 136 + (dh + g) * 4 + (aw ^ keya)];
                uint32_t xwb = sxo[cp * 136 + (dh + g + 8) * 4 + (aw ^ keyb)];
                float2 xa = __half22float2(*reinterpret_cast<__half2*>(&xwa));
                float2 xb = __half22float2(*reinterpret_cast<__half2*>(&xwb));
                pk2[ntd][0] = h2pack(gg * od[ntd][0] + g1 * xa.x,
                                     gg * od[ntd][1] + g1 * xa.y);
                pk2[ntd][1] = h2pack(gg * od[ntd][2] + g1 * xb.x,
                                     gg * od[ntd][3] + g1 * xb.y);
            }
        }
        __syncthreads();   // barrier 2: all x-blend reads + QKV reads done

        // sout (final fp16 values) overlays x-oct: word = cp*136 + w*34 + d (conflict-free)
        #pragma unroll
        for (int ntd = 0; ntd < 4; ++ntd) {
            int cp = (ch >> 1) + ntd * 4 + t;
            sxo[cp * 136 + aw * 34 + dh + g]     = pk2[ntd][0];
            sxo[cp * 136 + aw * 34 + dh + g + 8] = pk2[ntd][1];
        }
    }
    __syncthreads();   // all sout writes complete

    // ---- Epilogue: LDS.64 reads (d-pairs), coalesced 64B-strip stores ----
    #pragma unroll
    for (int it = 0; it < 4; ++it) {
        int i  = tid + it * NTHREADS;           // 2048 units: (cp, dpair, w4)
        int w4 = i & 3, dp = (i >> 2) & 15, cp = i >> 6;
        const uint32_t* so = sxw + w4 * OCT_S;
        int d0 = dp * 2;
        float a0[4], a1[4], b0[4], b1[4];       // [j]: a=d0 row, b=d0+1 row; 0=c2cp,1=c2cp+1
        #pragma unroll
        for (int j = 0; j < 4; ++j) {
            uint2 u = *reinterpret_cast<const uint2*>(&so[cp * 136 + j * 34 + d0]);
            float2 fa = __half22float2(*reinterpret_cast<__half2*>(&u.x));
            float2 fb = __half22float2(*reinterpret_cast<__half2*>(&u.y));
            a0[j] = fa.x; a1[j] = fa.y;
            b0[j] = fb.x; b1[j] = fb.y;
        }
        size_t ga00 = base + ((size_t)(2 * cp) * D_DIM + d0) * HW + w4 * 4;
        size_t ga10 = ga00 + (size_t)D_DIM * HW;            // c = 2cp+1, d = d0
        size_t ga01 = ga00 + HW;                             // c = 2cp,   d = d0+1
        size_t ga11 = ga10 + HW;                             // c = 2cp+1, d = d0+1
        *reinterpret_cast<float4*>(out + ga00) = make_float4(a0[0], a0[1], a0[2], a0[3]);
        *reinterpret_cast<float4*>(out + ga10) = make_float4(a1[0], a1[1], a1[2], a1[3]);
        *reinterpret_cast<float4*>(out + ga01) = make_float4(b0[0], b0[1], b0[2], b0[3]);
        *reinterpret_cast<float4*>(out + ga11) = make_float4(b1[0], b1[1], b1[2], b1[3]);
    }
}

// ---------------------------------------------------------------------------
extern "C" void kernel_launch(void* const* d_in, const int* in_sizes, int n_in,
                              void* d_out, int out_size) {
    const float* x        = (const float*)d_in[0];
    const float* text_emb = (const float*)d_in[1];
    const float* wq       = (const float*)d_in[2];
    const float* bq       = (const float*)d_in[3];
    const float* wk       = (const float*)d_in[4];
    const float* bk       = (const float*)d_in[5];
    const float* wv       = (const float*)d_in[6];
    const float* bv       = (const float*)d_in[7];
    const float* wt       = (const float*)d_in[8];
    const float* bt       = (const float*)d_in[9];
    const float* pos      = (const float*)d_in[10];
    const float* gamma    = (const float*)d_in[11];
    float* out = (float*)d_out;

    cudaFuncSetAttribute(attn_kernel, cudaFuncAttributeMaxDynamicSharedMemorySize, SMEM_BYTES);

    setup_kernel<<<1, 256>>>(text_emb, wt, bt, wq, wk, wv, bq, bk, pos);

    const int grid = B_DIM * H_DIM * (W_DIM / WT);  // 1152
    attn_kernel<<<grid, NTHREADS, SMEM_BYTES>>>(x, bv, gamma, out);
}